// round 7
// baseline (speedup 1.0000x reference)
#include <cuda_runtime.h>
#include <cuda_bf16.h>
#include <cstdint>

// Problem dims (fixed)
#define BB 8
#define SS 2048
#define DD 1024
#define HH 2048
#define AA 128
#define EE 8
#define MM (BB*SS)   // 16384 tokens

// tcgen05 is arch-SPECIFIC (sm_103a). Only use it in an arch-specific pass.
#if defined(__CUDA_ARCH_FEAT_SM103_ALL)
#define TCPATH 1
#endif

// -------- scratch (device globals; no allocation allowed) --------
__device__ float g_Yg[MM*HH];          // gate pre-act (exact fp32)
__device__ float g_Hid[MM*HH];         // hidden0 = silu(gate)*up (tf32-rounded)
__device__ float g_Pre[MM*AA];         // exact (atomic target)
__device__ float g_PreR[MM*AA];        // rounded copy for GEMM A
__device__ float g_Ain[MM*AA];         // LN(pre), rounded
__device__ float g_Post[MM*AA];        // exact (atomic target)
__device__ float g_Aout[MM*AA];        // LN(post), rounded
__device__ float g_AiT[BB*AA*SS];      // adapt_in transposed per batch [A,S], rounded
__device__ float g_AW[(long)BB*SS*SS]; // attention weights (silu-clip), rounded
__device__ float g_Adapt[MM*AA];       // exact (atomic target)
__device__ float g_AdaptR[MM*AA];      // rounded
__device__ float g_Eall[MM*EE*AA];     // experts' pre-LN activations (exact)
__device__ float g_Ecomp[MM*AA];       // selected+LN'd expert act, rounded
__device__ float g_Wcomb[DD*AA];       // w_out @ w_eproj (exact, atomic)
__device__ float g_WcombR[DD*AA];      // rounded
__device__ float g_W2[DD*AA];          // w_down @ w_aproj (exact, atomic)
__device__ float g_W2R[DD*AA];         // rounded
__device__ float g_Tep[AA*HH];         // w_eproj^T, rounded
__device__ float g_Tap[AA*HH];         // w_aproj^T, rounded
// rounded raw inputs
__device__ float g_xR[MM*DD];
__device__ float g_WgR[HH*DD];
__device__ float g_WuR[HH*DD];
__device__ float g_WdR[DD*HH];
__device__ float g_WoutR[DD*HH];
__device__ float g_WpreR[AA*DD];
__device__ float g_WpostR[AA*HH];
__device__ float g_WexpR[EE*AA*AA];

// ============================================================
// common helpers
// ============================================================
__device__ __forceinline__ float silu_f(float v) {
    return v * __frcp_rn(1.f + __expf(-v));
}

__device__ __forceinline__ uint32_t f2tf32(float f) {
    uint32_t u;
    asm("cvt.rna.tf32.f32 %0, %1;" : "=r"(u) : "f"(f));
    return u;
}
__device__ __forceinline__ float rndf(float f) {
    return __uint_as_float(f2tf32(f));
}

#ifdef TCPATH
// ============================================================
// tcgen05 helpers (sm_103a-specific pass only)
// ============================================================
__device__ __forceinline__ uint32_t smem_u32(const void* p) {
    uint32_t a;
    asm("{ .reg .u64 t; cvta.to.shared.u64 t, %1; cvt.u32.u64 %0, t; }"
        : "=r"(a) : "l"(p));
    return a;
}

__device__ __forceinline__ uint32_t elect1() {
    uint32_t p;
    asm volatile("{\n\t.reg .pred p;\n\telect.sync _|p, 0xFFFFFFFF;\n\t"
                 "selp.b32 %0, 1, 0, p;\n\t}" : "=r"(p));
    return p;
}

#define MBAR_INIT(addr, cnt) \
    asm volatile("mbarrier.init.shared.b64 [%0], %1;" :: "r"(addr), "r"(cnt) : "memory")

__device__ __forceinline__ void mbar_wait(uint32_t mbar, uint32_t parity) {
    uint32_t done;
    asm volatile("{\n\t.reg .pred p;\n\t"
                 "mbarrier.try_wait.parity.acquire.cta.shared::cta.b64 p, [%1], %2;\n\t"
                 "selp.b32 %0, 1, 0, p;\n\t}"
                 : "=r"(done) : "r"(mbar), "r"(parity) : "memory");
    while (!done) {
        asm volatile("{\n\t.reg .pred p;\n\t"
                     "mbarrier.try_wait.parity.acquire.cta.shared::cta.b64 p, [%1], %2, 0x989680;\n\t"
                     "selp.b32 %0, 1, 0, p;\n\t}"
                     : "=r"(done) : "r"(mbar), "r"(parity) : "memory");
    }
}

__device__ __forceinline__ void mma_tf32(uint32_t d, uint64_t da, uint64_t db,
                                         uint32_t idesc, uint32_t en) {
    asm volatile(
        "{\n\t.reg .pred p;\n\tsetp.ne.u32 p, %4, 0;\n\t"
        "tcgen05.mma.cta_group::1.kind::tf32 [%0], %1, %2, %3, {%5, %5, %5, %5}, p;\n\t}"
        :: "r"(d), "l"(da), "l"(db), "r"(idesc), "r"(en), "r"(0u)
        : "memory");
}

#define TC_COMMIT(mbar) \
    asm volatile("tcgen05.commit.cta_group::1.mbarrier::arrive::one.shared::cluster.b64 [%0];" \
                 :: "r"(mbar) : "memory")

#define LDTM_X32(r, addr) \
    asm volatile("tcgen05.ld.sync.aligned.32x32b.x32.b32 " \
        "{%0,%1,%2,%3,%4,%5,%6,%7,%8,%9,%10,%11,%12,%13,%14,%15," \
        "%16,%17,%18,%19,%20,%21,%22,%23,%24,%25,%26,%27,%28,%29,%30,%31}, [%32];" \
        : "=r"((r)[0]),  "=r"((r)[1]),  "=r"((r)[2]),  "=r"((r)[3]), \
          "=r"((r)[4]),  "=r"((r)[5]),  "=r"((r)[6]),  "=r"((r)[7]), \
          "=r"((r)[8]),  "=r"((r)[9]),  "=r"((r)[10]), "=r"((r)[11]), \
          "=r"((r)[12]), "=r"((r)[13]), "=r"((r)[14]), "=r"((r)[15]), \
          "=r"((r)[16]), "=r"((r)[17]), "=r"((r)[18]), "=r"((r)[19]), \
          "=r"((r)[20]), "=r"((r)[21]), "=r"((r)[22]), "=r"((r)[23]), \
          "=r"((r)[24]), "=r"((r)[25]), "=r"((r)[26]), "=r"((r)[27]), \
          "=r"((r)[28]), "=r"((r)[29]), "=r"((r)[30]), "=r"((r)[31]) \
        : "r"(addr))

static __device__ __forceinline__ uint64_t make_desc(uint32_t addr) {
    const uint64_t base = (2ULL << 61) | (1ULL << 46) | (64ULL << 32) | (1ULL << 16);
    return base | ((uint64_t)(addr >> 4) & 0x3FFF);
}

// idesc: dtype=F32(1<<4), atype=btype=TF32(2), M=128 ((M/16)<<24)
#define IDESC_TF32  ((1u << 4) | (2u << 7) | (2u << 10) | (16u << 17) | (8u << 24))
#define IDESC_TF32_N256 ((1u << 4) | (2u << 7) | (2u << 10) | (32u << 17) | (8u << 24))
#endif  // TCPATH

// ============================================================
// tc_gemm: 128x128 tile (validated path, unchanged from R6)
// C[M,N] (op)= alpha * A[M,K] * B[N,K]^T ; A,B tf32-pre-rounded.
// mode 0: C=alpha*acc  1: C+=alpha*acc  2: silu(clip)  3: silu(G)*acc
// mode 4: atomicAdd(C, alpha*acc) (split-K)
// grid = (N/128, M/128, batch*ksplit)
// ============================================================
#define TCG_SMEM (2048 + 3 * 32768)   // 100352

__global__ __launch_bounds__(256)
void tc_gemm(const float* __restrict__ A, const float* __restrict__ B,
             float* __restrict__ C, const float* __restrict__ G,
             int M, int N, int K, long sA, long sB, long sC,
             float alpha, int mode, int ksplit, int rnd)
{
    extern __shared__ char smem[];
    const int tid  = threadIdx.x;
    const int wid  = tid >> 5;
    const int lane = tid & 31;

    int Kc;
    {
        int bz = blockIdx.z;
        long b = bz / ksplit;
        int ik = bz - (int)b * ksplit;
        Kc = K / ksplit;
        A += b * sA + (long)ik * Kc;
        B += b * sB + (long)ik * Kc;
        C += b * sC;
        if (mode == 3) G += b * sC;
    }
    const int m0 = blockIdx.y * 128, n0 = blockIdx.x * 128;
    const float* Ap = A + (long)m0 * K;
    const float* Bp = B + (long)n0 * K;
    const int nch = Kc >> 5;

#ifdef TCPATH
    uint32_t sbase = smem_u32(smem);
    const uint32_t TM_PTR = sbase;
    const uint32_t MB0 = sbase + 16;
    const uint32_t MB1 = sbase + 24;
    const uint32_t MB2 = sbase + 32;
    uint32_t data0 = (sbase + 1024 + 1023) & ~1023u;

    if (wid == 0) {
        asm volatile("tcgen05.alloc.cta_group::1.sync.aligned.shared::cta.b32 [%0], %1;"
                     :: "r"(TM_PTR), "r"(128u) : "memory");
        asm volatile("tcgen05.relinquish_alloc_permit.cta_group::1.sync.aligned;");
    }
    if (tid == 0) { MBAR_INIT(MB0, 1); MBAR_INIT(MB1, 1); MBAR_INIT(MB2, 1); }
    __syncthreads();
    uint32_t tmem;
    asm volatile("ld.shared.b32 %0, [%1];" : "=r"(tmem) : "r"(TM_PTR));

#define ISSUE_CP(c, b) do {                                                  \
        const int k0_ = (c) << 5;                                            \
        const uint32_t so_ = (uint32_t)(b) * 32768u;                         \
        _Pragma("unroll")                                                    \
        for (int it_ = 0; it_ < 8; it_++) {                                  \
            int idx_ = it_ * 256 + tid;                                      \
            int r_ = idx_ >> 3, q_ = idx_ & 7;                               \
            const float* src_ = (r_ < 128)                                   \
                ? (Ap + (long)r_ * K + k0_ + q_ * 4)                         \
                : (Bp + (long)(r_ - 128) * K + k0_ + q_ * 4);                \
            uint32_t off_ = (uint32_t)(r_ * 128 + q_ * 16);                  \
            uint32_t sw_ = off_ ^ ((off_ >> 3) & 0x70u);                     \
            asm volatile("cp.async.cg.shared.global [%0], [%1], 16;"         \
                :: "r"(data0 + so_ + sw_), "l"(src_) : "memory");            \
        }                                                                    \
        asm volatile("cp.async.commit_group;" ::: "memory");                 \
    } while (0)

    int ph0 = 0, ph1 = 0, ph2 = 0;
    ISSUE_CP(0, 0);
    ISSUE_CP(1, 1);

    for (int i = 0; i < nch; i++) {
        const int ip2 = i + 2;
        if (ip2 < nch) {
            const int b = ip2 % 3;
            if (i >= 1) {
                if (b == 0)      { mbar_wait(MB0, ph0); ph0 ^= 1; }
                else if (b == 1) { mbar_wait(MB1, ph1); ph1 ^= 1; }
                else             { mbar_wait(MB2, ph2); ph2 ^= 1; }
            }
            ISSUE_CP(ip2, b);
        }
        if (ip2 < nch)          asm volatile("cp.async.wait_group 2;" ::: "memory");
        else if (i + 1 < nch)   asm volatile("cp.async.wait_group 1;" ::: "memory");
        else                    asm volatile("cp.async.wait_group 0;" ::: "memory");
        asm volatile("fence.proxy.async.shared::cta;" ::: "memory");
        __syncthreads();
        if (wid == 0 && elect1()) {
            const int bi = i % 3;
            uint64_t da = make_desc(data0 + (uint32_t)bi * 32768u);
            uint64_t db = make_desc(data0 + (uint32_t)bi * 32768u + 16384u);
#pragma unroll
            for (int ks = 0; ks < 4; ks++)
                mma_tf32(tmem, da + ks * 2, db + ks * 2, IDESC_TF32,
                         (i > 0 || ks > 0) ? 1u : 0u);
            if (bi == 0)      TC_COMMIT(MB0);
            else if (bi == 1) TC_COMMIT(MB1);
            else              TC_COMMIT(MB2);
        }
    }
    mbar_wait(MB0, ph0);
    mbar_wait(MB1, ph1);
    mbar_wait(MB2, ph2);
    asm volatile("tcgen05.fence::after_thread_sync;" ::: "memory");
#undef ISSUE_CP

    if (wid < 4) {
        float* Crow = C + (long)(m0 + wid * 32 + lane) * N + n0;
        const float* Grow = (mode == 3)
            ? (G + (long)(m0 + wid * 32 + lane) * N + n0) : nullptr;
#pragma unroll
        for (int cb = 0; cb < 128; cb += 32) {
            uint32_t r[32];
            LDTM_X32(r, tmem + cb);
            asm volatile("tcgen05.wait::ld.sync.aligned;" ::: "memory");
            if (mode == 4) {
#pragma unroll
                for (int j = 0; j < 32; j++)
                    atomicAdd(Crow + cb + j, alpha * __uint_as_float(r[j]));
            } else {
#pragma unroll
                for (int j = 0; j < 32; j += 4) {
                    float4 v;
                    v.x = __uint_as_float(r[j + 0]);
                    v.y = __uint_as_float(r[j + 1]);
                    v.z = __uint_as_float(r[j + 2]);
                    v.w = __uint_as_float(r[j + 3]);
                    if (mode == 0) {
                        v.x *= alpha; v.y *= alpha; v.z *= alpha; v.w *= alpha;
                    } else if (mode == 1) {
                        float4 c = *(const float4*)(Crow + cb + j);
                        v.x = fmaf(alpha, v.x, c.x); v.y = fmaf(alpha, v.y, c.y);
                        v.z = fmaf(alpha, v.z, c.z); v.w = fmaf(alpha, v.w, c.w);
                    } else if (mode == 2) {
                        v.x = silu_f(fminf(5.f, fmaxf(-5.f, v.x)));
                        v.y = silu_f(fminf(5.f, fmaxf(-5.f, v.y)));
                        v.z = silu_f(fminf(5.f, fmaxf(-5.f, v.z)));
                        v.w = silu_f(fminf(5.f, fmaxf(-5.f, v.w)));
                    } else {
                        float4 g = *(const float4*)(Grow + cb + j);
                        v.x *= silu_f(g.x); v.y *= silu_f(g.y);
                        v.z *= silu_f(g.z); v.w *= silu_f(g.w);
                    }
                    if (rnd) {
                        v.x = rndf(v.x); v.y = rndf(v.y);
                        v.z = rndf(v.z); v.w = rndf(v.w);
                    }
                    *(float4*)(Crow + cb + j) = v;
                }
            }
        }
    }
    asm volatile("tcgen05.fence::before_thread_sync;" ::: "memory");
    __syncthreads();
    if (wid == 0) {
        asm volatile("tcgen05.dealloc.cta_group::1.sync.aligned.b32 %0, %1;"
                     :: "r"(tmem), "r"(128u));
    }
#else
    // fallback (compile-only): naive
    for (int idx = tid; idx < 128 * 128; idx += 256) {
        int rr = idx >> 7, cc = idx & 127;
        long ci = (long)(m0 + rr) * N + n0 + cc;
        float acc = 0.f;
        for (int k = 0; k < Kc; k++)
            acc += A[(long)(m0 + rr) * K + k] * B[(long)(n0 + cc) * K + k];
        float v;
        if (mode == 4) { atomicAdd(C + ci, alpha * acc); continue; }
        else if (mode == 0) v = alpha * acc;
        else if (mode == 1) v = fmaf(alpha, acc, C[ci]);
        else if (mode == 2) v = silu_f(fminf(5.f, fmaxf(-5.f, acc)));
        else                v = silu_f(G[ci]) * acc;
        if (rnd) v = rndf(v);
        C[ci] = v;
    }
#endif
}

// ============================================================
// tc_gemm2: 256x256 tile (halved L2 traffic per FLOP).
// Two M=128 MMA dispatches share the B operand; D0 at TMEM col 0,
// D1 at col 256 (full 512-col TMEM). 3-stage cp.async, 64KB/stage.
// modes 0/1/2/3 (no split-K). grid = (N/256, M/256, batch).
// Requires M%256==0, N%256==0, K%32==0, K>=128 (nch>=4).
// ============================================================
#define TCG2_SMEM (2048 + 3 * 65536)   // 198656

__global__ __launch_bounds__(256)
void tc_gemm2(const float* __restrict__ A, const float* __restrict__ B,
              float* __restrict__ C, const float* __restrict__ G,
              int M, int N, int K, long sA, long sB, long sC,
              float alpha, int mode, int rnd)
{
    extern __shared__ char smem[];
    const int tid  = threadIdx.x;
    const int wid  = tid >> 5;
    const int lane = tid & 31;

    {
        long b = blockIdx.z;
        A += b * sA; B += b * sB; C += b * sC;
        if (mode == 3) G += b * sC;
    }
    const int m0 = blockIdx.y * 256, n0 = blockIdx.x * 256;
    const float* Ap = A + (long)m0 * K;
    const float* Bp = B + (long)n0 * K;
    const int nch = K >> 5;

#ifdef TCPATH
    uint32_t sbase = smem_u32(smem);
    const uint32_t TM_PTR = sbase;
    const uint32_t MB0 = sbase + 16;
    const uint32_t MB1 = sbase + 24;
    const uint32_t MB2 = sbase + 32;
    uint32_t data0 = (sbase + 1024 + 1023) & ~1023u;

    if (wid == 0) {
        asm volatile("tcgen05.alloc.cta_group::1.sync.aligned.shared::cta.b32 [%0], %1;"
                     :: "r"(TM_PTR), "r"(512u) : "memory");
        asm volatile("tcgen05.relinquish_alloc_permit.cta_group::1.sync.aligned;");
    }
    if (tid == 0) { MBAR_INIT(MB0, 1); MBAR_INIT(MB1, 1); MBAR_INIT(MB2, 1); }
    __syncthreads();
    uint32_t tmem;
    asm volatile("ld.shared.b32 %0, [%1];" : "=r"(tmem) : "r"(TM_PTR));

    // stage = A(256 rows) + B(256 rows), 128B/row = 64KB
#define ISSUE_CP2(c, b) do {                                                 \
        const int k0_ = (c) << 5;                                            \
        const uint32_t so_ = (uint32_t)(b) * 65536u;                         \
        _Pragma("unroll")                                                    \
        for (int it_ = 0; it_ < 16; it_++) {                                 \
            int idx_ = it_ * 256 + tid;                                      \
            int r_ = idx_ >> 3, q_ = idx_ & 7;                               \
            const float* src_ = (r_ < 256)                                   \
                ? (Ap + (long)r_ * K + k0_ + q_ * 4)                         \
                : (Bp + (long)(r_ - 256) * K + k0_ + q_ * 4);                \
            uint32_t off_ = (uint32_t)(r_ * 128 + q_ * 16);                  \
            uint32_t sw_ = off_ ^ ((off_ >> 3) & 0x70u);                     \
            asm volatile("cp.async.cg.shared.global [%0], [%1], 16;"         \
                :: "r"(data0 + so_ + sw_), "l"(src_) : "memory");            \
        }                                                                    \
        asm volatile("cp.async.commit_group;" ::: "memory");                 \
    } while (0)

    int ph0 = 0, ph1 = 0, ph2 = 0;
    ISSUE_CP2(0, 0);
    ISSUE_CP2(1, 1);

    for (int i = 0; i < nch; i++) {
        const int ip2 = i + 2;
        if (ip2 < nch) {
            const int b = ip2 % 3;
            if (i >= 1) {
                if (b == 0)      { mbar_wait(MB0, ph0); ph0 ^= 1; }
                else if (b == 1) { mbar_wait(MB1, ph1); ph1 ^= 1; }
                else             { mbar_wait(MB2, ph2); ph2 ^= 1; }
            }
            ISSUE_CP2(ip2, b);
        }
        if (ip2 < nch)          asm volatile("cp.async.wait_group 2;" ::: "memory");
        else if (i + 1 < nch)   asm volatile("cp.async.wait_group 1;" ::: "memory");
        else                    asm volatile("cp.async.wait_group 0;" ::: "memory");
        asm volatile("fence.proxy.async.shared::cta;" ::: "memory");
        __syncthreads();
        if (wid == 0 && elect1()) {
            const int bi = i % 3;
            uint64_t da0 = make_desc(data0 + (uint32_t)bi * 65536u);
            uint64_t da1 = da0 + 1024;    // +16KB = A rows 128..255
            uint64_t db  = make_desc(data0 + (uint32_t)bi * 65536u + 32768u);
            uint32_t en0 = (i > 0) ? 1u : 0u;
#pragma unroll
            for (int ks = 0; ks < 4; ks++) {
                uint32_t en = (en0 || ks > 0) ? 1u : 0u;
                mma_tf32(tmem,       da0 + ks * 2, db + ks * 2, IDESC_TF32_N256, en);
                mma_tf32(tmem + 256, da1 + ks * 2, db + ks * 2, IDESC_TF32_N256, en);
            }
            if (bi == 0)      TC_COMMIT(MB0);
            else if (bi == 1) TC_COMMIT(MB1);
            else              TC_COMMIT(MB2);
        }
    }
    mbar_wait(MB0, ph0);
    mbar_wait(MB1, ph1);
    mbar_wait(MB2, ph2);
    asm volatile("tcgen05.fence::after_thread_sync;" ::: "memory");
#undef ISSUE_CP2

    // epilogue: warps 0-3 -> D0 (rows m0+0..127), warps 4-7 -> D1 (rows m0+128..255)
    {
        const int sp   = wid & 3;
        const int dsel = wid >> 2;
        const int row  = m0 + dsel * 128 + sp * 32 + lane;
        const uint32_t tbase = tmem + (uint32_t)dsel * 256;
        float* Crow = C + (long)row * N + n0;
        const float* Grow = (mode == 3) ? (G + (long)row * N + n0) : nullptr;
#pragma unroll
        for (int cb = 0; cb < 256; cb += 32) {
            uint32_t r[32];
            LDTM_X32(r, tbase + cb);
            asm volatile("tcgen05.wait::ld.sync.aligned;" ::: "memory");
#pragma unroll
            for (int j = 0; j < 32; j += 4) {
                float4 v;
                v.x = __uint_as_float(r[j + 0]);
                v.y = __uint_as_float(r[j + 1]);
                v.z = __uint_as_float(r[j + 2]);
                v.w = __uint_as_float(r[j + 3]);
                if (mode == 0) {
                    v.x *= alpha; v.y *= alpha; v.z *= alpha; v.w *= alpha;
                } else if (mode == 1) {
                    float4 c = *(const float4*)(Crow + cb + j);
                    v.x = fmaf(alpha, v.x, c.x); v.y = fmaf(alpha, v.y, c.y);
                    v.z = fmaf(alpha, v.z, c.z); v.w = fmaf(alpha, v.w, c.w);
                } else if (mode == 2) {
                    v.x = silu_f(fminf(5.f, fmaxf(-5.f, v.x)));
                    v.y = silu_f(fminf(5.f, fmaxf(-5.f, v.y)));
                    v.z = silu_f(fminf(5.f, fmaxf(-5.f, v.z)));
                    v.w = silu_f(fminf(5.f, fmaxf(-5.f, v.w)));
                } else {
                    float4 g = *(const float4*)(Grow + cb + j);
                    v.x *= silu_f(g.x); v.y *= silu_f(g.y);
                    v.z *= silu_f(g.z); v.w *= silu_f(g.w);
                }
                if (rnd) {
                    v.x = rndf(v.x); v.y = rndf(v.y);
                    v.z = rndf(v.z); v.w = rndf(v.w);
                }
                *(float4*)(Crow + cb + j) = v;
            }
        }
    }
    asm volatile("tcgen05.fence::before_thread_sync;" ::: "memory");
    __syncthreads();
    if (wid == 0) {
        asm volatile("tcgen05.dealloc.cta_group::1.sync.aligned.b32 %0, %1;"
                     :: "r"(tmem), "r"(512u));
    }
#else
    // fallback (compile-only): naive
    for (int idx = tid; idx < 256 * 256; idx += 256) {
        int rr = idx >> 8, cc = idx & 255;
        long ci = (long)(m0 + rr) * N + n0 + cc;
        float acc = 0.f;
        for (int k = 0; k < K; k++)
            acc += A[(long)(m0 + rr) * K + k] * B[(long)(n0 + cc) * K + k];
        float v;
        if (mode == 0)      v = alpha * acc;
        else if (mode == 1) v = fmaf(alpha, acc, C[ci]);
        else if (mode == 2) v = silu_f(fminf(5.f, fmaxf(-5.f, acc)));
        else                v = silu_f(G[ci]) * acc;
        if (rnd) v = rndf(v);
        C[ci] = v;
    }
#endif
}

// ============================================================
// Small helpers
// ============================================================
__global__ void zero_kernel(float* p, long n)
{
    long i = (long)blockIdx.x * blockDim.x + threadIdx.x;
    long stride = (long)gridDim.x * blockDim.x;
    for (; i < n; i += stride) p[i] = 0.f;
}

__global__ void rnd_kernel(const float* __restrict__ in, float* __restrict__ out, long n)
{
    long i = (long)blockIdx.x * blockDim.x + threadIdx.x;
    long stride = (long)gridDim.x * blockDim.x;
    for (long j = i * 4; j < n; j += stride * 4) {
        float4 v = *(const float4*)(in + j);
        v.x = rndf(v.x); v.y = rndf(v.y); v.z = rndf(v.z); v.w = rndf(v.w);
        *(float4*)(out + j) = v;
    }
}

__global__ void transpose_kernel(const float* __restrict__ in, float* __restrict__ out,
                                 int R, int C, long sIn, long sOut)
{
    __shared__ float tile[32][33];
    in  += (long)blockIdx.z * sIn;
    out += (long)blockIdx.z * sOut;
    int r0 = blockIdx.y * 32, c0 = blockIdx.x * 32;
    int tx = threadIdx.x, ty = threadIdx.y;
#pragma unroll
    for (int i = 0; i < 32; i += 8)
        tile[ty + i][tx] = in[(long)(r0 + ty + i) * C + c0 + tx];
    __syncthreads();
#pragma unroll
    for (int i = 0; i < 32; i += 8)
        out[(long)(c0 + ty + i) * R + r0 + tx] = rndf(tile[tx][ty + i]);
}

__device__ __forceinline__ float2 block_mean_var_128(float v)
{
    float s = v, s2 = v * v;
#pragma unroll
    for (int o = 16; o > 0; o >>= 1) {
        s  += __shfl_xor_sync(0xffffffffu, s,  o);
        s2 += __shfl_xor_sync(0xffffffffu, s2, o);
    }
    __shared__ float sh[8];
    int w = threadIdx.x >> 5;
    if ((threadIdx.x & 31) == 0) { sh[w] = s; sh[4 + w] = s2; }
    __syncthreads();
    s  = sh[0] + sh[1] + sh[2] + sh[3];
    s2 = sh[4] + sh[5] + sh[6] + sh[7];
    __syncthreads();
    float m = s * (1.f / 128.f);
    return make_float2(m, s2 * (1.f / 128.f) - m * m);
}

__global__ void ln_kernel(const float* __restrict__ in, float* __restrict__ out,
                          const float* __restrict__ g, const float* __restrict__ b)
{
    long row = blockIdx.x;
    int  t   = threadIdx.x;
    float v  = in[row * 128 + t];
    float2 mv = block_mean_var_128(v);
    float inv = rsqrtf(mv.y + 1e-5f);
    out[row * 128 + t] = rndf((v - mv.x) * inv * g[t] + b[t]);
}

__global__ void expert_select_kernel(const float* __restrict__ ew,
                                     const float* __restrict__ Eall,
                                     const float* __restrict__ eln_g,
                                     const float* __restrict__ eln_b,
                                     float* __restrict__ Ecomp)
{
    long m = blockIdx.x;
    int  t = threadIdx.x;
    __shared__ int sidx;
    if (t == 0) {
        int idx = -1;
        const float* w = ew + m * EE;
#pragma unroll
        for (int i = 0; i < EE; i++) if (w[i] > 0.f) idx = i;
        sidx = idx;
    }
    __syncthreads();
    int idx = sidx;
    float o = 0.f;
    if (idx >= 0) {
        float v = Eall[m * (EE * AA) + idx * AA + t];
        float2 mv = block_mean_var_128(v);
        float inv = rsqrtf(mv.y + 1e-5f);
        o = rndf((v - mv.x) * inv * eln_g[idx * AA + t] + eln_b[idx * AA + t]);
    }
    Ecomp[m * AA + t] = o;
}

// ============================================================
// Launch
// ============================================================
extern "C" void kernel_launch(void* const* d_in, const int* in_sizes, int n_in,
                              void* d_out, int out_size)
{
    const float* x       = (const float*)d_in[0];
    const float* ew      = (const float*)d_in[1];
    const float* w_up    = (const float*)d_in[2];
    const float* w_gate  = (const float*)d_in[3];
    const float* w_down  = (const float*)d_in[4];
    const float* w_pre   = (const float*)d_in[5];
    const float* w_post  = (const float*)d_in[6];
    const float* an_g    = (const float*)d_in[7];
    const float* an_b    = (const float*)d_in[8];
    const float* w_aproj = (const float*)d_in[9];
    const float* w_exp   = (const float*)d_in[10];
    const float* eln_g   = (const float*)d_in[11];
    const float* eln_b   = (const float*)d_in[12];
    const float* w_eproj = (const float*)d_in[13];
    const float* w_out   = (const float*)d_in[14];
    float* out = (float*)d_out;

    float *Yg, *Hid, *Pre, *PreR, *Ain, *Post, *Aout, *AiT, *AW, *Adapt, *AdaptR,
          *Eall, *Ecomp, *Wcomb, *WcombR, *W2, *W2R, *Tep, *Tap,
          *xR, *WgR, *WuR, *WdR, *WoutR, *WpreR, *WpostR, *WexpR;
    cudaGetSymbolAddress((void**)&Yg,     g_Yg);
    cudaGetSymbolAddress((void**)&Hid,    g_Hid);
    cudaGetSymbolAddress((void**)&Pre,    g_Pre);
    cudaGetSymbolAddress((void**)&PreR,   g_PreR);
    cudaGetSymbolAddress((void**)&Ain,    g_Ain);
    cudaGetSymbolAddress((void**)&Post,   g_Post);
    cudaGetSymbolAddress((void**)&Aout,   g_Aout);
    cudaGetSymbolAddress((void**)&AiT,    g_AiT);
    cudaGetSymbolAddress((void**)&AW,     g_AW);
    cudaGetSymbolAddress((void**)&Adapt,  g_Adapt);
    cudaGetSymbolAddress((void**)&AdaptR, g_AdaptR);
    cudaGetSymbolAddress((void**)&Eall,   g_Eall);
    cudaGetSymbolAddress((void**)&Ecomp,  g_Ecomp);
    cudaGetSymbolAddress((void**)&Wcomb,  g_Wcomb);
    cudaGetSymbolAddress((void**)&WcombR, g_WcombR);
    cudaGetSymbolAddress((void**)&W2,     g_W2);
    cudaGetSymbolAddress((void**)&W2R,    g_W2R);
    cudaGetSymbolAddress((void**)&Tep,    g_Tep);
    cudaGetSymbolAddress((void**)&Tap,    g_Tap);
    cudaGetSymbolAddress((void**)&xR,     g_xR);
    cudaGetSymbolAddress((void**)&WgR,    g_WgR);
    cudaGetSymbolAddress((void**)&WuR,    g_WuR);
    cudaGetSymbolAddress((void**)&WdR,    g_WdR);
    cudaGetSymbolAddress((void**)&WoutR,  g_WoutR);
    cudaGetSymbolAddress((void**)&WpreR,  g_WpreR);
    cudaGetSymbolAddress((void**)&WpostR, g_WpostR);
    cudaGetSymbolAddress((void**)&WexpR,  g_WexpR);

    cudaFuncSetAttribute(tc_gemm,  cudaFuncAttributeMaxDynamicSharedMemorySize, TCG_SMEM);
    cudaFuncSetAttribute(tc_gemm2, cudaFuncAttributeMaxDynamicSharedMemorySize, TCG2_SMEM);

    dim3 tb32(32, 8);

    // ---- round raw inputs to tf32 once ----
    rnd_kernel<<<512, 256>>>(x,      xR,     (long)MM * DD);
    rnd_kernel<<<128, 256>>>(w_gate, WgR,    (long)HH * DD);
    rnd_kernel<<<128, 256>>>(w_up,   WuR,    (long)HH * DD);
    rnd_kernel<<<128, 256>>>(w_down, WdR,    (long)DD * HH);
    rnd_kernel<<<128, 256>>>(w_out,  WoutR,  (long)DD * HH);
    rnd_kernel<<<32,  256>>>(w_pre,  WpreR,  (long)AA * DD);
    rnd_kernel<<<32,  256>>>(w_post, WpostR, (long)AA * HH);
    rnd_kernel<<<32,  256>>>(w_exp,  WexpR,  (long)EE * AA * AA);

    // ---- zero split-K atomic targets ----
    zero_kernel<<<64,  256>>>(Wcomb, (long)DD * AA);
    zero_kernel<<<64,  256>>>(W2,    (long)DD * AA);
    zero_kernel<<<256, 256>>>(Pre,   (long)MM * AA);
    zero_kernel<<<256, 256>>>(Post,  (long)MM * AA);
    zero_kernel<<<256, 256>>>(Adapt, (long)MM * AA);

    // ---- weight-only precomputes (split-K 16, atomic; 128-tile kernel) ----
    transpose_kernel<<<dim3(AA / 32, HH / 32, 1), tb32>>>(w_eproj, Tep, HH, AA, 0, 0);
    transpose_kernel<<<dim3(AA / 32, HH / 32, 1), tb32>>>(w_aproj, Tap, HH, AA, 0, 0);
    tc_gemm<<<dim3(1, DD / 128, 16), 256, TCG_SMEM>>>(WoutR, Tep, Wcomb, nullptr,
                                                      DD, AA, HH, 0, 0, 0, 1.f, 4, 16, 0);
    tc_gemm<<<dim3(1, DD / 128, 16), 256, TCG_SMEM>>>(WdR, Tap, W2, nullptr,
                                                      DD, AA, HH, 0, 0, 0, 1.f, 4, 16, 0);
    rnd_kernel<<<32, 256>>>(Wcomb, WcombR, (long)DD * AA);
    rnd_kernel<<<32, 256>>>(W2,    W2R,    (long)DD * AA);

    // ---- gate, then fused up*silu(gate) -> Hid (256-tile) ----
    tc_gemm2<<<dim3(HH / 256, MM / 256, 1), 256, TCG2_SMEM>>>(xR, WgR, Yg, nullptr,
                                                              MM, HH, DD, 0, 0, 0, 1.f, 0, 0);
    tc_gemm2<<<dim3(HH / 256, MM / 256, 1), 256, TCG2_SMEM>>>(xR, WuR, Hid, Yg,
                                                              MM, HH, DD, 0, 0, 0, 1.f, 3, 1);

    // ---- pre / adapt_in (128-tile) ----
    tc_gemm<<<dim3(1, MM / 128, 2), 256, TCG_SMEM>>>(xR, WpreR, Pre, nullptr,
                                                     MM, AA, DD, 0, 0, 0, 1.f, 4, 2, 0);
    rnd_kernel<<<256, 256>>>(Pre, PreR, (long)MM * AA);
    ln_kernel<<<MM, 128>>>(Pre, Ain, an_g, an_b);

    // ---- post / adapt_out (128-tile) ----
    tc_gemm<<<dim3(1, MM / 128, 2), 256, TCG_SMEM>>>(Hid, WpostR, Post, nullptr,
                                                     MM, AA, HH, 0, 0, 0, 1.f, 4, 2, 0);
    ln_kernel<<<MM, 128>>>(Post, Aout, an_g, an_b);

    // ---- adapt attention ----
    transpose_kernel<<<dim3(AA / 32, SS / 32, BB), tb32>>>(Ain, AiT, SS, AA,
                                                           (long)SS * AA, (long)SS * AA);
    // AW = silu(clip(Ain @ Aout^T)) (256-tile, fused epilogue)
    tc_gemm2<<<dim3(SS / 256, SS / 256, BB), 256, TCG2_SMEM>>>(Ain, Aout, AW, nullptr,
                                                               SS, SS, AA,
                                                               (long)SS * AA, (long)SS * AA,
                                                               (long)SS * SS, 1.f, 2, 1);
    // Adapt = AW @ AiT^T (128-tile, batch 8, split-K 2, atomic)
    tc_gemm<<<dim3(1, SS / 128, BB * 2), 256, TCG_SMEM>>>(AW, AiT, Adapt, nullptr,
                                                          SS, AA, SS,
                                                          (long)SS * SS, (long)AA * SS,
                                                          (long)SS * AA, 1.f, 4, 2, 0);
    rnd_kernel<<<256, 256>>>(Adapt, AdaptR, (long)MM * AA);

    // ---- out = Hid @ w_down^T (256-tile) ----
    tc_gemm2<<<dim3(DD / 256, MM / 256, 1), 256, TCG2_SMEM>>>(Hid, WdR, out, nullptr,
                                                              MM, DD, HH, 0, 0, 0, 1.f, 0, 0);
    // out += 0.1 * AdaptR @ W2R^T (256-tile, K=128)
    tc_gemm2<<<dim3(DD / 256, MM / 256, 1), 256, TCG2_SMEM>>>(AdaptR, W2R, out, nullptr,
                                                              MM, DD, AA, 0, 0, 0, 0.1f, 1, 0);

    // ---- experts (256-tile) ----
    tc_gemm2<<<dim3(EE * AA / 256, MM / 256, 1), 256, TCG2_SMEM>>>(PreR, WexpR, Eall, nullptr,
                                                                   MM, EE * AA, AA,
                                                                   0, 0, 0, 1.f, 0, 0);
    expert_select_kernel<<<MM, 128>>>(ew, Eall, eln_g, eln_b, Ecomp);
    // out += 0.1 * Ecomp @ WcombR^T (256-tile, K=128)
    tc_gemm2<<<dim3(DD / 256, MM / 256, 1), 256, TCG2_SMEM>>>(Ecomp, WcombR, out, nullptr,
                                                              MM, DD, AA, 0, 0, 0, 0.1f, 1, 0);
}

// round 8
// speedup vs baseline: 1.0174x; 1.0174x over previous
#include <cuda_runtime.h>
#include <cuda_bf16.h>
#include <cstdint>

// Problem dims (fixed)
#define BB 8
#define SS 2048
#define DD 1024
#define HH 2048
#define AA 128
#define EE 8
#define MM (BB*SS)   // 16384 tokens

// tcgen05 is arch-SPECIFIC (sm_103a). Only use it in an arch-specific pass.
#if defined(__CUDA_ARCH_FEAT_SM103_ALL)
#define TCPATH 1
#endif

// -------- scratch (device globals; no allocation allowed) --------
__device__ float g_Yg[MM*HH];          // gate pre-act (exact fp32)
__device__ float g_Hid[MM*HH];         // hidden0 = silu(gate)*up (tf32-rounded)
__device__ float g_Pre[MM*AA];         // exact (atomic target)
__device__ float g_PreR[MM*AA];        // rounded copy for GEMM A
__device__ float g_Ain[MM*AA];         // LN(pre), rounded
__device__ float g_Post[MM*AA];        // exact (atomic target)
__device__ float g_Aout[MM*AA];        // LN(post), rounded
__device__ float g_AiT[BB*AA*SS];      // adapt_in transposed per batch [A,S], rounded
__device__ float g_AdaptR[MM*AA];      // fused adapt output, rounded
__device__ float g_Eall[MM*EE*AA];     // experts' pre-LN activations (exact)
__device__ float g_Ecomp[MM*AA];       // selected+LN'd expert act, rounded
__device__ float g_Wcomb[DD*AA];       // w_out @ w_eproj (exact, atomic)
__device__ float g_WcombR[DD*AA];      // rounded
__device__ float g_W2[DD*AA];          // w_down @ w_aproj (exact, atomic)
__device__ float g_W2R[DD*AA];         // rounded
__device__ float g_Tep[AA*HH];         // w_eproj^T, rounded
__device__ float g_Tap[AA*HH];         // w_aproj^T, rounded
// rounded raw inputs
__device__ float g_xR[MM*DD];
__device__ float g_WgR[HH*DD];
__device__ float g_WuR[HH*DD];
__device__ float g_WdR[DD*HH];
__device__ float g_WoutR[DD*HH];
__device__ float g_WpreR[AA*DD];
__device__ float g_WpostR[AA*HH];
__device__ float g_WexpR[EE*AA*AA];

// ============================================================
// common helpers
// ============================================================
__device__ __forceinline__ float silu_f(float v) {
    return v * __frcp_rn(1.f + __expf(-v));
}

__device__ __forceinline__ uint32_t f2tf32(float f) {
    uint32_t u;
    asm("cvt.rna.tf32.f32 %0, %1;" : "=r"(u) : "f"(f));
    return u;
}
__device__ __forceinline__ float rndf(float f) {
    return __uint_as_float(f2tf32(f));
}

#ifdef TCPATH
// ============================================================
// tcgen05 helpers (sm_103a-specific pass only)
// ============================================================
__device__ __forceinline__ uint32_t smem_u32(const void* p) {
    uint32_t a;
    asm("{ .reg .u64 t; cvta.to.shared.u64 t, %1; cvt.u32.u64 %0, t; }"
        : "=r"(a) : "l"(p));
    return a;
}

__device__ __forceinline__ uint32_t elect1() {
    uint32_t p;
    asm volatile("{\n\t.reg .pred p;\n\telect.sync _|p, 0xFFFFFFFF;\n\t"
                 "selp.b32 %0, 1, 0, p;\n\t}" : "=r"(p));
    return p;
}

#define MBAR_INIT(addr, cnt) \
    asm volatile("mbarrier.init.shared.b64 [%0], %1;" :: "r"(addr), "r"(cnt) : "memory")

__device__ __forceinline__ void mbar_wait(uint32_t mbar, uint32_t parity) {
    uint32_t done;
    asm volatile("{\n\t.reg .pred p;\n\t"
                 "mbarrier.try_wait.parity.acquire.cta.shared::cta.b64 p, [%1], %2;\n\t"
                 "selp.b32 %0, 1, 0, p;\n\t}"
                 : "=r"(done) : "r"(mbar), "r"(parity) : "memory");
    while (!done) {
        asm volatile("{\n\t.reg .pred p;\n\t"
                     "mbarrier.try_wait.parity.acquire.cta.shared::cta.b64 p, [%1], %2, 0x989680;\n\t"
                     "selp.b32 %0, 1, 0, p;\n\t}"
                     : "=r"(done) : "r"(mbar), "r"(parity) : "memory");
    }
}

__device__ __forceinline__ void mma_tf32(uint32_t d, uint64_t da, uint64_t db,
                                         uint32_t idesc, uint32_t en) {
    asm volatile(
        "{\n\t.reg .pred p;\n\tsetp.ne.u32 p, %4, 0;\n\t"
        "tcgen05.mma.cta_group::1.kind::tf32 [%0], %1, %2, %3, {%5, %5, %5, %5}, p;\n\t}"
        :: "r"(d), "l"(da), "l"(db), "r"(idesc), "r"(en), "r"(0u)
        : "memory");
}

#define TC_COMMIT(mbar) \
    asm volatile("tcgen05.commit.cta_group::1.mbarrier::arrive::one.shared::cluster.b64 [%0];" \
                 :: "r"(mbar) : "memory")

#define LDTM_X32(r, addr) \
    asm volatile("tcgen05.ld.sync.aligned.32x32b.x32.b32 " \
        "{%0,%1,%2,%3,%4,%5,%6,%7,%8,%9,%10,%11,%12,%13,%14,%15," \
        "%16,%17,%18,%19,%20,%21,%22,%23,%24,%25,%26,%27,%28,%29,%30,%31}, [%32];" \
        : "=r"((r)[0]),  "=r"((r)[1]),  "=r"((r)[2]),  "=r"((r)[3]), \
          "=r"((r)[4]),  "=r"((r)[5]),  "=r"((r)[6]),  "=r"((r)[7]), \
          "=r"((r)[8]),  "=r"((r)[9]),  "=r"((r)[10]), "=r"((r)[11]), \
          "=r"((r)[12]), "=r"((r)[13]), "=r"((r)[14]), "=r"((r)[15]), \
          "=r"((r)[16]), "=r"((r)[17]), "=r"((r)[18]), "=r"((r)[19]), \
          "=r"((r)[20]), "=r"((r)[21]), "=r"((r)[22]), "=r"((r)[23]), \
          "=r"((r)[24]), "=r"((r)[25]), "=r"((r)[26]), "=r"((r)[27]), \
          "=r"((r)[28]), "=r"((r)[29]), "=r"((r)[30]), "=r"((r)[31]) \
        : "r"(addr))

static __device__ __forceinline__ uint64_t make_desc(uint32_t addr) {
    const uint64_t base = (2ULL << 61) | (1ULL << 46) | (64ULL << 32) | (1ULL << 16);
    return base | ((uint64_t)(addr >> 4) & 0x3FFF);
}

// idesc: dtype=F32(1<<4), atype=btype=TF32(2), N=128 ((N/8)<<17), M=128 ((M/16)<<24)
#define IDESC_TF32 ((1u << 4) | (2u << 7) | (2u << 10) | (16u << 17) | (8u << 24))
#endif  // TCPATH

// ============================================================
// tc_gemm: 128x128 tile (validated R6 path, unchanged)
// C[M,N] (op)= alpha * A[M,K] * B[N,K]^T ; A,B tf32-pre-rounded.
// mode 0: C=alpha*acc  1: C+=alpha*acc  2: silu(clip)  3: silu(G)*acc
// mode 4: atomicAdd(C, alpha*acc) (split-K)
// grid = (N/128, M/128, batch*ksplit)
// ============================================================
#define TCG_SMEM (2048 + 3 * 32768)   // 100352

__global__ __launch_bounds__(256)
void tc_gemm(const float* __restrict__ A, const float* __restrict__ B,
             float* __restrict__ C, const float* __restrict__ G,
             int M, int N, int K, long sA, long sB, long sC,
             float alpha, int mode, int ksplit, int rnd)
{
    extern __shared__ char smem[];
    const int tid  = threadIdx.x;
    const int wid  = tid >> 5;
    const int lane = tid & 31;

    int Kc;
    {
        int bz = blockIdx.z;
        long b = bz / ksplit;
        int ik = bz - (int)b * ksplit;
        Kc = K / ksplit;
        A += b * sA + (long)ik * Kc;
        B += b * sB + (long)ik * Kc;
        C += b * sC;
        if (mode == 3) G += b * sC;
    }
    const int m0 = blockIdx.y * 128, n0 = blockIdx.x * 128;
    const float* Ap = A + (long)m0 * K;
    const float* Bp = B + (long)n0 * K;
    const int nch = Kc >> 5;

#ifdef TCPATH
    uint32_t sbase = smem_u32(smem);
    const uint32_t TM_PTR = sbase;
    const uint32_t MB0 = sbase + 16;
    const uint32_t MB1 = sbase + 24;
    const uint32_t MB2 = sbase + 32;
    uint32_t data0 = (sbase + 1024 + 1023) & ~1023u;

    if (wid == 0) {
        asm volatile("tcgen05.alloc.cta_group::1.sync.aligned.shared::cta.b32 [%0], %1;"
                     :: "r"(TM_PTR), "r"(128u) : "memory");
        asm volatile("tcgen05.relinquish_alloc_permit.cta_group::1.sync.aligned;");
    }
    if (tid == 0) { MBAR_INIT(MB0, 1); MBAR_INIT(MB1, 1); MBAR_INIT(MB2, 1); }
    __syncthreads();
    uint32_t tmem;
    asm volatile("ld.shared.b32 %0, [%1];" : "=r"(tmem) : "r"(TM_PTR));

#define ISSUE_CP(c, b) do {                                                  \
        const int k0_ = (c) << 5;                                            \
        const uint32_t so_ = (uint32_t)(b) * 32768u;                         \
        _Pragma("unroll")                                                    \
        for (int it_ = 0; it_ < 8; it_++) {                                  \
            int idx_ = it_ * 256 + tid;                                      \
            int r_ = idx_ >> 3, q_ = idx_ & 7;                               \
            const float* src_ = (r_ < 128)                                   \
                ? (Ap + (long)r_ * K + k0_ + q_ * 4)                         \
                : (Bp + (long)(r_ - 128) * K + k0_ + q_ * 4);                \
            uint32_t off_ = (uint32_t)(r_ * 128 + q_ * 16);                  \
            uint32_t sw_ = off_ ^ ((off_ >> 3) & 0x70u);                     \
            asm volatile("cp.async.cg.shared.global [%0], [%1], 16;"         \
                :: "r"(data0 + so_ + sw_), "l"(src_) : "memory");            \
        }                                                                    \
        asm volatile("cp.async.commit_group;" ::: "memory");                 \
    } while (0)

    int ph0 = 0, ph1 = 0, ph2 = 0;
    ISSUE_CP(0, 0);
    ISSUE_CP(1, 1);

    for (int i = 0; i < nch; i++) {
        const int ip2 = i + 2;
        if (ip2 < nch) {
            const int b = ip2 % 3;
            if (i >= 1) {
                if (b == 0)      { mbar_wait(MB0, ph0); ph0 ^= 1; }
                else if (b == 1) { mbar_wait(MB1, ph1); ph1 ^= 1; }
                else             { mbar_wait(MB2, ph2); ph2 ^= 1; }
            }
            ISSUE_CP(ip2, b);
        }
        if (ip2 < nch)          asm volatile("cp.async.wait_group 2;" ::: "memory");
        else if (i + 1 < nch)   asm volatile("cp.async.wait_group 1;" ::: "memory");
        else                    asm volatile("cp.async.wait_group 0;" ::: "memory");
        asm volatile("fence.proxy.async.shared::cta;" ::: "memory");
        __syncthreads();
        if (wid == 0 && elect1()) {
            const int bi = i % 3;
            uint64_t da = make_desc(data0 + (uint32_t)bi * 32768u);
            uint64_t db = make_desc(data0 + (uint32_t)bi * 32768u + 16384u);
#pragma unroll
            for (int ks = 0; ks < 4; ks++)
                mma_tf32(tmem, da + ks * 2, db + ks * 2, IDESC_TF32,
                         (i > 0 || ks > 0) ? 1u : 0u);
            if (bi == 0)      TC_COMMIT(MB0);
            else if (bi == 1) TC_COMMIT(MB1);
            else              TC_COMMIT(MB2);
        }
    }
    mbar_wait(MB0, ph0);
    mbar_wait(MB1, ph1);
    mbar_wait(MB2, ph2);
    asm volatile("tcgen05.fence::after_thread_sync;" ::: "memory");
#undef ISSUE_CP

    if (wid < 4) {
        float* Crow = C + (long)(m0 + wid * 32 + lane) * N + n0;
        const float* Grow = (mode == 3)
            ? (G + (long)(m0 + wid * 32 + lane) * N + n0) : nullptr;
#pragma unroll
        for (int cb = 0; cb < 128; cb += 32) {
            uint32_t r[32];
            LDTM_X32(r, tmem + cb);
            asm volatile("tcgen05.wait::ld.sync.aligned;" ::: "memory");
            if (mode == 4) {
#pragma unroll
                for (int j = 0; j < 32; j++)
                    atomicAdd(Crow + cb + j, alpha * __uint_as_float(r[j]));
            } else {
#pragma unroll
                for (int j = 0; j < 32; j += 4) {
                    float4 v;
                    v.x = __uint_as_float(r[j + 0]);
                    v.y = __uint_as_float(r[j + 1]);
                    v.z = __uint_as_float(r[j + 2]);
                    v.w = __uint_as_float(r[j + 3]);
                    if (mode == 0) {
                        v.x *= alpha; v.y *= alpha; v.z *= alpha; v.w *= alpha;
                    } else if (mode == 1) {
                        float4 c = *(const float4*)(Crow + cb + j);
                        v.x = fmaf(alpha, v.x, c.x); v.y = fmaf(alpha, v.y, c.y);
                        v.z = fmaf(alpha, v.z, c.z); v.w = fmaf(alpha, v.w, c.w);
                    } else if (mode == 2) {
                        v.x = silu_f(fminf(5.f, fmaxf(-5.f, v.x)));
                        v.y = silu_f(fminf(5.f, fmaxf(-5.f, v.y)));
                        v.z = silu_f(fminf(5.f, fmaxf(-5.f, v.z)));
                        v.w = silu_f(fminf(5.f, fmaxf(-5.f, v.w)));
                    } else {
                        float4 g = *(const float4*)(Grow + cb + j);
                        v.x *= silu_f(g.x); v.y *= silu_f(g.y);
                        v.z *= silu_f(g.z); v.w *= silu_f(g.w);
                    }
                    if (rnd) {
                        v.x = rndf(v.x); v.y = rndf(v.y);
                        v.z = rndf(v.z); v.w = rndf(v.w);
                    }
                    *(float4*)(Crow + cb + j) = v;
                }
            }
        }
    }
    asm volatile("tcgen05.fence::before_thread_sync;" ::: "memory");
    __syncthreads();
    if (wid == 0) {
        asm volatile("tcgen05.dealloc.cta_group::1.sync.aligned.b32 %0, %1;"
                     :: "r"(tmem), "r"(128u));
    }
#else
    // fallback (compile-only): naive
    for (int idx = tid; idx < 128 * 128; idx += 256) {
        int rr = idx >> 7, cc = idx & 127;
        long ci = (long)(m0 + rr) * N + n0 + cc;
        float acc = 0.f;
        for (int k = 0; k < Kc; k++)
            acc += A[(long)(m0 + rr) * K + k] * B[(long)(n0 + cc) * K + k];
        float v;
        if (mode == 4) { atomicAdd(C + ci, alpha * acc); continue; }
        else if (mode == 0) v = alpha * acc;
        else if (mode == 1) v = fmaf(alpha, acc, C[ci]);
        else if (mode == 2) v = silu_f(fminf(5.f, fmaxf(-5.f, acc)));
        else                v = silu_f(G[ci]) * acc;
        if (rnd) v = rndf(v);
        C[ci] = v;
    }
#endif
}

// ============================================================
// tc_adapt: fused adapt attention (flash-style), per (batch, m-tile):
//   for kt in 0..15:
//     P = silu(clip(Ain_m @ Aout_kt^T))        (TMEM cols 0-127 -> SMEM, tf32)
//     Acc += P @ AiT_kt^T                      (TMEM cols 128-255)
//   AdaptR_m = Acc (tf32-rounded)
// SMEM: AinS 64KB (persistent) + Bsh 64KB (Aout_kt / AiT_kt shared) + Psh 64KB.
// Each 64KB tile = 4 chunk-blocks of 16KB (128 rows x 32 floats, SW128).
// grid = (16 m-tiles, 8 batches), 256 threads.
// ============================================================
#define ADP_SMEM (2048 + 3 * 65536)   // 198656

__global__ __launch_bounds__(256)
void tc_adapt(const float* __restrict__ Ain,   // [B][S][A] tf32
              const float* __restrict__ Aout,  // [B][S][A] tf32
              const float* __restrict__ AiT,   // [B][A][S] tf32
              float* __restrict__ AdaptR)      // [B][S][A] out, tf32
{
    extern __shared__ char smem[];
    const int tid  = threadIdx.x;
    const int wid  = tid >> 5;
    const int lane = tid & 31;
    const int b    = blockIdx.y;
    const int m0   = blockIdx.x * 128;

    const float* AinB  = Ain  + (long)b * SS * AA;
    const float* AoutB = Aout + (long)b * SS * AA;
    const float* AiTB  = AiT  + (long)b * AA * SS;
    float*       AdB   = AdaptR + (long)b * SS * AA;

#ifdef TCPATH
    uint32_t sbase = smem_u32(smem);
    const uint32_t TM_PTR = sbase;
    const uint32_t MB0 = sbase + 16;   // MMA1 done
    const uint32_t MB1 = sbase + 24;   // MMA2 done
    uint32_t data0 = (sbase + 1024 + 1023) & ~1023u;
    const uint32_t AinS = data0;
    const uint32_t Bsh  = data0 + 65536u;
    const uint32_t Psh  = data0 + 131072u;

    if (wid == 0) {
        asm volatile("tcgen05.alloc.cta_group::1.sync.aligned.shared::cta.b32 [%0], %1;"
                     :: "r"(TM_PTR), "r"(256u) : "memory");
        asm volatile("tcgen05.relinquish_alloc_permit.cta_group::1.sync.aligned;");
    }
    if (tid == 0) { MBAR_INIT(MB0, 1); MBAR_INIT(MB1, 1); }
    __syncthreads();
    uint32_t tmem;
    asm volatile("ld.shared.b32 %0, [%1];" : "=r"(tmem) : "r"(TM_PTR));

    // load a [128 x 128] tile (row stride ldg floats) into 4-chunk block at base
#define ADP_LOAD256(base, gptr, ldg) do {                                    \
        _Pragma("unroll")                                                    \
        for (int it_ = 0; it_ < 16; it_++) {                                 \
            int idx_ = it_ * 256 + tid;                                      \
            int c_ = idx_ >> 10, r_ = (idx_ >> 3) & 127, q_ = idx_ & 7;      \
            const float* src_ = (gptr) + (long)r_ * (ldg) + c_ * 32 + q_ * 4;\
            uint32_t off_ = (uint32_t)(r_ * 128 + q_ * 16);                  \
            uint32_t sw_ = off_ ^ ((off_ >> 3) & 0x70u);                     \
            asm volatile("cp.async.cg.shared.global [%0], [%1], 16;"         \
                :: "r"((base) + (uint32_t)c_ * 16384u + sw_), "l"(src_)      \
                : "memory");                                                 \
        }                                                                    \
        asm volatile("cp.async.commit_group;" ::: "memory");                 \
    } while (0)

    // prologue: Ain_m (persistent) + Aout_0
    ADP_LOAD256(AinS, AinB + (long)m0 * AA, AA);
    ADP_LOAD256(Bsh,  AoutB, AA);
    asm volatile("cp.async.wait_group 0;" ::: "memory");
    asm volatile("fence.proxy.async.shared::cta;" ::: "memory");
    __syncthreads();

    int ph0 = 0, ph1 = 0;
    for (int kt = 0; kt < 16; kt++) {
        // ---- MMA1: P = Ain_m @ Aout_kt^T (fresh) ----
        if (wid == 0 && elect1()) {
#pragma unroll
            for (int c = 0; c < 4; c++) {
                uint64_t da = make_desc(AinS + (uint32_t)c * 16384u);
                uint64_t db = make_desc(Bsh  + (uint32_t)c * 16384u);
#pragma unroll
                for (int ks = 0; ks < 4; ks++)
                    mma_tf32(tmem, da + ks * 2, db + ks * 2, IDESC_TF32,
                             (c > 0 || ks > 0) ? 1u : 0u);
            }
            TC_COMMIT(MB0);
        }
        mbar_wait(MB0, ph0); ph0 ^= 1;
        asm volatile("tcgen05.fence::after_thread_sync;" ::: "memory");

        // ---- warps 0-3: P epilogue (silu∘clip∘rnd -> Psh);
        //      warps 4-7: load AiT_kt into Bsh (MMA1 done with it) ----
        if (wid < 4) {
            const int r = wid * 32 + lane;
#pragma unroll
            for (int cb = 0; cb < 4; cb++) {
                uint32_t rg[32];
                LDTM_X32(rg, tmem + cb * 32);
                asm volatile("tcgen05.wait::ld.sync.aligned;" ::: "memory");
#pragma unroll
                for (int j = 0; j < 32; j += 4) {
                    float4 v;
                    v.x = rndf(silu_f(fminf(5.f, fmaxf(-5.f, __uint_as_float(rg[j + 0])))));
                    v.y = rndf(silu_f(fminf(5.f, fmaxf(-5.f, __uint_as_float(rg[j + 1])))));
                    v.z = rndf(silu_f(fminf(5.f, fmaxf(-5.f, __uint_as_float(rg[j + 2])))));
                    v.w = rndf(silu_f(fminf(5.f, fmaxf(-5.f, __uint_as_float(rg[j + 3])))));
                    uint32_t off = (uint32_t)(r * 128 + j * 4);
                    uint32_t sw = off ^ ((off >> 3) & 0x70u);
                    uint32_t addr = Psh + (uint32_t)cb * 16384u + sw;
                    asm volatile("st.shared.v4.b32 [%0], {%1, %2, %3, %4};"
                        :: "r"(addr), "r"(__float_as_uint(v.x)), "r"(__float_as_uint(v.y)),
                           "r"(__float_as_uint(v.z)), "r"(__float_as_uint(v.w)) : "memory");
                }
            }
        } else {
            const int tid2 = tid - 128;
#pragma unroll
            for (int it = 0; it < 32; it++) {
                int idx = it * 128 + tid2;
                int c = idx >> 10, r = (idx >> 3) & 127, q = idx & 7;
                const float* src = AiTB + (long)r * SS + kt * 128 + c * 32 + q * 4;
                uint32_t off = (uint32_t)(r * 128 + q * 16);
                uint32_t sw = off ^ ((off >> 3) & 0x70u);
                asm volatile("cp.async.cg.shared.global [%0], [%1], 16;"
                    :: "r"(Bsh + (uint32_t)c * 16384u + sw), "l"(src) : "memory");
            }
            asm volatile("cp.async.commit_group;" ::: "memory");
        }
        asm volatile("cp.async.wait_group 0;" ::: "memory");
        asm volatile("fence.proxy.async.shared::cta;" ::: "memory");
        __syncthreads();

        // ---- MMA2: Acc += P @ AiT_kt^T ----
        if (wid == 0 && elect1()) {
#pragma unroll
            for (int c = 0; c < 4; c++) {
                uint64_t da = make_desc(Psh + (uint32_t)c * 16384u);
                uint64_t db = make_desc(Bsh + (uint32_t)c * 16384u);
#pragma unroll
                for (int ks = 0; ks < 4; ks++)
                    mma_tf32(tmem + 128, da + ks * 2, db + ks * 2, IDESC_TF32,
                             (kt > 0 || c > 0 || ks > 0) ? 1u : 0u);
            }
            TC_COMMIT(MB1);
        }
        mbar_wait(MB1, ph1); ph1 ^= 1;

        // ---- next Aout into Bsh (MMA2 done with Bsh and Psh) ----
        if (kt < 15) {
            ADP_LOAD256(Bsh, AoutB + (long)(kt + 1) * 128 * AA, AA);
            asm volatile("cp.async.wait_group 0;" ::: "memory");
            asm volatile("fence.proxy.async.shared::cta;" ::: "memory");
            __syncthreads();
        }
    }
#undef ADP_LOAD256

    // ---- final: write AdaptR ----
    asm volatile("tcgen05.fence::after_thread_sync;" ::: "memory");
    if (wid < 4) {
        const int r = wid * 32 + lane;
        float* Crow = AdB + (long)(m0 + r) * AA;
#pragma unroll
        for (int cb = 0; cb < 128; cb += 32) {
            uint32_t rg[32];
            LDTM_X32(rg, tmem + 128 + cb);
            asm volatile("tcgen05.wait::ld.sync.aligned;" ::: "memory");
#pragma unroll
            for (int j = 0; j < 32; j += 4) {
                float4 v;
                v.x = rndf(__uint_as_float(rg[j + 0]));
                v.y = rndf(__uint_as_float(rg[j + 1]));
                v.z = rndf(__uint_as_float(rg[j + 2]));
                v.w = rndf(__uint_as_float(rg[j + 3]));
                *(float4*)(Crow + cb + j) = v;
            }
        }
    }
    asm volatile("tcgen05.fence::before_thread_sync;" ::: "memory");
    __syncthreads();
    if (wid == 0) {
        asm volatile("tcgen05.dealloc.cta_group::1.sync.aligned.b32 %0, %1;"
                     :: "r"(tmem), "r"(256u));
    }
#else
    // fallback (compile-only): naive fused
    for (int r = tid; r < 128; r += 256) {
        float acc[AA];
        for (int a = 0; a < AA; a++) acc[a] = 0.f;
        for (int s = 0; s < SS; s++) {
            float p = 0.f;
            for (int a = 0; a < AA; a++)
                p += AinB[(long)(m0 + r) * AA + a] * AoutB[(long)s * AA + a];
            p = silu_f(fminf(5.f, fmaxf(-5.f, p)));
            for (int a = 0; a < AA; a++)
                acc[a] += p * AinB[(long)s * AA + a];
        }
        for (int a = 0; a < AA; a++)
            AdB[(long)(m0 + r) * AA + a] = rndf(acc[a]);
    }
#endif
}

// ============================================================
// Small helpers
// ============================================================
__global__ void zero_kernel(float* p, long n)
{
    long i = (long)blockIdx.x * blockDim.x + threadIdx.x;
    long stride = (long)gridDim.x * blockDim.x;
    for (; i < n; i += stride) p[i] = 0.f;
}

__global__ void rnd_kernel(const float* __restrict__ in, float* __restrict__ out, long n)
{
    long i = (long)blockIdx.x * blockDim.x + threadIdx.x;
    long stride = (long)gridDim.x * blockDim.x;
    for (long j = i * 4; j < n; j += stride * 4) {
        float4 v = *(const float4*)(in + j);
        v.x = rndf(v.x); v.y = rndf(v.y); v.z = rndf(v.z); v.w = rndf(v.w);
        *(float4*)(out + j) = v;
    }
}

__global__ void transpose_kernel(const float* __restrict__ in, float* __restrict__ out,
                                 int R, int C, long sIn, long sOut)
{
    __shared__ float tile[32][33];
    in  += (long)blockIdx.z * sIn;
    out += (long)blockIdx.z * sOut;
    int r0 = blockIdx.y * 32, c0 = blockIdx.x * 32;
    int tx = threadIdx.x, ty = threadIdx.y;
#pragma unroll
    for (int i = 0; i < 32; i += 8)
        tile[ty + i][tx] = in[(long)(r0 + ty + i) * C + c0 + tx];
    __syncthreads();
#pragma unroll
    for (int i = 0; i < 32; i += 8)
        out[(long)(c0 + ty + i) * R + r0 + tx] = rndf(tile[tx][ty + i]);
}

__device__ __forceinline__ float2 block_mean_var_128(float v)
{
    float s = v, s2 = v * v;
#pragma unroll
    for (int o = 16; o > 0; o >>= 1) {
        s  += __shfl_xor_sync(0xffffffffu, s,  o);
        s2 += __shfl_xor_sync(0xffffffffu, s2, o);
    }
    __shared__ float sh[8];
    int w = threadIdx.x >> 5;
    if ((threadIdx.x & 31) == 0) { sh[w] = s; sh[4 + w] = s2; }
    __syncthreads();
    s  = sh[0] + sh[1] + sh[2] + sh[3];
    s2 = sh[4] + sh[5] + sh[6] + sh[7];
    __syncthreads();
    float m = s * (1.f / 128.f);
    return make_float2(m, s2 * (1.f / 128.f) - m * m);
}

__global__ void ln_kernel(const float* __restrict__ in, float* __restrict__ out,
                          const float* __restrict__ g, const float* __restrict__ b)
{
    long row = blockIdx.x;
    int  t   = threadIdx.x;
    float v  = in[row * 128 + t];
    float2 mv = block_mean_var_128(v);
    float inv = rsqrtf(mv.y + 1e-5f);
    out[row * 128 + t] = rndf((v - mv.x) * inv * g[t] + b[t]);
}

__global__ void expert_select_kernel(const float* __restrict__ ew,
                                     const float* __restrict__ Eall,
                                     const float* __restrict__ eln_g,
                                     const float* __restrict__ eln_b,
                                     float* __restrict__ Ecomp)
{
    long m = blockIdx.x;
    int  t = threadIdx.x;
    __shared__ int sidx;
    if (t == 0) {
        int idx = -1;
        const float* w = ew + m * EE;
#pragma unroll
        for (int i = 0; i < EE; i++) if (w[i] > 0.f) idx = i;
        sidx = idx;
    }
    __syncthreads();
    int idx = sidx;
    float o = 0.f;
    if (idx >= 0) {
        float v = Eall[m * (EE * AA) + idx * AA + t];
        float2 mv = block_mean_var_128(v);
        float inv = rsqrtf(mv.y + 1e-5f);
        o = rndf((v - mv.x) * inv * eln_g[idx * AA + t] + eln_b[idx * AA + t]);
    }
    Ecomp[m * AA + t] = o;
}

// ============================================================
// Launch
// ============================================================
extern "C" void kernel_launch(void* const* d_in, const int* in_sizes, int n_in,
                              void* d_out, int out_size)
{
    const float* x       = (const float*)d_in[0];
    const float* ew      = (const float*)d_in[1];
    const float* w_up    = (const float*)d_in[2];
    const float* w_gate  = (const float*)d_in[3];
    const float* w_down  = (const float*)d_in[4];
    const float* w_pre   = (const float*)d_in[5];
    const float* w_post  = (const float*)d_in[6];
    const float* an_g    = (const float*)d_in[7];
    const float* an_b    = (const float*)d_in[8];
    const float* w_aproj = (const float*)d_in[9];
    const float* w_exp   = (const float*)d_in[10];
    const float* eln_g   = (const float*)d_in[11];
    const float* eln_b   = (const float*)d_in[12];
    const float* w_eproj = (const float*)d_in[13];
    const float* w_out   = (const float*)d_in[14];
    float* out = (float*)d_out;

    float *Yg, *Hid, *Pre, *PreR, *Ain, *Post, *Aout, *AiT, *AdaptR,
          *Eall, *Ecomp, *Wcomb, *WcombR, *W2, *W2R, *Tep, *Tap,
          *xR, *WgR, *WuR, *WdR, *WoutR, *WpreR, *WpostR, *WexpR;
    cudaGetSymbolAddress((void**)&Yg,     g_Yg);
    cudaGetSymbolAddress((void**)&Hid,    g_Hid);
    cudaGetSymbolAddress((void**)&Pre,    g_Pre);
    cudaGetSymbolAddress((void**)&PreR,   g_PreR);
    cudaGetSymbolAddress((void**)&Ain,    g_Ain);
    cudaGetSymbolAddress((void**)&Post,   g_Post);
    cudaGetSymbolAddress((void**)&Aout,   g_Aout);
    cudaGetSymbolAddress((void**)&AiT,    g_AiT);
    cudaGetSymbolAddress((void**)&AdaptR, g_AdaptR);
    cudaGetSymbolAddress((void**)&Eall,   g_Eall);
    cudaGetSymbolAddress((void**)&Ecomp,  g_Ecomp);
    cudaGetSymbolAddress((void**)&Wcomb,  g_Wcomb);
    cudaGetSymbolAddress((void**)&WcombR, g_WcombR);
    cudaGetSymbolAddress((void**)&W2,     g_W2);
    cudaGetSymbolAddress((void**)&W2R,    g_W2R);
    cudaGetSymbolAddress((void**)&Tep,    g_Tep);
    cudaGetSymbolAddress((void**)&Tap,    g_Tap);
    cudaGetSymbolAddress((void**)&xR,     g_xR);
    cudaGetSymbolAddress((void**)&WgR,    g_WgR);
    cudaGetSymbolAddress((void**)&WuR,    g_WuR);
    cudaGetSymbolAddress((void**)&WdR,    g_WdR);
    cudaGetSymbolAddress((void**)&WoutR,  g_WoutR);
    cudaGetSymbolAddress((void**)&WpreR,  g_WpreR);
    cudaGetSymbolAddress((void**)&WpostR, g_WpostR);
    cudaGetSymbolAddress((void**)&WexpR,  g_WexpR);

    cudaFuncSetAttribute(tc_gemm,  cudaFuncAttributeMaxDynamicSharedMemorySize, TCG_SMEM);
    cudaFuncSetAttribute(tc_adapt, cudaFuncAttributeMaxDynamicSharedMemorySize, ADP_SMEM);

    dim3 tb32(32, 8);

    // ---- round raw inputs to tf32 once ----
    rnd_kernel<<<512, 256>>>(x,      xR,     (long)MM * DD);
    rnd_kernel<<<128, 256>>>(w_gate, WgR,    (long)HH * DD);
    rnd_kernel<<<128, 256>>>(w_up,   WuR,    (long)HH * DD);
    rnd_kernel<<<128, 256>>>(w_down, WdR,    (long)DD * HH);
    rnd_kernel<<<128, 256>>>(w_out,  WoutR,  (long)DD * HH);
    rnd_kernel<<<32,  256>>>(w_pre,  WpreR,  (long)AA * DD);
    rnd_kernel<<<32,  256>>>(w_post, WpostR, (long)AA * HH);
    rnd_kernel<<<32,  256>>>(w_exp,  WexpR,  (long)EE * AA * AA);

    // ---- zero split-K atomic targets ----
    zero_kernel<<<64,  256>>>(Wcomb, (long)DD * AA);
    zero_kernel<<<64,  256>>>(W2,    (long)DD * AA);
    zero_kernel<<<256, 256>>>(Pre,   (long)MM * AA);
    zero_kernel<<<256, 256>>>(Post,  (long)MM * AA);

    // ---- weight-only precomputes (split-K 16, atomic) ----
    transpose_kernel<<<dim3(AA / 32, HH / 32, 1), tb32>>>(w_eproj, Tep, HH, AA, 0, 0);
    transpose_kernel<<<dim3(AA / 32, HH / 32, 1), tb32>>>(w_aproj, Tap, HH, AA, 0, 0);
    tc_gemm<<<dim3(1, DD / 128, 16), 256, TCG_SMEM>>>(WoutR, Tep, Wcomb, nullptr,
                                                      DD, AA, HH, 0, 0, 0, 1.f, 4, 16, 0);
    tc_gemm<<<dim3(1, DD / 128, 16), 256, TCG_SMEM>>>(WdR, Tap, W2, nullptr,
                                                      DD, AA, HH, 0, 0, 0, 1.f, 4, 16, 0);
    rnd_kernel<<<32, 256>>>(Wcomb, WcombR, (long)DD * AA);
    rnd_kernel<<<32, 256>>>(W2,    W2R,    (long)DD * AA);

    // ---- gate, then fused up*silu(gate) -> Hid (rounded) ----
    tc_gemm<<<dim3(HH / 128, MM / 128, 1), 256, TCG_SMEM>>>(xR, WgR, Yg, nullptr,
                                                            MM, HH, DD, 0, 0, 0, 1.f, 0, 1, 0);
    tc_gemm<<<dim3(HH / 128, MM / 128, 1), 256, TCG_SMEM>>>(xR, WuR, Hid, Yg,
                                                            MM, HH, DD, 0, 0, 0, 1.f, 3, 1, 1);

    // ---- pre / adapt_in ----
    tc_gemm<<<dim3(1, MM / 128, 2), 256, TCG_SMEM>>>(xR, WpreR, Pre, nullptr,
                                                     MM, AA, DD, 0, 0, 0, 1.f, 4, 2, 0);
    rnd_kernel<<<256, 256>>>(Pre, PreR, (long)MM * AA);
    ln_kernel<<<MM, 128>>>(Pre, Ain, an_g, an_b);

    // ---- post / adapt_out ----
    tc_gemm<<<dim3(1, MM / 128, 2), 256, TCG_SMEM>>>(Hid, WpostR, Post, nullptr,
                                                     MM, AA, HH, 0, 0, 0, 1.f, 4, 2, 0);
    ln_kernel<<<MM, 128>>>(Post, Aout, an_g, an_b);

    // ---- fused adapt attention: AdaptR = silu(clip(Ain@Aout^T)) @ Ain ----
    transpose_kernel<<<dim3(AA / 32, SS / 32, BB), tb32>>>(Ain, AiT, SS, AA,
                                                           (long)SS * AA, (long)SS * AA);
    tc_adapt<<<dim3(SS / 128, BB, 1), 256, ADP_SMEM>>>(Ain, Aout, AiT, AdaptR);

    // ---- out = Hid @ w_down^T ----
    tc_gemm<<<dim3(DD / 128, MM / 128, 1), 256, TCG_SMEM>>>(Hid, WdR, out, nullptr,
                                                            MM, DD, HH, 0, 0, 0, 1.f, 0, 1, 0);
    // out += 0.1 * AdaptR @ W2R^T
    tc_gemm<<<dim3(DD / 128, MM / 128, 1), 256, TCG_SMEM>>>(AdaptR, W2R, out, nullptr,
                                                            MM, DD, AA, 0, 0, 0, 0.1f, 1, 1, 0);

    // ---- experts ----
    tc_gemm<<<dim3(EE * AA / 128, MM / 128, 1), 256, TCG_SMEM>>>(PreR, WexpR, Eall, nullptr,
                                                                 MM, EE * AA, AA,
                                                                 0, 0, 0, 1.f, 0, 1, 0);
    expert_select_kernel<<<MM, 128>>>(ew, Eall, eln_g, eln_b, Ecomp);
    // out += 0.1 * Ecomp @ WcombR^T
    tc_gemm<<<dim3(DD / 128, MM / 128, 1), 256, TCG_SMEM>>>(Ecomp, WcombR, out, nullptr,
                                                            MM, DD, AA, 0, 0, 0, 0.1f, 1, 1, 0);
}

// round 11
// speedup vs baseline: 1.1352x; 1.1157x over previous
#include <cuda_runtime.h>
#include <cuda_bf16.h>
#include <cstdint>

// Problem dims (fixed)
#define BB 8
#define SS 2048
#define DD 1024
#define HH 2048
#define AA 128
#define EE 8
#define MM (BB*SS)   // 16384 tokens

// tcgen05 is arch-SPECIFIC (sm_103a). Only use it in an arch-specific pass.
#if defined(__CUDA_ARCH_FEAT_SM103_ALL)
#define TCPATH 1
#endif

// -------- scratch (device globals; no allocation allowed) --------
__device__ float g_Hid[MM*HH];         // hidden0 = silu(gate)*up (tf32-rounded)
__device__ float g_Pre[MM*AA];         // exact
__device__ float g_PreR[MM*AA];        // rounded copy for GEMM A
__device__ float g_Ain[MM*AA];         // LN(pre), rounded
__device__ float g_Post[MM*AA];        // exact
__device__ float g_Aout[MM*AA];        // LN(post), rounded
__device__ float g_AiT[BB*AA*SS];      // adapt_in transposed per batch [A,S], rounded
__device__ float g_AdaptR[MM*AA];      // fused adapt output, rounded
__device__ float g_Eall[MM*EE*AA];     // experts' pre-LN activations (exact)
__device__ float g_Ecomp[MM*AA];       // selected+LN'd expert act, rounded
__device__ float g_Wcomb[DD*AA];       // w_out @ w_eproj (exact, atomic)
__device__ float g_WcombR[DD*AA];      // rounded
__device__ float g_W2[DD*AA];          // w_down @ w_aproj (exact, atomic)
__device__ float g_W2R[DD*AA];         // rounded
__device__ float g_Tep[AA*HH];         // w_eproj^T, rounded
__device__ float g_Tap[AA*HH];         // w_aproj^T, rounded
// rounded raw inputs
__device__ float g_xR[MM*DD];
__device__ float g_WgR[HH*DD];
__device__ float g_WuR[HH*DD];
__device__ float g_WdR[DD*HH];
__device__ float g_WoutR[DD*HH];
__device__ float g_WpreR[AA*DD];
__device__ float g_WpostR[AA*HH];
__device__ float g_WexpR[EE*AA*AA];

// ============================================================
// common helpers
// ============================================================
__device__ __forceinline__ float silu_f(float v) {
    return v * __frcp_rn(1.f + __expf(-v));
}

__device__ __forceinline__ uint32_t f2tf32(float f) {
    uint32_t u;
    asm("cvt.rna.tf32.f32 %0, %1;" : "=r"(u) : "f"(f));
    return u;
}
__device__ __forceinline__ float rndf(float f) {
    return __uint_as_float(f2tf32(f));
}

#ifdef TCPATH
// ============================================================
// tcgen05 helpers (sm_103a-specific pass only)
// ============================================================
__device__ __forceinline__ uint32_t smem_u32(const void* p) {
    uint32_t a;
    asm("{ .reg .u64 t; cvta.to.shared.u64 t, %1; cvt.u32.u64 %0, t; }"
        : "=r"(a) : "l"(p));
    return a;
}

__device__ __forceinline__ uint32_t elect1() {
    uint32_t p;
    asm volatile("{\n\t.reg .pred p;\n\telect.sync _|p, 0xFFFFFFFF;\n\t"
                 "selp.b32 %0, 1, 0, p;\n\t}" : "=r"(p));
    return p;
}

#define MBAR_INIT(addr, cnt) \
    asm volatile("mbarrier.init.shared.b64 [%0], %1;" :: "r"(addr), "r"(cnt) : "memory")

__device__ __forceinline__ void mbar_wait(uint32_t mbar, uint32_t parity) {
    uint32_t done;
    asm volatile("{\n\t.reg .pred p;\n\t"
                 "mbarrier.try_wait.parity.acquire.cta.shared::cta.b64 p, [%1], %2;\n\t"
                 "selp.b32 %0, 1, 0, p;\n\t}"
                 : "=r"(done) : "r"(mbar), "r"(parity) : "memory");
    while (!done) {
        asm volatile("{\n\t.reg .pred p;\n\t"
                     "mbarrier.try_wait.parity.acquire.cta.shared::cta.b64 p, [%1], %2, 0x989680;\n\t"
                     "selp.b32 %0, 1, 0, p;\n\t}"
                     : "=r"(done) : "r"(mbar), "r"(parity) : "memory");
    }
}

__device__ __forceinline__ void mma_tf32(uint32_t d, uint64_t da, uint64_t db,
                                         uint32_t idesc, uint32_t en) {
    asm volatile(
        "{\n\t.reg .pred p;\n\tsetp.ne.u32 p, %4, 0;\n\t"
        "tcgen05.mma.cta_group::1.kind::tf32 [%0], %1, %2, %3, {%5, %5, %5, %5}, p;\n\t}"
        :: "r"(d), "l"(da), "l"(db), "r"(idesc), "r"(en), "r"(0u)
        : "memory");
}

#define TC_COMMIT(mbar) \
    asm volatile("tcgen05.commit.cta_group::1.mbarrier::arrive::one.shared::cluster.b64 [%0];" \
                 :: "r"(mbar) : "memory")

#define LDTM_X32(r, addr) \
    asm volatile("tcgen05.ld.sync.aligned.32x32b.x32.b32 " \
        "{%0,%1,%2,%3,%4,%5,%6,%7,%8,%9,%10,%11,%12,%13,%14,%15," \
        "%16,%17,%18,%19,%20,%21,%22,%23,%24,%25,%26,%27,%28,%29,%30,%31}, [%32];" \
        : "=r"((r)[0]),  "=r"((r)[1]),  "=r"((r)[2]),  "=r"((r)[3]), \
          "=r"((r)[4]),  "=r"((r)[5]),  "=r"((r)[6]),  "=r"((r)[7]), \
          "=r"((r)[8]),  "=r"((r)[9]),  "=r"((r)[10]), "=r"((r)[11]), \
          "=r"((r)[12]), "=r"((r)[13]), "=r"((r)[14]), "=r"((r)[15]), \
          "=r"((r)[16]), "=r"((r)[17]), "=r"((r)[18]), "=r"((r)[19]), \
          "=r"((r)[20]), "=r"((r)[21]), "=r"((r)[22]), "=r"((r)[23]), \
          "=r"((r)[24]), "=r"((r)[25]), "=r"((r)[26]), "=r"((r)[27]), \
          "=r"((r)[28]), "=r"((r)[29]), "=r"((r)[30]), "=r"((r)[31]) \
        : "r"(addr))

static __device__ __forceinline__ uint64_t make_desc(uint32_t addr) {
    const uint64_t base = (2ULL << 61) | (1ULL << 46) | (64ULL << 32) | (1ULL << 16);
    return base | ((uint64_t)(addr >> 4) & 0x3FFF);
}

// idesc: dtype=F32(1<<4), atype=btype=TF32(2), N=128 ((N/8)<<17), M=128 ((M/16)<<24)
#define IDESC_TF32 ((1u << 4) | (2u << 7) | (2u << 10) | (16u << 17) | (8u << 24))
#endif  // TCPATH

// ============================================================
// tc_gemm: 128x128 tile (validated path, unchanged)
// C[M,N] (op)= alpha * A[M,K] * B[N,K]^T ; A,B tf32-pre-rounded.
// mode 0: C=alpha*acc  1: C+=alpha*acc  2: silu(clip)  3: silu(G)*acc
// mode 4: atomicAdd(C, alpha*acc) (split-K)
// grid = (N/128, M/128, batch*ksplit)
// ============================================================
#define TCG_SMEM (2048 + 3 * 32768)   // 100352

__global__ __launch_bounds__(256)
void tc_gemm(const float* __restrict__ A, const float* __restrict__ B,
             float* __restrict__ C, const float* __restrict__ G,
             int M, int N, int K, long sA, long sB, long sC,
             float alpha, int mode, int ksplit, int rnd)
{
    extern __shared__ char smem[];
    const int tid  = threadIdx.x;
    const int wid  = tid >> 5;
    const int lane = tid & 31;

    int Kc;
    {
        int bz = blockIdx.z;
        long b = bz / ksplit;
        int ik = bz - (int)b * ksplit;
        Kc = K / ksplit;
        A += b * sA + (long)ik * Kc;
        B += b * sB + (long)ik * Kc;
        C += b * sC;
        if (mode == 3) G += b * sC;
    }
    const int m0 = blockIdx.y * 128, n0 = blockIdx.x * 128;
    const float* Ap = A + (long)m0 * K;
    const float* Bp = B + (long)n0 * K;
    const int nch = Kc >> 5;

#ifdef TCPATH
    uint32_t sbase = smem_u32(smem);
    const uint32_t TM_PTR = sbase;
    const uint32_t MB0 = sbase + 16;
    const uint32_t MB1 = sbase + 24;
    const uint32_t MB2 = sbase + 32;
    uint32_t data0 = (sbase + 1024 + 1023) & ~1023u;

    if (wid == 0) {
        asm volatile("tcgen05.alloc.cta_group::1.sync.aligned.shared::cta.b32 [%0], %1;"
                     :: "r"(TM_PTR), "r"(128u) : "memory");
        asm volatile("tcgen05.relinquish_alloc_permit.cta_group::1.sync.aligned;");
    }
    if (tid == 0) { MBAR_INIT(MB0, 1); MBAR_INIT(MB1, 1); MBAR_INIT(MB2, 1); }
    __syncthreads();
    uint32_t tmem;
    asm volatile("ld.shared.b32 %0, [%1];" : "=r"(tmem) : "r"(TM_PTR));

#define ISSUE_CP(c, b) do {                                                  \
        const int k0_ = (c) << 5;                                            \
        const uint32_t so_ = (uint32_t)(b) * 32768u;                         \
        _Pragma("unroll")                                                    \
        for (int it_ = 0; it_ < 8; it_++) {                                  \
            int idx_ = it_ * 256 + tid;                                      \
            int r_ = idx_ >> 3, q_ = idx_ & 7;                               \
            const float* src_ = (r_ < 128)                                   \
                ? (Ap + (long)r_ * K + k0_ + q_ * 4)                         \
                : (Bp + (long)(r_ - 128) * K + k0_ + q_ * 4);                \
            uint32_t off_ = (uint32_t)(r_ * 128 + q_ * 16);                  \
            uint32_t sw_ = off_ ^ ((off_ >> 3) & 0x70u);                     \
            asm volatile("cp.async.cg.shared.global [%0], [%1], 16;"         \
                :: "r"(data0 + so_ + sw_), "l"(src_) : "memory");            \
        }                                                                    \
        asm volatile("cp.async.commit_group;" ::: "memory");                 \
    } while (0)

    int ph0 = 0, ph1 = 0, ph2 = 0;
    ISSUE_CP(0, 0);
    ISSUE_CP(1, 1);

    for (int i = 0; i < nch; i++) {
        const int ip2 = i + 2;
        if (ip2 < nch) {
            const int b = ip2 % 3;
            if (i >= 1) {
                if (b == 0)      { mbar_wait(MB0, ph0); ph0 ^= 1; }
                else if (b == 1) { mbar_wait(MB1, ph1); ph1 ^= 1; }
                else             { mbar_wait(MB2, ph2); ph2 ^= 1; }
            }
            ISSUE_CP(ip2, b);
        }
        if (ip2 < nch)          asm volatile("cp.async.wait_group 2;" ::: "memory");
        else if (i + 1 < nch)   asm volatile("cp.async.wait_group 1;" ::: "memory");
        else                    asm volatile("cp.async.wait_group 0;" ::: "memory");
        asm volatile("fence.proxy.async.shared::cta;" ::: "memory");
        __syncthreads();
        if (wid == 0 && elect1()) {
            const int bi = i % 3;
            uint64_t da = make_desc(data0 + (uint32_t)bi * 32768u);
            uint64_t db = make_desc(data0 + (uint32_t)bi * 32768u + 16384u);
#pragma unroll
            for (int ks = 0; ks < 4; ks++)
                mma_tf32(tmem, da + ks * 2, db + ks * 2, IDESC_TF32,
                         (i > 0 || ks > 0) ? 1u : 0u);
            if (bi == 0)      TC_COMMIT(MB0);
            else if (bi == 1) TC_COMMIT(MB1);
            else              TC_COMMIT(MB2);
        }
    }
    mbar_wait(MB0, ph0);
    mbar_wait(MB1, ph1);
    mbar_wait(MB2, ph2);
    asm volatile("tcgen05.fence::after_thread_sync;" ::: "memory");
#undef ISSUE_CP

    if (wid < 4) {
        float* Crow = C + (long)(m0 + wid * 32 + lane) * N + n0;
        const float* Grow = (mode == 3)
            ? (G + (long)(m0 + wid * 32 + lane) * N + n0) : nullptr;
#pragma unroll
        for (int cb = 0; cb < 128; cb += 32) {
            uint32_t r[32];
            LDTM_X32(r, tmem + cb);
            asm volatile("tcgen05.wait::ld.sync.aligned;" ::: "memory");
            if (mode == 4) {
#pragma unroll
                for (int j = 0; j < 32; j++)
                    atomicAdd(Crow + cb + j, alpha * __uint_as_float(r[j]));
            } else {
#pragma unroll
                for (int j = 0; j < 32; j += 4) {
                    float4 v;
                    v.x = __uint_as_float(r[j + 0]);
                    v.y = __uint_as_float(r[j + 1]);
                    v.z = __uint_as_float(r[j + 2]);
                    v.w = __uint_as_float(r[j + 3]);
                    if (mode == 0) {
                        v.x *= alpha; v.y *= alpha; v.z *= alpha; v.w *= alpha;
                    } else if (mode == 1) {
                        float4 c = *(const float4*)(Crow + cb + j);
                        v.x = fmaf(alpha, v.x, c.x); v.y = fmaf(alpha, v.y, c.y);
                        v.z = fmaf(alpha, v.z, c.z); v.w = fmaf(alpha, v.w, c.w);
                    } else if (mode == 2) {
                        v.x = silu_f(fminf(5.f, fmaxf(-5.f, v.x)));
                        v.y = silu_f(fminf(5.f, fmaxf(-5.f, v.y)));
                        v.z = silu_f(fminf(5.f, fmaxf(-5.f, v.z)));
                        v.w = silu_f(fminf(5.f, fmaxf(-5.f, v.w)));
                    } else {
                        float4 g = *(const float4*)(Grow + cb + j);
                        v.x *= silu_f(g.x); v.y *= silu_f(g.y);
                        v.z *= silu_f(g.z); v.w *= silu_f(g.w);
                    }
                    if (rnd) {
                        v.x = rndf(v.x); v.y = rndf(v.y);
                        v.z = rndf(v.z); v.w = rndf(v.w);
                    }
                    *(float4*)(Crow + cb + j) = v;
                }
            }
        }
    }
    asm volatile("tcgen05.fence::before_thread_sync;" ::: "memory");
    __syncthreads();
    if (wid == 0) {
        asm volatile("tcgen05.dealloc.cta_group::1.sync.aligned.b32 %0, %1;"
                     :: "r"(tmem), "r"(128u));
    }
#else
    // fallback (compile-only): naive
    for (int idx = tid; idx < 128 * 128; idx += 256) {
        int rr = idx >> 7, cc = idx & 127;
        long ci = (long)(m0 + rr) * N + n0 + cc;
        float acc = 0.f;
        for (int k = 0; k < Kc; k++)
            acc += A[(long)(m0 + rr) * K + k] * B[(long)(n0 + cc) * K + k];
        float v;
        if (mode == 4) { atomicAdd(C + ci, alpha * acc); continue; }
        else if (mode == 0) v = alpha * acc;
        else if (mode == 1) v = fmaf(alpha, acc, C[ci]);
        else if (mode == 2) v = silu_f(fminf(5.f, fmaxf(-5.f, acc)));
        else                v = silu_f(G[ci]) * acc;
        if (rnd) v = rndf(v);
        C[ci] = v;
    }
#endif
}

// ============================================================
// tc_swiglu: fused gate+up GEMM + SwiGLU epilogue.
//   Gacc = x_m @ Wg_n^T   (TMEM cols 0-127)
//   Uacc = x_m @ Wu_n^T   (TMEM cols 128-255)
//   Hid  = rnd(silu(Gacc) * Uacc)
// Stage = A 16KB + Bg 16KB + Bu 16KB = 48KB; 3 stages.
// grid = (HH/128, MM/128), 256 threads. K = DD.
// ============================================================
#define SWI_SMEM (2048 + 3 * 49152)   // 149504

__global__ __launch_bounds__(256)
void tc_swiglu(const float* __restrict__ A, const float* __restrict__ Bg,
               const float* __restrict__ Bu, float* __restrict__ C, int K)
{
    extern __shared__ char smem[];
    const int tid  = threadIdx.x;
    const int wid  = tid >> 5;
    const int lane = tid & 31;
    const int m0 = blockIdx.y * 128, n0 = blockIdx.x * 128;
    const int N = HH;
    const float* Ap  = A  + (long)m0 * K;
    const float* Bgp = Bg + (long)n0 * K;
    const float* Bup = Bu + (long)n0 * K;
    const int nch = K >> 5;   // 32

#ifdef TCPATH
    uint32_t sbase = smem_u32(smem);
    const uint32_t TM_PTR = sbase;
    const uint32_t MB0 = sbase + 16;
    const uint32_t MB1 = sbase + 24;
    const uint32_t MB2 = sbase + 32;
    uint32_t data0 = (sbase + 1024 + 1023) & ~1023u;

    if (wid == 0) {
        asm volatile("tcgen05.alloc.cta_group::1.sync.aligned.shared::cta.b32 [%0], %1;"
                     :: "r"(TM_PTR), "r"(256u) : "memory");
        asm volatile("tcgen05.relinquish_alloc_permit.cta_group::1.sync.aligned;");
    }
    if (tid == 0) { MBAR_INIT(MB0, 1); MBAR_INIT(MB1, 1); MBAR_INIT(MB2, 1); }
    __syncthreads();
    uint32_t tmem;
    asm volatile("ld.shared.b32 %0, [%1];" : "=r"(tmem) : "r"(TM_PTR));

#define SWI_CP(c, b) do {                                                    \
        const int k0_ = (c) << 5;                                            \
        const uint32_t so_ = (uint32_t)(b) * 49152u;                         \
        _Pragma("unroll")                                                    \
        for (int it_ = 0; it_ < 12; it_++) {                                 \
            int idx_ = it_ * 256 + tid;                                      \
            int r_ = idx_ >> 3, q_ = idx_ & 7;                               \
            int rr_ = r_ & 127;                                              \
            const float* src_;                                               \
            if (r_ < 128)       src_ = Ap  + (long)rr_ * K + k0_ + q_ * 4;   \
            else if (r_ < 256)  src_ = Bgp + (long)rr_ * K + k0_ + q_ * 4;   \
            else                src_ = Bup + (long)rr_ * K + k0_ + q_ * 4;   \
            uint32_t off_ = (uint32_t)(rr_ * 128 + q_ * 16);                 \
            uint32_t sw_ = off_ ^ ((off_ >> 3) & 0x70u);                     \
            asm volatile("cp.async.cg.shared.global [%0], [%1], 16;"         \
                :: "r"(data0 + so_ + (uint32_t)(r_ >> 7) * 16384u + sw_),    \
                   "l"(src_) : "memory");                                    \
        }                                                                    \
        asm volatile("cp.async.commit_group;" ::: "memory");                 \
    } while (0)

    int ph0 = 0, ph1 = 0, ph2 = 0;
    SWI_CP(0, 0);
    SWI_CP(1, 1);

    for (int i = 0; i < nch; i++) {
        const int ip2 = i + 2;
        if (ip2 < nch) {
            const int b = ip2 % 3;
            if (i >= 1) {
                if (b == 0)      { mbar_wait(MB0, ph0); ph0 ^= 1; }
                else if (b == 1) { mbar_wait(MB1, ph1); ph1 ^= 1; }
                else             { mbar_wait(MB2, ph2); ph2 ^= 1; }
            }
            SWI_CP(ip2, b);
        }
        if (ip2 < nch)          asm volatile("cp.async.wait_group 2;" ::: "memory");
        else if (i + 1 < nch)   asm volatile("cp.async.wait_group 1;" ::: "memory");
        else                    asm volatile("cp.async.wait_group 0;" ::: "memory");
        asm volatile("fence.proxy.async.shared::cta;" ::: "memory");
        __syncthreads();
        if (wid == 0 && elect1()) {
            const int bi = i % 3;
            uint64_t da  = make_desc(data0 + (uint32_t)bi * 49152u);
            uint64_t dbg = make_desc(data0 + (uint32_t)bi * 49152u + 16384u);
            uint64_t dbu = make_desc(data0 + (uint32_t)bi * 49152u + 32768u);
            uint32_t en0 = (i > 0) ? 1u : 0u;
#pragma unroll
            for (int ks = 0; ks < 4; ks++) {
                uint32_t en = (en0 || ks > 0) ? 1u : 0u;
                mma_tf32(tmem,       da + ks * 2, dbg + ks * 2, IDESC_TF32, en);
                mma_tf32(tmem + 128, da + ks * 2, dbu + ks * 2, IDESC_TF32, en);
            }
            if (bi == 0)      TC_COMMIT(MB0);
            else if (bi == 1) TC_COMMIT(MB1);
            else              TC_COMMIT(MB2);
        }
    }
    mbar_wait(MB0, ph0);
    mbar_wait(MB1, ph1);
    mbar_wait(MB2, ph2);
    asm volatile("tcgen05.fence::after_thread_sync;" ::: "memory");
#undef SWI_CP

    // epilogue: warp w -> subpartition (w&3) rows, col-half (w>>2).
    {
        const int sp   = wid & 3;
        const int half = wid >> 2;
        const int row  = m0 + sp * 32 + lane;
        float* Crow = C + (long)row * N + n0;
#pragma unroll
        for (int c = 0; c < 2; c++) {
            const int cb = half * 64 + c * 32;
            uint32_t gr[32], ur[32];
            LDTM_X32(gr, tmem + cb);
            LDTM_X32(ur, tmem + 128 + cb);
            asm volatile("tcgen05.wait::ld.sync.aligned;" ::: "memory");
#pragma unroll
            for (int j = 0; j < 32; j += 4) {
                float4 v;
                v.x = rndf(silu_f(__uint_as_float(gr[j + 0])) * __uint_as_float(ur[j + 0]));
                v.y = rndf(silu_f(__uint_as_float(gr[j + 1])) * __uint_as_float(ur[j + 1]));
                v.z = rndf(silu_f(__uint_as_float(gr[j + 2])) * __uint_as_float(ur[j + 2]));
                v.w = rndf(silu_f(__uint_as_float(gr[j + 3])) * __uint_as_float(ur[j + 3]));
                *(float4*)(Crow + cb + j) = v;
            }
        }
    }
    asm volatile("tcgen05.fence::before_thread_sync;" ::: "memory");
    __syncthreads();
    if (wid == 0) {
        asm volatile("tcgen05.dealloc.cta_group::1.sync.aligned.b32 %0, %1;"
                     :: "r"(tmem), "r"(256u));
    }
#else
    // fallback (compile-only): naive
    for (int idx = tid; idx < 128 * 128; idx += 256) {
        int rr = idx >> 7, cc = idx & 127;
        float g = 0.f, u = 0.f;
        for (int k = 0; k < K; k++) {
            float a = A[(long)(m0 + rr) * K + k];
            g += a * Bg[(long)(n0 + cc) * K + k];
            u += a * Bu[(long)(n0 + cc) * K + k];
        }
        C[(long)(m0 + rr) * N + n0 + cc] = rndf(silu_f(g) * u);
    }
#endif
}

// ============================================================
// tc_adapt: fused adapt attention (flash-style) — unchanged from R8.
// ============================================================
#define ADP_SMEM (2048 + 3 * 65536)   // 198656

__global__ __launch_bounds__(256)
void tc_adapt(const float* __restrict__ Ain,   // [B][S][A] tf32
              const float* __restrict__ Aout,  // [B][S][A] tf32
              const float* __restrict__ AiT,   // [B][A][S] tf32
              float* __restrict__ AdaptR)      // [B][S][A] out, tf32
{
    extern __shared__ char smem[];
    const int tid  = threadIdx.x;
    const int wid  = tid >> 5;
    const int lane = tid & 31;
    const int b    = blockIdx.y;
    const int m0   = blockIdx.x * 128;

    const float* AinB  = Ain  + (long)b * SS * AA;
    const float* AoutB = Aout + (long)b * SS * AA;
    const float* AiTB  = AiT  + (long)b * AA * SS;
    float*       AdB   = AdaptR + (long)b * SS * AA;

#ifdef TCPATH
    uint32_t sbase = smem_u32(smem);
    const uint32_t TM_PTR = sbase;
    const uint32_t MB0 = sbase + 16;   // MMA1 done
    const uint32_t MB1 = sbase + 24;   // MMA2 done
    uint32_t data0 = (sbase + 1024 + 1023) & ~1023u;
    const uint32_t AinS = data0;
    const uint32_t Bsh  = data0 + 65536u;
    const uint32_t Psh  = data0 + 131072u;

    if (wid == 0) {
        asm volatile("tcgen05.alloc.cta_group::1.sync.aligned.shared::cta.b32 [%0], %1;"
                     :: "r"(TM_PTR), "r"(256u) : "memory");
        asm volatile("tcgen05.relinquish_alloc_permit.cta_group::1.sync.aligned;");
    }
    if (tid == 0) { MBAR_INIT(MB0, 1); MBAR_INIT(MB1, 1); }
    __syncthreads();
    uint32_t tmem;
    asm volatile("ld.shared.b32 %0, [%1];" : "=r"(tmem) : "r"(TM_PTR));

#define ADP_LOAD256(base, gptr, ldg) do {                                    \
        _Pragma("unroll")                                                    \
        for (int it_ = 0; it_ < 16; it_++) {                                 \
            int idx_ = it_ * 256 + tid;                                      \
            int c_ = idx_ >> 10, r_ = (idx_ >> 3) & 127, q_ = idx_ & 7;      \
            const float* src_ = (gptr) + (long)r_ * (ldg) + c_ * 32 + q_ * 4;\
            uint32_t off_ = (uint32_t)(r_ * 128 + q_ * 16);                  \
            uint32_t sw_ = off_ ^ ((off_ >> 3) & 0x70u);                     \
            asm volatile("cp.async.cg.shared.global [%0], [%1], 16;"         \
                :: "r"((base) + (uint32_t)c_ * 16384u + sw_), "l"(src_)      \
                : "memory");                                                 \
        }                                                                    \
        asm volatile("cp.async.commit_group;" ::: "memory");                 \
    } while (0)

    ADP_LOAD256(AinS, AinB + (long)m0 * AA, AA);
    ADP_LOAD256(Bsh,  AoutB, AA);
    asm volatile("cp.async.wait_group 0;" ::: "memory");
    asm volatile("fence.proxy.async.shared::cta;" ::: "memory");
    __syncthreads();

    int ph0 = 0, ph1 = 0;
    for (int kt = 0; kt < 16; kt++) {
        if (wid == 0 && elect1()) {
#pragma unroll
            for (int c = 0; c < 4; c++) {
                uint64_t da = make_desc(AinS + (uint32_t)c * 16384u);
                uint64_t db = make_desc(Bsh  + (uint32_t)c * 16384u);
#pragma unroll
                for (int ks = 0; ks < 4; ks++)
                    mma_tf32(tmem, da + ks * 2, db + ks * 2, IDESC_TF32,
                             (c > 0 || ks > 0) ? 1u : 0u);
            }
            TC_COMMIT(MB0);
        }
        mbar_wait(MB0, ph0); ph0 ^= 1;
        asm volatile("tcgen05.fence::after_thread_sync;" ::: "memory");

        if (wid < 4) {
            const int r = wid * 32 + lane;
#pragma unroll
            for (int cb = 0; cb < 4; cb++) {
                uint32_t rg[32];
                LDTM_X32(rg, tmem + cb * 32);
                asm volatile("tcgen05.wait::ld.sync.aligned;" ::: "memory");
#pragma unroll
                for (int j = 0; j < 32; j += 4) {
                    float4 v;
                    v.x = rndf(silu_f(fminf(5.f, fmaxf(-5.f, __uint_as_float(rg[j + 0])))));
                    v.y = rndf(silu_f(fminf(5.f, fmaxf(-5.f, __uint_as_float(rg[j + 1])))));
                    v.z = rndf(silu_f(fminf(5.f, fmaxf(-5.f, __uint_as_float(rg[j + 2])))));
                    v.w = rndf(silu_f(fminf(5.f, fmaxf(-5.f, __uint_as_float(rg[j + 3])))));
                    uint32_t off = (uint32_t)(r * 128 + j * 4);
                    uint32_t sw = off ^ ((off >> 3) & 0x70u);
                    uint32_t addr = Psh + (uint32_t)cb * 16384u + sw;
                    asm volatile("st.shared.v4.b32 [%0], {%1, %2, %3, %4};"
                        :: "r"(addr), "r"(__float_as_uint(v.x)), "r"(__float_as_uint(v.y)),
                           "r"(__float_as_uint(v.z)), "r"(__float_as_uint(v.w)) : "memory");
                }
            }
        } else {
            const int tid2 = tid - 128;
#pragma unroll
            for (int it = 0; it < 32; it++) {
                int idx = it * 128 + tid2;
                int c = idx >> 10, r = (idx >> 3) & 127, q = idx & 7;
                const float* src = AiTB + (long)r * SS + kt * 128 + c * 32 + q * 4;
                uint32_t off = (uint32_t)(r * 128 + q * 16);
                uint32_t sw = off ^ ((off >> 3) & 0x70u);
                asm volatile("cp.async.cg.shared.global [%0], [%1], 16;"
                    :: "r"(Bsh + (uint32_t)c * 16384u + sw), "l"(src) : "memory");
            }
            asm volatile("cp.async.commit_group;" ::: "memory");
        }
        asm volatile("cp.async.wait_group 0;" ::: "memory");
        asm volatile("fence.proxy.async.shared::cta;" ::: "memory");
        __syncthreads();

        if (wid == 0 && elect1()) {
#pragma unroll
            for (int c = 0; c < 4; c++) {
                uint64_t da = make_desc(Psh + (uint32_t)c * 16384u);
                uint64_t db = make_desc(Bsh + (uint32_t)c * 16384u);
#pragma unroll
                for (int ks = 0; ks < 4; ks++)
                    mma_tf32(tmem + 128, da + ks * 2, db + ks * 2, IDESC_TF32,
                             (kt > 0 || c > 0 || ks > 0) ? 1u : 0u);
            }
            TC_COMMIT(MB1);
        }
        mbar_wait(MB1, ph1); ph1 ^= 1;

        if (kt < 15) {
            ADP_LOAD256(Bsh, AoutB + (long)(kt + 1) * 128 * AA, AA);
            asm volatile("cp.async.wait_group 0;" ::: "memory");
            asm volatile("fence.proxy.async.shared::cta;" ::: "memory");
            __syncthreads();
        }
    }
#undef ADP_LOAD256

    asm volatile("tcgen05.fence::after_thread_sync;" ::: "memory");
    if (wid < 4) {
        const int r = wid * 32 + lane;
        float* Crow = AdB + (long)(m0 + r) * AA;
#pragma unroll
        for (int cb = 0; cb < 128; cb += 32) {
            uint32_t rg[32];
            LDTM_X32(rg, tmem + 128 + cb);
            asm volatile("tcgen05.wait::ld.sync.aligned;" ::: "memory");
#pragma unroll
            for (int j = 0; j < 32; j += 4) {
                float4 v;
                v.x = rndf(__uint_as_float(rg[j + 0]));
                v.y = rndf(__uint_as_float(rg[j + 1]));
                v.z = rndf(__uint_as_float(rg[j + 2]));
                v.w = rndf(__uint_as_float(rg[j + 3]));
                *(float4*)(Crow + cb + j) = v;
            }
        }
    }
    asm volatile("tcgen05.fence::before_thread_sync;" ::: "memory");
    __syncthreads();
    if (wid == 0) {
        asm volatile("tcgen05.dealloc.cta_group::1.sync.aligned.b32 %0, %1;"
                     :: "r"(tmem), "r"(256u));
    }
#else
    for (int r = tid; r < 128; r += 256) {
        float acc[AA];
        for (int a = 0; a < AA; a++) acc[a] = 0.f;
        for (int s = 0; s < SS; s++) {
            float p = 0.f;
            for (int a = 0; a < AA; a++)
                p += AinB[(long)(m0 + r) * AA + a] * AoutB[(long)s * AA + a];
            p = silu_f(fminf(5.f, fmaxf(-5.f, p)));
            for (int a = 0; a < AA; a++)
                acc[a] += p * AinB[(long)s * AA + a];
        }
        for (int a = 0; a < AA; a++)
            AdB[(long)(m0 + r) * AA + a] = rndf(acc[a]);
    }
#endif
}

// ============================================================
// Small helpers
// ============================================================
__global__ void zero_kernel(float* p, long n)
{
    long i = (long)blockIdx.x * blockDim.x + threadIdx.x;
    long stride = (long)gridDim.x * blockDim.x;
    for (; i < n; i += stride) p[i] = 0.f;
}

__global__ void rnd_kernel(const float* __restrict__ in, float* __restrict__ out, long n)
{
    long i = (long)blockIdx.x * blockDim.x + threadIdx.x;
    long stride = (long)gridDim.x * blockDim.x;
    for (long j = i * 4; j < n; j += stride * 4) {
        float4 v = *(const float4*)(in + j);
        v.x = rndf(v.x); v.y = rndf(v.y); v.z = rndf(v.z); v.w = rndf(v.w);
        *(float4*)(out + j) = v;
    }
}

__global__ void transpose_kernel(const float* __restrict__ in, float* __restrict__ out,
                                 int R, int C, long sIn, long sOut)
{
    __shared__ float tile[32][33];
    in  += (long)blockIdx.z * sIn;
    out += (long)blockIdx.z * sOut;
    int r0 = blockIdx.y * 32, c0 = blockIdx.x * 32;
    int tx = threadIdx.x, ty = threadIdx.y;
#pragma unroll
    for (int i = 0; i < 32; i += 8)
        tile[ty + i][tx] = in[(long)(r0 + ty + i) * C + c0 + tx];
    __syncthreads();
#pragma unroll
    for (int i = 0; i < 32; i += 8)
        out[(long)(c0 + ty + i) * R + r0 + tx] = rndf(tile[tx][ty + i]);
}

__device__ __forceinline__ float2 block_mean_var_128(float v)
{
    float s = v, s2 = v * v;
#pragma unroll
    for (int o = 16; o > 0; o >>= 1) {
        s  += __shfl_xor_sync(0xffffffffu, s,  o);
        s2 += __shfl_xor_sync(0xffffffffu, s2, o);
    }
    __shared__ float sh[8];
    int w = threadIdx.x >> 5;
    if ((threadIdx.x & 31) == 0) { sh[w] = s; sh[4 + w] = s2; }
    __syncthreads();
    s  = sh[0] + sh[1] + sh[2] + sh[3];
    s2 = sh[4] + sh[5] + sh[6] + sh[7];
    __syncthreads();
    float m = s * (1.f / 128.f);
    return make_float2(m, s2 * (1.f / 128.f) - m * m);
}

__global__ void ln_kernel(const float* __restrict__ in, float* __restrict__ out,
                          const float* __restrict__ g, const float* __restrict__ b)
{
    long row = blockIdx.x;
    int  t   = threadIdx.x;
    float v  = in[row * 128 + t];
    float2 mv = block_mean_var_128(v);
    float inv = rsqrtf(mv.y + 1e-5f);
    out[row * 128 + t] = rndf((v - mv.x) * inv * g[t] + b[t]);
}

__global__ void expert_select_kernel(const float* __restrict__ ew,
                                     const float* __restrict__ Eall,
                                     const float* __restrict__ eln_g,
                                     const float* __restrict__ eln_b,
                                     float* __restrict__ Ecomp)
{
    long m = blockIdx.x;
    int  t = threadIdx.x;
    __shared__ int sidx;
    if (t == 0) {
        int idx = -1;
        const float* w = ew + m * EE;
#pragma unroll
        for (int i = 0; i < EE; i++) if (w[i] > 0.f) idx = i;
        sidx = idx;
    }
    __syncthreads();
    int idx = sidx;
    float o = 0.f;
    if (idx >= 0) {
        float v = Eall[m * (EE * AA) + idx * AA + t];
        float2 mv = block_mean_var_128(v);
        float inv = rsqrtf(mv.y + 1e-5f);
        o = rndf((v - mv.x) * inv * eln_g[idx * AA + t] + eln_b[idx * AA + t]);
    }
    Ecomp[m * AA + t] = o;
}

// ============================================================
// Launch
// ============================================================
extern "C" void kernel_launch(void* const* d_in, const int* in_sizes, int n_in,
                              void* d_out, int out_size)
{
    const float* x       = (const float*)d_in[0];
    const float* ew      = (const float*)d_in[1];
    const float* w_up    = (const float*)d_in[2];
    const float* w_gate  = (const float*)d_in[3];
    const float* w_down  = (const float*)d_in[4];
    const float* w_pre   = (const float*)d_in[5];
    const float* w_post  = (const float*)d_in[6];
    const float* an_g    = (const float*)d_in[7];
    const float* an_b    = (const float*)d_in[8];
    const float* w_aproj = (const float*)d_in[9];
    const float* w_exp   = (const float*)d_in[10];
    const float* eln_g   = (const float*)d_in[11];
    const float* eln_b   = (const float*)d_in[12];
    const float* w_eproj = (const float*)d_in[13];
    const float* w_out   = (const float*)d_in[14];
    float* out = (float*)d_out;

    float *Hid, *Pre, *PreR, *Ain, *Post, *Aout, *AiT, *AdaptR,
          *Eall, *Ecomp, *Wcomb, *WcombR, *W2, *W2R, *Tep, *Tap,
          *xR, *WgR, *WuR, *WdR, *WoutR, *WpreR, *WpostR, *WexpR;
    cudaGetSymbolAddress((void**)&Hid,    g_Hid);
    cudaGetSymbolAddress((void**)&Pre,    g_Pre);
    cudaGetSymbolAddress((void**)&PreR,   g_PreR);
    cudaGetSymbolAddress((void**)&Ain,    g_Ain);
    cudaGetSymbolAddress((void**)&Post,   g_Post);
    cudaGetSymbolAddress((void**)&Aout,   g_Aout);
    cudaGetSymbolAddress((void**)&AiT,    g_AiT);
    cudaGetSymbolAddress((void**)&AdaptR, g_AdaptR);
    cudaGetSymbolAddress((void**)&Eall,   g_Eall);
    cudaGetSymbolAddress((void**)&Ecomp,  g_Ecomp);
    cudaGetSymbolAddress((void**)&Wcomb,  g_Wcomb);
    cudaGetSymbolAddress((void**)&WcombR, g_WcombR);
    cudaGetSymbolAddress((void**)&W2,     g_W2);
    cudaGetSymbolAddress((void**)&W2R,    g_W2R);
    cudaGetSymbolAddress((void**)&Tep,    g_Tep);
    cudaGetSymbolAddress((void**)&Tap,    g_Tap);
    cudaGetSymbolAddress((void**)&xR,     g_xR);
    cudaGetSymbolAddress((void**)&WgR,    g_WgR);
    cudaGetSymbolAddress((void**)&WuR,    g_WuR);
    cudaGetSymbolAddress((void**)&WdR,    g_WdR);
    cudaGetSymbolAddress((void**)&WoutR,  g_WoutR);
    cudaGetSymbolAddress((void**)&WpreR,  g_WpreR);
    cudaGetSymbolAddress((void**)&WpostR, g_WpostR);
    cudaGetSymbolAddress((void**)&WexpR,  g_WexpR);

    cudaFuncSetAttribute(tc_gemm,   cudaFuncAttributeMaxDynamicSharedMemorySize, TCG_SMEM);
    cudaFuncSetAttribute(tc_swiglu, cudaFuncAttributeMaxDynamicSharedMemorySize, SWI_SMEM);
    cudaFuncSetAttribute(tc_adapt,  cudaFuncAttributeMaxDynamicSharedMemorySize, ADP_SMEM);

    dim3 tb32(32, 8);

    // ---- round raw inputs to tf32 once (saturating grids) ----
    rnd_kernel<<<2048, 256>>>(x,      xR,     (long)MM * DD);
    rnd_kernel<<<512,  256>>>(w_gate, WgR,    (long)HH * DD);
    rnd_kernel<<<512,  256>>>(w_up,   WuR,    (long)HH * DD);
    rnd_kernel<<<512,  256>>>(w_down, WdR,    (long)DD * HH);
    rnd_kernel<<<512,  256>>>(w_out,  WoutR,  (long)DD * HH);
    rnd_kernel<<<128,  256>>>(w_pre,  WpreR,  (long)AA * DD);
    rnd_kernel<<<128,  256>>>(w_post, WpostR, (long)AA * HH);
    rnd_kernel<<<128,  256>>>(w_exp,  WexpR,  (long)EE * AA * AA);

    // ---- zero split-K atomic targets (only Wcomb/W2 now) ----
    zero_kernel<<<64, 256>>>(Wcomb, (long)DD * AA);
    zero_kernel<<<64, 256>>>(W2,    (long)DD * AA);

    // ---- weight-only precomputes (split-K 16, atomic) ----
    transpose_kernel<<<dim3(AA / 32, HH / 32, 1), tb32>>>(w_eproj, Tep, HH, AA, 0, 0);
    transpose_kernel<<<dim3(AA / 32, HH / 32, 1), tb32>>>(w_aproj, Tap, HH, AA, 0, 0);
    tc_gemm<<<dim3(1, DD / 128, 16), 256, TCG_SMEM>>>(WoutR, Tep, Wcomb, nullptr,
                                                      DD, AA, HH, 0, 0, 0, 1.f, 4, 16, 0);
    tc_gemm<<<dim3(1, DD / 128, 16), 256, TCG_SMEM>>>(WdR, Tap, W2, nullptr,
                                                      DD, AA, HH, 0, 0, 0, 1.f, 4, 16, 0);
    rnd_kernel<<<128, 256>>>(Wcomb, WcombR, (long)DD * AA);
    rnd_kernel<<<128, 256>>>(W2,    W2R,    (long)DD * AA);

    // ---- fused gate+up+SwiGLU -> Hid (no Yg round-trip) ----
    tc_swiglu<<<dim3(HH / 128, MM / 128, 1), 256, SWI_SMEM>>>(xR, WgR, WuR, Hid, DD);

    // ---- pre / adapt_in (ksplit=1, no atomics) ----
    tc_gemm<<<dim3(1, MM / 128, 1), 256, TCG_SMEM>>>(xR, WpreR, Pre, nullptr,
                                                     MM, AA, DD, 0, 0, 0, 1.f, 0, 1, 0);
    rnd_kernel<<<512, 256>>>(Pre, PreR, (long)MM * AA);
    ln_kernel<<<MM, 128>>>(Pre, Ain, an_g, an_b);

    // ---- post / adapt_out (ksplit=1) ----
    tc_gemm<<<dim3(1, MM / 128, 1), 256, TCG_SMEM>>>(Hid, WpostR, Post, nullptr,
                                                     MM, AA, HH, 0, 0, 0, 1.f, 0, 1, 0);
    ln_kernel<<<MM, 128>>>(Post, Aout, an_g, an_b);

    // ---- fused adapt attention: AdaptR = silu(clip(Ain@Aout^T)) @ Ain ----
    transpose_kernel<<<dim3(AA / 32, SS / 32, BB), tb32>>>(Ain, AiT, SS, AA,
                                                           (long)SS * AA, (long)SS * AA);
    tc_adapt<<<dim3(SS / 128, BB, 1), 256, ADP_SMEM>>>(Ain, Aout, AiT, AdaptR);

    // ---- out = Hid @ w_down^T ----
    tc_gemm<<<dim3(DD / 128, MM / 128, 1), 256, TCG_SMEM>>>(Hid, WdR, out, nullptr,
                                                            MM, DD, HH, 0, 0, 0, 1.f, 0, 1, 0);
    // out += 0.1 * AdaptR @ W2R^T
    tc_gemm<<<dim3(DD / 128, MM / 128, 1), 256, TCG_SMEM>>>(AdaptR, W2R, out, nullptr,
                                                            MM, DD, AA, 0, 0, 0, 0.1f, 1, 1, 0);

    // ---- experts ----
    tc_gemm<<<dim3(EE * AA / 128, MM / 128, 1), 256, TCG_SMEM>>>(PreR, WexpR, Eall, nullptr,
                                                                 MM, EE * AA, AA,
                                                                 0, 0, 0, 1.f, 0, 1, 0);
    expert_select_kernel<<<MM, 128>>>(ew, Eall, eln_g, eln_b, Ecomp);
    // out += 0.1 * Ecomp @ WcombR^T
    tc_gemm<<<dim3(DD / 128, MM / 128, 1), 256, TCG_SMEM>>>(Ecomp, WcombR, out, nullptr,
                                                            MM, DD, AA, 0, 0, 0, 0.1f, 1, 1, 0);
}

// round 13
// speedup vs baseline: 1.3416x; 1.1819x over previous
#include <cuda_runtime.h>
#include <cuda_bf16.h>
#include <cstdint>

// Problem dims (fixed)
#define BB 8
#define SS 2048
#define DD 1024
#define HH 2048
#define AA 128
#define EE 8
#define MM (BB*SS)   // 16384 tokens

// tcgen05 is arch-SPECIFIC (sm_103a). Only use it in an arch-specific pass.
#if defined(__CUDA_ARCH_FEAT_SM103_ALL)
#define TCPATH 1
#endif

// -------- scratch (device globals; no allocation allowed) --------
__device__ float g_Hid[MM*HH];         // hidden0 = silu(gate)*up (tf32-rounded)
__device__ float g_Pre[MM*AA];         // rounded (feeds ln + Eall GEMM)
__device__ float g_Ain[MM*AA];         // LN(pre), rounded
__device__ float g_Post[MM*AA];        // exact
__device__ float g_Aout[MM*AA];        // LN(post), rounded
__device__ float g_AiT[BB*AA*SS];      // adapt_in transposed per batch [A,S], rounded
__device__ float g_AdaptS[MM*AA];      // fused adapt output, PRE-SCALED by 0.1, rounded
__device__ float g_Eall[MM*EE*AA];     // experts' pre-LN activations (exact)
__device__ float g_EcompS[MM*AA];      // selected+LN'd expert act, PRE-SCALED 0.1, rounded
__device__ float g_Wcomb[DD*AA];       // w_out @ w_eproj (exact, atomic)
__device__ float g_WcombR[DD*AA];      // rounded
__device__ float g_W2[DD*AA];          // w_down @ w_aproj (exact, atomic)
__device__ float g_W2R[DD*AA];         // rounded
__device__ float g_Tep[AA*HH];         // w_eproj^T, rounded
__device__ float g_Tap[AA*HH];         // w_aproj^T, rounded
// rounded raw inputs
__device__ float g_xR[MM*DD];
__device__ float g_WgR[HH*DD];
__device__ float g_WuR[HH*DD];
__device__ float g_WdR[DD*HH];
__device__ float g_WoutR[DD*HH];
__device__ float g_WpreR[AA*DD];
__device__ float g_WpostR[AA*HH];
__device__ float g_WexpR[EE*AA*AA];

// ============================================================
// common helpers
// ============================================================
__device__ __forceinline__ float silu_f(float v) {
    return v * __frcp_rn(1.f + __expf(-v));
}

__device__ __forceinline__ uint32_t f2tf32(float f) {
    uint32_t u;
    asm("cvt.rna.tf32.f32 %0, %1;" : "=r"(u) : "f"(f));
    return u;
}
__device__ __forceinline__ float rndf(float f) {
    return __uint_as_float(f2tf32(f));
}

#ifdef TCPATH
// ============================================================
// tcgen05 helpers (sm_103a-specific pass only)
// ============================================================
__device__ __forceinline__ uint32_t smem_u32(const void* p) {
    uint32_t a;
    asm("{ .reg .u64 t; cvta.to.shared.u64 t, %1; cvt.u32.u64 %0, t; }"
        : "=r"(a) : "l"(p));
    return a;
}

__device__ __forceinline__ uint32_t elect1() {
    uint32_t p;
    asm volatile("{\n\t.reg .pred p;\n\telect.sync _|p, 0xFFFFFFFF;\n\t"
                 "selp.b32 %0, 1, 0, p;\n\t}" : "=r"(p));
    return p;
}

#define MBAR_INIT(addr, cnt) \
    asm volatile("mbarrier.init.shared.b64 [%0], %1;" :: "r"(addr), "r"(cnt) : "memory")

__device__ __forceinline__ void mbar_wait(uint32_t mbar, uint32_t parity) {
    uint32_t done;
    asm volatile("{\n\t.reg .pred p;\n\t"
                 "mbarrier.try_wait.parity.acquire.cta.shared::cta.b64 p, [%1], %2;\n\t"
                 "selp.b32 %0, 1, 0, p;\n\t}"
                 : "=r"(done) : "r"(mbar), "r"(parity) : "memory");
    while (!done) {
        asm volatile("{\n\t.reg .pred p;\n\t"
                     "mbarrier.try_wait.parity.acquire.cta.shared::cta.b64 p, [%1], %2, 0x989680;\n\t"
                     "selp.b32 %0, 1, 0, p;\n\t}"
                     : "=r"(done) : "r"(mbar), "r"(parity) : "memory");
    }
}

__device__ __forceinline__ void mma_tf32(uint32_t d, uint64_t da, uint64_t db,
                                         uint32_t idesc, uint32_t en) {
    asm volatile(
        "{\n\t.reg .pred p;\n\tsetp.ne.u32 p, %4, 0;\n\t"
        "tcgen05.mma.cta_group::1.kind::tf32 [%0], %1, %2, %3, {%5, %5, %5, %5}, p;\n\t}"
        :: "r"(d), "l"(da), "l"(db), "r"(idesc), "r"(en), "r"(0u)
        : "memory");
}

#define TC_COMMIT(mbar) \
    asm volatile("tcgen05.commit.cta_group::1.mbarrier::arrive::one.shared::cluster.b64 [%0];" \
                 :: "r"(mbar) : "memory")

#define LDTM_X32(r, addr) \
    asm volatile("tcgen05.ld.sync.aligned.32x32b.x32.b32 " \
        "{%0,%1,%2,%3,%4,%5,%6,%7,%8,%9,%10,%11,%12,%13,%14,%15," \
        "%16,%17,%18,%19,%20,%21,%22,%23,%24,%25,%26,%27,%28,%29,%30,%31}, [%32];" \
        : "=r"((r)[0]),  "=r"((r)[1]),  "=r"((r)[2]),  "=r"((r)[3]), \
          "=r"((r)[4]),  "=r"((r)[5]),  "=r"((r)[6]),  "=r"((r)[7]), \
          "=r"((r)[8]),  "=r"((r)[9]),  "=r"((r)[10]), "=r"((r)[11]), \
          "=r"((r)[12]), "=r"((r)[13]), "=r"((r)[14]), "=r"((r)[15]), \
          "=r"((r)[16]), "=r"((r)[17]), "=r"((r)[18]), "=r"((r)[19]), \
          "=r"((r)[20]), "=r"((r)[21]), "=r"((r)[22]), "=r"((r)[23]), \
          "=r"((r)[24]), "=r"((r)[25]), "=r"((r)[26]), "=r"((r)[27]), \
          "=r"((r)[28]), "=r"((r)[29]), "=r"((r)[30]), "=r"((r)[31]) \
        : "r"(addr))

static __device__ __forceinline__ uint64_t make_desc(uint32_t addr) {
    const uint64_t base = (2ULL << 61) | (1ULL << 46) | (64ULL << 32) | (1ULL << 16);
    return base | ((uint64_t)(addr >> 4) & 0x3FFF);
}

// idesc: dtype=F32(1<<4), atype=btype=TF32(2), N=128 ((N/8)<<17), M=128 ((M/16)<<24)
#define IDESC_TF32 ((1u << 4) | (2u << 7) | (2u << 10) | (16u << 17) | (8u << 24))
#endif  // TCPATH

// ============================================================
// tc_gemm: 128x128 tile (validated path, unchanged)
// ============================================================
#define TCG_SMEM (2048 + 3 * 32768)   // 100352

__global__ __launch_bounds__(256)
void tc_gemm(const float* __restrict__ A, const float* __restrict__ B,
             float* __restrict__ C, const float* __restrict__ G,
             int M, int N, int K, long sA, long sB, long sC,
             float alpha, int mode, int ksplit, int rnd)
{
    extern __shared__ char smem[];
    const int tid  = threadIdx.x;
    const int wid  = tid >> 5;
    const int lane = tid & 31;

    int Kc;
    {
        int bz = blockIdx.z;
        long b = bz / ksplit;
        int ik = bz - (int)b * ksplit;
        Kc = K / ksplit;
        A += b * sA + (long)ik * Kc;
        B += b * sB + (long)ik * Kc;
        C += b * sC;
        if (mode == 3) G += b * sC;
    }
    const int m0 = blockIdx.y * 128, n0 = blockIdx.x * 128;
    const float* Ap = A + (long)m0 * K;
    const float* Bp = B + (long)n0 * K;
    const int nch = Kc >> 5;

#ifdef TCPATH
    uint32_t sbase = smem_u32(smem);
    const uint32_t TM_PTR = sbase;
    const uint32_t MB0 = sbase + 16;
    const uint32_t MB1 = sbase + 24;
    const uint32_t MB2 = sbase + 32;
    uint32_t data0 = (sbase + 1024 + 1023) & ~1023u;

    if (wid == 0) {
        asm volatile("tcgen05.alloc.cta_group::1.sync.aligned.shared::cta.b32 [%0], %1;"
                     :: "r"(TM_PTR), "r"(128u) : "memory");
        asm volatile("tcgen05.relinquish_alloc_permit.cta_group::1.sync.aligned;");
    }
    if (tid == 0) { MBAR_INIT(MB0, 1); MBAR_INIT(MB1, 1); MBAR_INIT(MB2, 1); }
    __syncthreads();
    uint32_t tmem;
    asm volatile("ld.shared.b32 %0, [%1];" : "=r"(tmem) : "r"(TM_PTR));

#define ISSUE_CP(c, b) do {                                                  \
        const int k0_ = (c) << 5;                                            \
        const uint32_t so_ = (uint32_t)(b) * 32768u;                         \
        _Pragma("unroll")                                                    \
        for (int it_ = 0; it_ < 8; it_++) {                                  \
            int idx_ = it_ * 256 + tid;                                      \
            int r_ = idx_ >> 3, q_ = idx_ & 7;                               \
            const float* src_ = (r_ < 128)                                   \
                ? (Ap + (long)r_ * K + k0_ + q_ * 4)                         \
                : (Bp + (long)(r_ - 128) * K + k0_ + q_ * 4);                \
            uint32_t off_ = (uint32_t)(r_ * 128 + q_ * 16);                  \
            uint32_t sw_ = off_ ^ ((off_ >> 3) & 0x70u);                     \
            asm volatile("cp.async.cg.shared.global [%0], [%1], 16;"         \
                :: "r"(data0 + so_ + sw_), "l"(src_) : "memory");            \
        }                                                                    \
        asm volatile("cp.async.commit_group;" ::: "memory");                 \
    } while (0)

    int ph0 = 0, ph1 = 0, ph2 = 0;
    ISSUE_CP(0, 0);
    ISSUE_CP(1, 1);

    for (int i = 0; i < nch; i++) {
        const int ip2 = i + 2;
        if (ip2 < nch) {
            const int b = ip2 % 3;
            if (i >= 1) {
                if (b == 0)      { mbar_wait(MB0, ph0); ph0 ^= 1; }
                else if (b == 1) { mbar_wait(MB1, ph1); ph1 ^= 1; }
                else             { mbar_wait(MB2, ph2); ph2 ^= 1; }
            }
            ISSUE_CP(ip2, b);
        }
        if (ip2 < nch)          asm volatile("cp.async.wait_group 2;" ::: "memory");
        else if (i + 1 < nch)   asm volatile("cp.async.wait_group 1;" ::: "memory");
        else                    asm volatile("cp.async.wait_group 0;" ::: "memory");
        asm volatile("fence.proxy.async.shared::cta;" ::: "memory");
        __syncthreads();
        if (wid == 0 && elect1()) {
            const int bi = i % 3;
            uint64_t da = make_desc(data0 + (uint32_t)bi * 32768u);
            uint64_t db = make_desc(data0 + (uint32_t)bi * 32768u + 16384u);
#pragma unroll
            for (int ks = 0; ks < 4; ks++)
                mma_tf32(tmem, da + ks * 2, db + ks * 2, IDESC_TF32,
                         (i > 0 || ks > 0) ? 1u : 0u);
            if (bi == 0)      TC_COMMIT(MB0);
            else if (bi == 1) TC_COMMIT(MB1);
            else              TC_COMMIT(MB2);
        }
    }
    mbar_wait(MB0, ph0);
    mbar_wait(MB1, ph1);
    mbar_wait(MB2, ph2);
    asm volatile("tcgen05.fence::after_thread_sync;" ::: "memory");
#undef ISSUE_CP

    if (wid < 4) {
        float* Crow = C + (long)(m0 + wid * 32 + lane) * N + n0;
        const float* Grow = (mode == 3)
            ? (G + (long)(m0 + wid * 32 + lane) * N + n0) : nullptr;
#pragma unroll
        for (int cb = 0; cb < 128; cb += 32) {
            uint32_t r[32];
            LDTM_X32(r, tmem + cb);
            asm volatile("tcgen05.wait::ld.sync.aligned;" ::: "memory");
            if (mode == 4) {
#pragma unroll
                for (int j = 0; j < 32; j++)
                    atomicAdd(Crow + cb + j, alpha * __uint_as_float(r[j]));
            } else {
#pragma unroll
                for (int j = 0; j < 32; j += 4) {
                    float4 v;
                    v.x = __uint_as_float(r[j + 0]);
                    v.y = __uint_as_float(r[j + 1]);
                    v.z = __uint_as_float(r[j + 2]);
                    v.w = __uint_as_float(r[j + 3]);
                    if (mode == 0) {
                        v.x *= alpha; v.y *= alpha; v.z *= alpha; v.w *= alpha;
                    } else if (mode == 1) {
                        float4 c = *(const float4*)(Crow + cb + j);
                        v.x = fmaf(alpha, v.x, c.x); v.y = fmaf(alpha, v.y, c.y);
                        v.z = fmaf(alpha, v.z, c.z); v.w = fmaf(alpha, v.w, c.w);
                    } else if (mode == 2) {
                        v.x = silu_f(fminf(5.f, fmaxf(-5.f, v.x)));
                        v.y = silu_f(fminf(5.f, fmaxf(-5.f, v.y)));
                        v.z = silu_f(fminf(5.f, fmaxf(-5.f, v.z)));
                        v.w = silu_f(fminf(5.f, fmaxf(-5.f, v.w)));
                    } else {
                        float4 g = *(const float4*)(Grow + cb + j);
                        v.x *= silu_f(g.x); v.y *= silu_f(g.y);
                        v.z *= silu_f(g.z); v.w *= silu_f(g.w);
                    }
                    if (rnd) {
                        v.x = rndf(v.x); v.y = rndf(v.y);
                        v.z = rndf(v.z); v.w = rndf(v.w);
                    }
                    *(float4*)(Crow + cb + j) = v;
                }
            }
        }
    }
    asm volatile("tcgen05.fence::before_thread_sync;" ::: "memory");
    __syncthreads();
    if (wid == 0) {
        asm volatile("tcgen05.dealloc.cta_group::1.sync.aligned.b32 %0, %1;"
                     :: "r"(tmem), "r"(128u));
    }
#else
    for (int idx = tid; idx < 128 * 128; idx += 256) {
        int rr = idx >> 7, cc = idx & 127;
        long ci = (long)(m0 + rr) * N + n0 + cc;
        float acc = 0.f;
        for (int k = 0; k < Kc; k++)
            acc += A[(long)(m0 + rr) * K + k] * B[(long)(n0 + cc) * K + k];
        float v;
        if (mode == 4) { atomicAdd(C + ci, alpha * acc); continue; }
        else if (mode == 0) v = alpha * acc;
        else if (mode == 1) v = fmaf(alpha, acc, C[ci]);
        else if (mode == 2) v = silu_f(fminf(5.f, fmaxf(-5.f, acc)));
        else                v = silu_f(G[ci]) * acc;
        if (rnd) v = rndf(v);
        C[ci] = v;
    }
#endif
}

// ============================================================
// tc_out: single-pass output GEMM over a virtual-K concat:
//   out = Hid@WdR^T + AdaptS@W2R^T + EcompS@WcombR^T
// (AdaptS/EcompS pre-scaled by 0.1). 72 chunks: 0-63 Hid/WdR (K=HH),
// 64-67 AdaptS/W2R (K=AA), 68-71 EcompS/WcombR (K=AA).
// grid = (DD/128, MM/128). mode-0 plain store.
// ============================================================
__global__ __launch_bounds__(256)
void tc_out(const float* __restrict__ Hid, const float* __restrict__ WdR,
            const float* __restrict__ AdS, const float* __restrict__ W2R,
            const float* __restrict__ EcS, const float* __restrict__ WcR,
            float* __restrict__ C)
{
    extern __shared__ char smem[];
    const int tid  = threadIdx.x;
    const int wid  = tid >> 5;
    const int lane = tid & 31;
    const int m0 = blockIdx.y * 128, n0 = blockIdx.x * 128;
    const int N = DD;
    const int nch = 72;

#ifdef TCPATH
    uint32_t sbase = smem_u32(smem);
    const uint32_t TM_PTR = sbase;
    const uint32_t MB0 = sbase + 16;
    const uint32_t MB1 = sbase + 24;
    const uint32_t MB2 = sbase + 32;
    uint32_t data0 = (sbase + 1024 + 1023) & ~1023u;

    if (wid == 0) {
        asm volatile("tcgen05.alloc.cta_group::1.sync.aligned.shared::cta.b32 [%0], %1;"
                     :: "r"(TM_PTR), "r"(128u) : "memory");
        asm volatile("tcgen05.relinquish_alloc_permit.cta_group::1.sync.aligned;");
    }
    if (tid == 0) { MBAR_INIT(MB0, 1); MBAR_INIT(MB1, 1); MBAR_INIT(MB2, 1); }
    __syncthreads();
    uint32_t tmem;
    asm volatile("ld.shared.b32 %0, [%1];" : "=r"(tmem) : "r"(TM_PTR));

    // per-chunk source select
#define OUT_CP(c, b) do {                                                    \
        const float* aB_; const float* bB_; int ldA_, k0_;                   \
        if ((c) < 64)      { aB_ = Hid + (long)m0 * HH; bB_ = WdR + (long)n0 * HH; \
                             ldA_ = HH; k0_ = (c) << 5; }                    \
        else if ((c) < 68) { aB_ = AdS + (long)m0 * AA; bB_ = W2R + (long)n0 * AA; \
                             ldA_ = AA; k0_ = ((c) - 64) << 5; }             \
        else               { aB_ = EcS + (long)m0 * AA; bB_ = WcR + (long)n0 * AA; \
                             ldA_ = AA; k0_ = ((c) - 68) << 5; }             \
        const uint32_t so_ = (uint32_t)(b) * 32768u;                         \
        _Pragma("unroll")                                                    \
        for (int it_ = 0; it_ < 8; it_++) {                                  \
            int idx_ = it_ * 256 + tid;                                      \
            int r_ = idx_ >> 3, q_ = idx_ & 7;                               \
            const float* src_ = (r_ < 128)                                   \
                ? (aB_ + (long)r_ * ldA_ + k0_ + q_ * 4)                     \
                : (bB_ + (long)(r_ - 128) * ldA_ + k0_ + q_ * 4);            \
            uint32_t off_ = (uint32_t)(r_ * 128 + q_ * 16);                  \
            uint32_t sw_ = off_ ^ ((off_ >> 3) & 0x70u);                     \
            asm volatile("cp.async.cg.shared.global [%0], [%1], 16;"         \
                :: "r"(data0 + so_ + sw_), "l"(src_) : "memory");            \
        }                                                                    \
        asm volatile("cp.async.commit_group;" ::: "memory");                 \
    } while (0)

    int ph0 = 0, ph1 = 0, ph2 = 0;
    OUT_CP(0, 0);
    OUT_CP(1, 1);

    for (int i = 0; i < nch; i++) {
        const int ip2 = i + 2;
        if (ip2 < nch) {
            const int b = ip2 % 3;
            if (i >= 1) {
                if (b == 0)      { mbar_wait(MB0, ph0); ph0 ^= 1; }
                else if (b == 1) { mbar_wait(MB1, ph1); ph1 ^= 1; }
                else             { mbar_wait(MB2, ph2); ph2 ^= 1; }
            }
            OUT_CP(ip2, b);
        }
        if (ip2 < nch)          asm volatile("cp.async.wait_group 2;" ::: "memory");
        else if (i + 1 < nch)   asm volatile("cp.async.wait_group 1;" ::: "memory");
        else                    asm volatile("cp.async.wait_group 0;" ::: "memory");
        asm volatile("fence.proxy.async.shared::cta;" ::: "memory");
        __syncthreads();
        if (wid == 0 && elect1()) {
            const int bi = i % 3;
            uint64_t da = make_desc(data0 + (uint32_t)bi * 32768u);
            uint64_t db = make_desc(data0 + (uint32_t)bi * 32768u + 16384u);
#pragma unroll
            for (int ks = 0; ks < 4; ks++)
                mma_tf32(tmem, da + ks * 2, db + ks * 2, IDESC_TF32,
                         (i > 0 || ks > 0) ? 1u : 0u);
            if (bi == 0)      TC_COMMIT(MB0);
            else if (bi == 1) TC_COMMIT(MB1);
            else              TC_COMMIT(MB2);
        }
    }
    mbar_wait(MB0, ph0);
    mbar_wait(MB1, ph1);
    mbar_wait(MB2, ph2);
    asm volatile("tcgen05.fence::after_thread_sync;" ::: "memory");
#undef OUT_CP

    if (wid < 4) {
        float* Crow = C + (long)(m0 + wid * 32 + lane) * N + n0;
#pragma unroll
        for (int cb = 0; cb < 128; cb += 32) {
            uint32_t r[32];
            LDTM_X32(r, tmem + cb);
            asm volatile("tcgen05.wait::ld.sync.aligned;" ::: "memory");
#pragma unroll
            for (int j = 0; j < 32; j += 4) {
                float4 v;
                v.x = __uint_as_float(r[j + 0]);
                v.y = __uint_as_float(r[j + 1]);
                v.z = __uint_as_float(r[j + 2]);
                v.w = __uint_as_float(r[j + 3]);
                *(float4*)(Crow + cb + j) = v;
            }
        }
    }
    asm volatile("tcgen05.fence::before_thread_sync;" ::: "memory");
    __syncthreads();
    if (wid == 0) {
        asm volatile("tcgen05.dealloc.cta_group::1.sync.aligned.b32 %0, %1;"
                     :: "r"(tmem), "r"(128u));
    }
#else
    for (int idx = tid; idx < 128 * 128; idx += 256) {
        int rr = idx >> 7, cc = idx & 127;
        float acc = 0.f;
        for (int k = 0; k < HH; k++)
            acc += Hid[(long)(m0 + rr) * HH + k] * WdR[(long)(n0 + cc) * HH + k];
        for (int k = 0; k < AA; k++)
            acc += AdS[(long)(m0 + rr) * AA + k] * W2R[(long)(n0 + cc) * AA + k];
        for (int k = 0; k < AA; k++)
            acc += EcS[(long)(m0 + rr) * AA + k] * WcR[(long)(n0 + cc) * AA + k];
        C[(long)(m0 + rr) * DD + n0 + cc] = acc;
    }
#endif
}

// ============================================================
// tc_swiglu: fused gate+up GEMM + SwiGLU epilogue (unchanged from R11)
// ============================================================
#define SWI_SMEM (2048 + 3 * 49152)   // 149504

__global__ __launch_bounds__(256)
void tc_swiglu(const float* __restrict__ A, const float* __restrict__ Bg,
               const float* __restrict__ Bu, float* __restrict__ C, int K)
{
    extern __shared__ char smem[];
    const int tid  = threadIdx.x;
    const int wid  = tid >> 5;
    const int lane = tid & 31;
    const int m0 = blockIdx.y * 128, n0 = blockIdx.x * 128;
    const int N = HH;
    const float* Ap  = A  + (long)m0 * K;
    const float* Bgp = Bg + (long)n0 * K;
    const float* Bup = Bu + (long)n0 * K;
    const int nch = K >> 5;   // 32

#ifdef TCPATH
    uint32_t sbase = smem_u32(smem);
    const uint32_t TM_PTR = sbase;
    const uint32_t MB0 = sbase + 16;
    const uint32_t MB1 = sbase + 24;
    const uint32_t MB2 = sbase + 32;
    uint32_t data0 = (sbase + 1024 + 1023) & ~1023u;

    if (wid == 0) {
        asm volatile("tcgen05.alloc.cta_group::1.sync.aligned.shared::cta.b32 [%0], %1;"
                     :: "r"(TM_PTR), "r"(256u) : "memory");
        asm volatile("tcgen05.relinquish_alloc_permit.cta_group::1.sync.aligned;");
    }
    if (tid == 0) { MBAR_INIT(MB0, 1); MBAR_INIT(MB1, 1); MBAR_INIT(MB2, 1); }
    __syncthreads();
    uint32_t tmem;
    asm volatile("ld.shared.b32 %0, [%1];" : "=r"(tmem) : "r"(TM_PTR));

#define SWI_CP(c, b) do {                                                    \
        const int k0_ = (c) << 5;                                            \
        const uint32_t so_ = (uint32_t)(b) * 49152u;                         \
        _Pragma("unroll")                                                    \
        for (int it_ = 0; it_ < 12; it_++) {                                 \
            int idx_ = it_ * 256 + tid;                                      \
            int r_ = idx_ >> 3, q_ = idx_ & 7;                               \
            int rr_ = r_ & 127;                                              \
            const float* src_;                                               \
            if (r_ < 128)       src_ = Ap  + (long)rr_ * K + k0_ + q_ * 4;   \
            else if (r_ < 256)  src_ = Bgp + (long)rr_ * K + k0_ + q_ * 4;   \
            else                src_ = Bup + (long)rr_ * K + k0_ + q_ * 4;   \
            uint32_t off_ = (uint32_t)(rr_ * 128 + q_ * 16);                 \
            uint32_t sw_ = off_ ^ ((off_ >> 3) & 0x70u);                     \
            asm volatile("cp.async.cg.shared.global [%0], [%1], 16;"         \
                :: "r"(data0 + so_ + (uint32_t)(r_ >> 7) * 16384u + sw_),    \
                   "l"(src_) : "memory");                                    \
        }                                                                    \
        asm volatile("cp.async.commit_group;" ::: "memory");                 \
    } while (0)

    int ph0 = 0, ph1 = 0, ph2 = 0;
    SWI_CP(0, 0);
    SWI_CP(1, 1);

    for (int i = 0; i < nch; i++) {
        const int ip2 = i + 2;
        if (ip2 < nch) {
            const int b = ip2 % 3;
            if (i >= 1) {
                if (b == 0)      { mbar_wait(MB0, ph0); ph0 ^= 1; }
                else if (b == 1) { mbar_wait(MB1, ph1); ph1 ^= 1; }
                else             { mbar_wait(MB2, ph2); ph2 ^= 1; }
            }
            SWI_CP(ip2, b);
        }
        if (ip2 < nch)          asm volatile("cp.async.wait_group 2;" ::: "memory");
        else if (i + 1 < nch)   asm volatile("cp.async.wait_group 1;" ::: "memory");
        else                    asm volatile("cp.async.wait_group 0;" ::: "memory");
        asm volatile("fence.proxy.async.shared::cta;" ::: "memory");
        __syncthreads();
        if (wid == 0 && elect1()) {
            const int bi = i % 3;
            uint64_t da  = make_desc(data0 + (uint32_t)bi * 49152u);
            uint64_t dbg = make_desc(data0 + (uint32_t)bi * 49152u + 16384u);
            uint64_t dbu = make_desc(data0 + (uint32_t)bi * 49152u + 32768u);
            uint32_t en0 = (i > 0) ? 1u : 0u;
#pragma unroll
            for (int ks = 0; ks < 4; ks++) {
                uint32_t en = (en0 || ks > 0) ? 1u : 0u;
                mma_tf32(tmem,       da + ks * 2, dbg + ks * 2, IDESC_TF32, en);
                mma_tf32(tmem + 128, da + ks * 2, dbu + ks * 2, IDESC_TF32, en);
            }
            if (bi == 0)      TC_COMMIT(MB0);
            else if (bi == 1) TC_COMMIT(MB1);
            else              TC_COMMIT(MB2);
        }
    }
    mbar_wait(MB0, ph0);
    mbar_wait(MB1, ph1);
    mbar_wait(MB2, ph2);
    asm volatile("tcgen05.fence::after_thread_sync;" ::: "memory");
#undef SWI_CP

    {
        const int sp   = wid & 3;
        const int half = wid >> 2;
        const int row  = m0 + sp * 32 + lane;
        float* Crow = C + (long)row * N + n0;
#pragma unroll
        for (int c = 0; c < 2; c++) {
            const int cb = half * 64 + c * 32;
            uint32_t gr[32], ur[32];
            LDTM_X32(gr, tmem + cb);
            LDTM_X32(ur, tmem + 128 + cb);
            asm volatile("tcgen05.wait::ld.sync.aligned;" ::: "memory");
#pragma unroll
            for (int j = 0; j < 32; j += 4) {
                float4 v;
                v.x = rndf(silu_f(__uint_as_float(gr[j + 0])) * __uint_as_float(ur[j + 0]));
                v.y = rndf(silu_f(__uint_as_float(gr[j + 1])) * __uint_as_float(ur[j + 1]));
                v.z = rndf(silu_f(__uint_as_float(gr[j + 2])) * __uint_as_float(ur[j + 2]));
                v.w = rndf(silu_f(__uint_as_float(gr[j + 3])) * __uint_as_float(ur[j + 3]));
                *(float4*)(Crow + cb + j) = v;
            }
        }
    }
    asm volatile("tcgen05.fence::before_thread_sync;" ::: "memory");
    __syncthreads();
    if (wid == 0) {
        asm volatile("tcgen05.dealloc.cta_group::1.sync.aligned.b32 %0, %1;"
                     :: "r"(tmem), "r"(256u));
    }
#else
    for (int idx = tid; idx < 128 * 128; idx += 256) {
        int rr = idx >> 7, cc = idx & 127;
        float g = 0.f, u = 0.f;
        for (int k = 0; k < K; k++) {
            float a = A[(long)(m0 + rr) * K + k];
            g += a * Bg[(long)(n0 + cc) * K + k];
            u += a * Bu[(long)(n0 + cc) * K + k];
        }
        C[(long)(m0 + rr) * N + n0 + cc] = rndf(silu_f(g) * u);
    }
#endif
}

// ============================================================
// tc_adapt: fused adapt attention; final output PRE-SCALED by 0.1.
// ============================================================
#define ADP_SMEM (2048 + 3 * 65536)   // 198656

__global__ __launch_bounds__(256)
void tc_adapt(const float* __restrict__ Ain,   // [B][S][A] tf32
              const float* __restrict__ Aout,  // [B][S][A] tf32
              const float* __restrict__ AiT,   // [B][A][S] tf32
              float* __restrict__ AdaptS)      // [B][S][A] out = rnd(0.1*acc)
{
    extern __shared__ char smem[];
    const int tid  = threadIdx.x;
    const int wid  = tid >> 5;
    const int lane = tid & 31;
    const int b    = blockIdx.y;
    const int m0   = blockIdx.x * 128;

    const float* AinB  = Ain  + (long)b * SS * AA;
    const float* AoutB = Aout + (long)b * SS * AA;
    const float* AiTB  = AiT  + (long)b * AA * SS;
    float*       AdB   = AdaptS + (long)b * SS * AA;

#ifdef TCPATH
    uint32_t sbase = smem_u32(smem);
    const uint32_t TM_PTR = sbase;
    const uint32_t MB0 = sbase + 16;
    const uint32_t MB1 = sbase + 24;
    uint32_t data0 = (sbase + 1024 + 1023) & ~1023u;
    const uint32_t AinS = data0;
    const uint32_t Bsh  = data0 + 65536u;
    const uint32_t Psh  = data0 + 131072u;

    if (wid == 0) {
        asm volatile("tcgen05.alloc.cta_group::1.sync.aligned.shared::cta.b32 [%0], %1;"
                     :: "r"(TM_PTR), "r"(256u) : "memory");
        asm volatile("tcgen05.relinquish_alloc_permit.cta_group::1.sync.aligned;");
    }
    if (tid == 0) { MBAR_INIT(MB0, 1); MBAR_INIT(MB1, 1); }
    __syncthreads();
    uint32_t tmem;
    asm volatile("ld.shared.b32 %0, [%1];" : "=r"(tmem) : "r"(TM_PTR));

#define ADP_LOAD256(base, gptr, ldg) do {                                    \
        _Pragma("unroll")                                                    \
        for (int it_ = 0; it_ < 16; it_++) {                                 \
            int idx_ = it_ * 256 + tid;                                      \
            int c_ = idx_ >> 10, r_ = (idx_ >> 3) & 127, q_ = idx_ & 7;      \
            const float* src_ = (gptr) + (long)r_ * (ldg) + c_ * 32 + q_ * 4;\
            uint32_t off_ = (uint32_t)(r_ * 128 + q_ * 16);                  \
            uint32_t sw_ = off_ ^ ((off_ >> 3) & 0x70u);                     \
            asm volatile("cp.async.cg.shared.global [%0], [%1], 16;"         \
                :: "r"((base) + (uint32_t)c_ * 16384u + sw_), "l"(src_)      \
                : "memory");                                                 \
        }                                                                    \
        asm volatile("cp.async.commit_group;" ::: "memory");                 \
    } while (0)

    ADP_LOAD256(AinS, AinB + (long)m0 * AA, AA);
    ADP_LOAD256(Bsh,  AoutB, AA);
    asm volatile("cp.async.wait_group 0;" ::: "memory");
    asm volatile("fence.proxy.async.shared::cta;" ::: "memory");
    __syncthreads();

    int ph0 = 0, ph1 = 0;
    for (int kt = 0; kt < 16; kt++) {
        if (wid == 0 && elect1()) {
#pragma unroll
            for (int c = 0; c < 4; c++) {
                uint64_t da = make_desc(AinS + (uint32_t)c * 16384u);
                uint64_t db = make_desc(Bsh  + (uint32_t)c * 16384u);
#pragma unroll
                for (int ks = 0; ks < 4; ks++)
                    mma_tf32(tmem, da + ks * 2, db + ks * 2, IDESC_TF32,
                             (c > 0 || ks > 0) ? 1u : 0u);
            }
            TC_COMMIT(MB0);
        }
        mbar_wait(MB0, ph0); ph0 ^= 1;
        asm volatile("tcgen05.fence::after_thread_sync;" ::: "memory");

        if (wid < 4) {
            const int r = wid * 32 + lane;
#pragma unroll
            for (int cb = 0; cb < 4; cb++) {
                uint32_t rg[32];
                LDTM_X32(rg, tmem + cb * 32);
                asm volatile("tcgen05.wait::ld.sync.aligned;" ::: "memory");
#pragma unroll
                for (int j = 0; j < 32; j += 4) {
                    float4 v;
                    v.x = rndf(silu_f(fminf(5.f, fmaxf(-5.f, __uint_as_float(rg[j + 0])))));
                    v.y = rndf(silu_f(fminf(5.f, fmaxf(-5.f, __uint_as_float(rg[j + 1])))));
                    v.z = rndf(silu_f(fminf(5.f, fmaxf(-5.f, __uint_as_float(rg[j + 2])))));
                    v.w = rndf(silu_f(fminf(5.f, fmaxf(-5.f, __uint_as_float(rg[j + 3])))));
                    uint32_t off = (uint32_t)(r * 128 + j * 4);
                    uint32_t sw = off ^ ((off >> 3) & 0x70u);
                    uint32_t addr = Psh + (uint32_t)cb * 16384u + sw;
                    asm volatile("st.shared.v4.b32 [%0], {%1, %2, %3, %4};"
                        :: "r"(addr), "r"(__float_as_uint(v.x)), "r"(__float_as_uint(v.y)),
                           "r"(__float_as_uint(v.z)), "r"(__float_as_uint(v.w)) : "memory");
                }
            }
        } else {
            const int tid2 = tid - 128;
#pragma unroll
            for (int it = 0; it < 32; it++) {
                int idx = it * 128 + tid2;
                int c = idx >> 10, r = (idx >> 3) & 127, q = idx & 7;
                const float* src = AiTB + (long)r * SS + kt * 128 + c * 32 + q * 4;
                uint32_t off = (uint32_t)(r * 128 + q * 16);
                uint32_t sw = off ^ ((off >> 3) & 0x70u);
                asm volatile("cp.async.cg.shared.global [%0], [%1], 16;"
                    :: "r"(Bsh + (uint32_t)c * 16384u + sw), "l"(src) : "memory");
            }
            asm volatile("cp.async.commit_group;" ::: "memory");
        }
        asm volatile("cp.async.wait_group 0;" ::: "memory");
        asm volatile("fence.proxy.async.shared::cta;" ::: "memory");
        __syncthreads();

        if (wid == 0 && elect1()) {
#pragma unroll
            for (int c = 0; c < 4; c++) {
                uint64_t da = make_desc(Psh + (uint32_t)c * 16384u);
                uint64_t db = make_desc(Bsh + (uint32_t)c * 16384u);
#pragma unroll
                for (int ks = 0; ks < 4; ks++)
                    mma_tf32(tmem + 128, da + ks * 2, db + ks * 2, IDESC_TF32,
                             (kt > 0 || c > 0 || ks > 0) ? 1u : 0u);
            }
            TC_COMMIT(MB1);
        }
        mbar_wait(MB1, ph1); ph1 ^= 1;

        if (kt < 15) {
            ADP_LOAD256(Bsh, AoutB + (long)(kt + 1) * 128 * AA, AA);
            asm volatile("cp.async.wait_group 0;" ::: "memory");
            asm volatile("fence.proxy.async.shared::cta;" ::: "memory");
            __syncthreads();
        }
    }
#undef ADP_LOAD256

    asm volatile("tcgen05.fence::after_thread_sync;" ::: "memory");
    if (wid < 4) {
        const int r = wid * 32 + lane;
        float* Crow = AdB + (long)(m0 + r) * AA;
#pragma unroll
        for (int cb = 0; cb < 128; cb += 32) {
            uint32_t rg[32];
            LDTM_X32(rg, tmem + 128 + cb);
            asm volatile("tcgen05.wait::ld.sync.aligned;" ::: "memory");
#pragma unroll
            for (int j = 0; j < 32; j += 4) {
                float4 v;
                v.x = rndf(0.1f * __uint_as_float(rg[j + 0]));
                v.y = rndf(0.1f * __uint_as_float(rg[j + 1]));
                v.z = rndf(0.1f * __uint_as_float(rg[j + 2]));
                v.w = rndf(0.1f * __uint_as_float(rg[j + 3]));
                *(float4*)(Crow + cb + j) = v;
            }
        }
    }
    asm volatile("tcgen05.fence::before_thread_sync;" ::: "memory");
    __syncthreads();
    if (wid == 0) {
        asm volatile("tcgen05.dealloc.cta_group::1.sync.aligned.b32 %0, %1;"
                     :: "r"(tmem), "r"(256u));
    }
#else
    for (int r = tid; r < 128; r += 256) {
        float acc[AA];
        for (int a = 0; a < AA; a++) acc[a] = 0.f;
        for (int s = 0; s < SS; s++) {
            float p = 0.f;
            for (int a = 0; a < AA; a++)
                p += AinB[(long)(m0 + r) * AA + a] * AoutB[(long)s * AA + a];
            p = silu_f(fminf(5.f, fmaxf(-5.f, p)));
            for (int a = 0; a < AA; a++)
                acc[a] += p * AinB[(long)s * AA + a];
        }
        for (int a = 0; a < AA; a++)
            AdB[(long)(m0 + r) * AA + a] = rndf(0.1f * acc[a]);
    }
#endif
}

// ============================================================
// Small helpers
// ============================================================
__global__ void zero_kernel(float* p, long n)
{
    long i = (long)blockIdx.x * blockDim.x + threadIdx.x;
    long stride = (long)gridDim.x * blockDim.x;
    for (; i < n; i += stride) p[i] = 0.f;
}

// one float4 per thread, exact grid
__global__ void rnd_kernel(const float* __restrict__ in, float* __restrict__ out, long n)
{
    long j = ((long)blockIdx.x * blockDim.x + threadIdx.x) * 4;
    if (j < n) {
        float4 v = *(const float4*)(in + j);
        v.x = rndf(v.x); v.y = rndf(v.y); v.z = rndf(v.z); v.w = rndf(v.w);
        *(float4*)(out + j) = v;
    }
}
#define RND_GRID(n) ((int)(((n) / 4 + 255) / 256))

__global__ void transpose_kernel(const float* __restrict__ in, float* __restrict__ out,
                                 int R, int C, long sIn, long sOut)
{
    __shared__ float tile[32][33];
    in  += (long)blockIdx.z * sIn;
    out += (long)blockIdx.z * sOut;
    int r0 = blockIdx.y * 32, c0 = blockIdx.x * 32;
    int tx = threadIdx.x, ty = threadIdx.y;
#pragma unroll
    for (int i = 0; i < 32; i += 8)
        tile[ty + i][tx] = in[(long)(r0 + ty + i) * C + c0 + tx];
    __syncthreads();
#pragma unroll
    for (int i = 0; i < 32; i += 8)
        out[(long)(c0 + ty + i) * R + r0 + tx] = rndf(tile[tx][ty + i]);
}

__device__ __forceinline__ float2 block_mean_var_128(float v)
{
    float s = v, s2 = v * v;
#pragma unroll
    for (int o = 16; o > 0; o >>= 1) {
        s  += __shfl_xor_sync(0xffffffffu, s,  o);
        s2 += __shfl_xor_sync(0xffffffffu, s2, o);
    }
    __shared__ float sh[8];
    int w = threadIdx.x >> 5;
    if ((threadIdx.x & 31) == 0) { sh[w] = s; sh[4 + w] = s2; }
    __syncthreads();
    s  = sh[0] + sh[1] + sh[2] + sh[3];
    s2 = sh[4] + sh[5] + sh[6] + sh[7];
    __syncthreads();
    float m = s * (1.f / 128.f);
    return make_float2(m, s2 * (1.f / 128.f) - m * m);
}

__global__ void ln_kernel(const float* __restrict__ in, float* __restrict__ out,
                          const float* __restrict__ g, const float* __restrict__ b)
{
    long row = blockIdx.x;
    int  t   = threadIdx.x;
    float v  = in[row * 128 + t];
    float2 mv = block_mean_var_128(v);
    float inv = rsqrtf(mv.y + 1e-5f);
    out[row * 128 + t] = rndf((v - mv.x) * inv * g[t] + b[t]);
}

// Ecomp = rnd(0.1 * LN(selected expert)) (pre-scaled)
__global__ void expert_select_kernel(const float* __restrict__ ew,
                                     const float* __restrict__ Eall,
                                     const float* __restrict__ eln_g,
                                     const float* __restrict__ eln_b,
                                     float* __restrict__ EcompS)
{
    long m = blockIdx.x;
    int  t = threadIdx.x;
    __shared__ int sidx;
    if (t == 0) {
        int idx = -1;
        const float* w = ew + m * EE;
#pragma unroll
        for (int i = 0; i < EE; i++) if (w[i] > 0.f) idx = i;
        sidx = idx;
    }
    __syncthreads();
    int idx = sidx;
    float o = 0.f;
    if (idx >= 0) {
        float v = Eall[m * (EE * AA) + idx * AA + t];
        float2 mv = block_mean_var_128(v);
        float inv = rsqrtf(mv.y + 1e-5f);
        o = rndf(0.1f * ((v - mv.x) * inv * eln_g[idx * AA + t] + eln_b[idx * AA + t]));
    }
    EcompS[m * AA + t] = o;
}

// ============================================================
// Launch
// ============================================================
extern "C" void kernel_launch(void* const* d_in, const int* in_sizes, int n_in,
                              void* d_out, int out_size)
{
    const float* x       = (const float*)d_in[0];
    const float* ew      = (const float*)d_in[1];
    const float* w_up    = (const float*)d_in[2];
    const float* w_gate  = (const float*)d_in[3];
    const float* w_down  = (const float*)d_in[4];
    const float* w_pre   = (const float*)d_in[5];
    const float* w_post  = (const float*)d_in[6];
    const float* an_g    = (const float*)d_in[7];
    const float* an_b    = (const float*)d_in[8];
    const float* w_aproj = (const float*)d_in[9];
    const float* w_exp   = (const float*)d_in[10];
    const float* eln_g   = (const float*)d_in[11];
    const float* eln_b   = (const float*)d_in[12];
    const float* w_eproj = (const float*)d_in[13];
    const float* w_out   = (const float*)d_in[14];
    float* out = (float*)d_out;

    float *Hid, *Pre, *Ain, *Post, *Aout, *AiT, *AdaptS,
          *Eall, *EcompS, *Wcomb, *WcombR, *W2, *W2R, *Tep, *Tap,
          *xR, *WgR, *WuR, *WdR, *WoutR, *WpreR, *WpostR, *WexpR;
    cudaGetSymbolAddress((void**)&Hid,    g_Hid);
    cudaGetSymbolAddress((void**)&Pre,    g_Pre);
    cudaGetSymbolAddress((void**)&Ain,    g_Ain);
    cudaGetSymbolAddress((void**)&Post,   g_Post);
    cudaGetSymbolAddress((void**)&Aout,   g_Aout);
    cudaGetSymbolAddress((void**)&AiT,    g_AiT);
    cudaGetSymbolAddress((void**)&AdaptS, g_AdaptS);
    cudaGetSymbolAddress((void**)&Eall,   g_Eall);
    cudaGetSymbolAddress((void**)&EcompS, g_EcompS);
    cudaGetSymbolAddress((void**)&Wcomb,  g_Wcomb);
    cudaGetSymbolAddress((void**)&WcombR, g_WcombR);
    cudaGetSymbolAddress((void**)&W2,     g_W2);
    cudaGetSymbolAddress((void**)&W2R,    g_W2R);
    cudaGetSymbolAddress((void**)&Tep,    g_Tep);
    cudaGetSymbolAddress((void**)&Tap,    g_Tap);
    cudaGetSymbolAddress((void**)&xR,     g_xR);
    cudaGetSymbolAddress((void**)&WgR,    g_WgR);
    cudaGetSymbolAddress((void**)&WuR,    g_WuR);
    cudaGetSymbolAddress((void**)&WdR,    g_WdR);
    cudaGetSymbolAddress((void**)&WoutR,  g_WoutR);
    cudaGetSymbolAddress((void**)&WpreR,  g_WpreR);
    cudaGetSymbolAddress((void**)&WpostR, g_WpostR);
    cudaGetSymbolAddress((void**)&WexpR,  g_WexpR);

    cudaFuncSetAttribute(tc_gemm,   cudaFuncAttributeMaxDynamicSharedMemorySize, TCG_SMEM);
    cudaFuncSetAttribute(tc_out,    cudaFuncAttributeMaxDynamicSharedMemorySize, TCG_SMEM);
    cudaFuncSetAttribute(tc_swiglu, cudaFuncAttributeMaxDynamicSharedMemorySize, SWI_SMEM);
    cudaFuncSetAttribute(tc_adapt,  cudaFuncAttributeMaxDynamicSharedMemorySize, ADP_SMEM);

    dim3 tb32(32, 8);

    // ---- round raw inputs to tf32 once (one float4/thread) ----
    rnd_kernel<<<RND_GRID((long)MM * DD), 256>>>(x,      xR,     (long)MM * DD);
    rnd_kernel<<<RND_GRID((long)HH * DD), 256>>>(w_gate, WgR,    (long)HH * DD);
    rnd_kernel<<<RND_GRID((long)HH * DD), 256>>>(w_up,   WuR,    (long)HH * DD);
    rnd_kernel<<<RND_GRID((long)DD * HH), 256>>>(w_down, WdR,    (long)DD * HH);
    rnd_kernel<<<RND_GRID((long)DD * HH), 256>>>(w_out,  WoutR,  (long)DD * HH);
    rnd_kernel<<<RND_GRID((long)AA * DD), 256>>>(w_pre,  WpreR,  (long)AA * DD);
    rnd_kernel<<<RND_GRID((long)AA * HH), 256>>>(w_post, WpostR, (long)AA * HH);
    rnd_kernel<<<RND_GRID((long)EE * AA * AA), 256>>>(w_exp, WexpR, (long)EE * AA * AA);

    // ---- zero split-K atomic targets ----
    zero_kernel<<<64, 256>>>(Wcomb, (long)DD * AA);
    zero_kernel<<<64, 256>>>(W2,    (long)DD * AA);

    // ---- weight-only precomputes (split-K 16, atomic) ----
    transpose_kernel<<<dim3(AA / 32, HH / 32, 1), tb32>>>(w_eproj, Tep, HH, AA, 0, 0);
    transpose_kernel<<<dim3(AA / 32, HH / 32, 1), tb32>>>(w_aproj, Tap, HH, AA, 0, 0);
    tc_gemm<<<dim3(1, DD / 128, 16), 256, TCG_SMEM>>>(WoutR, Tep, Wcomb, nullptr,
                                                      DD, AA, HH, 0, 0, 0, 1.f, 4, 16, 0);
    tc_gemm<<<dim3(1, DD / 128, 16), 256, TCG_SMEM>>>(WdR, Tap, W2, nullptr,
                                                      DD, AA, HH, 0, 0, 0, 1.f, 4, 16, 0);
    rnd_kernel<<<RND_GRID((long)DD * AA), 256>>>(Wcomb, WcombR, (long)DD * AA);
    rnd_kernel<<<RND_GRID((long)DD * AA), 256>>>(W2,    W2R,    (long)DD * AA);

    // ---- fused gate+up+SwiGLU -> Hid ----
    tc_swiglu<<<dim3(HH / 128, MM / 128, 1), 256, SWI_SMEM>>>(xR, WgR, WuR, Hid, DD);

    // ---- pre / adapt_in (rounded store feeds ln + Eall GEMM) ----
    tc_gemm<<<dim3(1, MM / 128, 1), 256, TCG_SMEM>>>(xR, WpreR, Pre, nullptr,
                                                     MM, AA, DD, 0, 0, 0, 1.f, 0, 1, 1);
    ln_kernel<<<MM, 128>>>(Pre, Ain, an_g, an_b);

    // ---- post / adapt_out ----
    tc_gemm<<<dim3(1, MM / 128, 1), 256, TCG_SMEM>>>(Hid, WpostR, Post, nullptr,
                                                     MM, AA, HH, 0, 0, 0, 1.f, 0, 1, 0);
    ln_kernel<<<MM, 128>>>(Post, Aout, an_g, an_b);

    // ---- fused adapt attention -> AdaptS (pre-scaled 0.1) ----
    transpose_kernel<<<dim3(AA / 32, SS / 32, BB), tb32>>>(Ain, AiT, SS, AA,
                                                           (long)SS * AA, (long)SS * AA);
    tc_adapt<<<dim3(SS / 128, BB, 1), 256, ADP_SMEM>>>(Ain, Aout, AiT, AdaptS);

    // ---- experts -> EcompS (pre-scaled 0.1) ----
    tc_gemm<<<dim3(EE * AA / 128, MM / 128, 1), 256, TCG_SMEM>>>(Pre, WexpR, Eall, nullptr,
                                                                 MM, EE * AA, AA,
                                                                 0, 0, 0, 1.f, 0, 1, 0);
    expert_select_kernel<<<MM, 128>>>(ew, Eall, eln_g, eln_b, EcompS);

    // ---- single-pass output: out = Hid@WdR^T + AdaptS@W2R^T + EcompS@WcombR^T ----
    tc_out<<<dim3(DD / 128, MM / 128, 1), 256, TCG_SMEM>>>(Hid, WdR, AdaptS, W2R,
                                                           EcompS, WcombR, out);
}

// round 14
// speedup vs baseline: 1.4011x; 1.0443x over previous
#include <cuda_runtime.h>
#include <cuda_bf16.h>
#include <cstdint>

// Problem dims (fixed)
#define BB 8
#define SS 2048
#define DD 1024
#define HH 2048
#define AA 128
#define EE 8
#define MM (BB*SS)   // 16384 tokens

// tcgen05 is arch-SPECIFIC (sm_103a). Only use it in an arch-specific pass.
#if defined(__CUDA_ARCH_FEAT_SM103_ALL)
#define TCPATH 1
#endif

// -------- scratch (device globals; no allocation allowed) --------
__device__ float g_Hid[MM*HH];         // hidden0 = silu(gate)*up (tf32-rounded)
__device__ float g_Pre[MM*AA];         // rounded (feeds Eall GEMM)
__device__ float g_Ain[MM*AA];         // LN(pre), rounded
__device__ float g_Aout[MM*AA];        // LN(post), rounded
__device__ float g_AiT[BB*AA*SS];      // adapt_in transposed per batch [A,S], rounded
__device__ float g_AdaptS[MM*AA];      // fused adapt output, PRE-SCALED by 0.1, rounded
__device__ float g_EcompS[MM*AA];      // selected+LN'd expert act, PRE-SCALED 0.1, rounded
__device__ float g_Wcomb[DD*AA];       // w_out @ w_eproj (exact, atomic)
__device__ float g_WcombR[DD*AA];      // rounded
__device__ float g_W2[DD*AA];          // w_down @ w_aproj (exact, atomic)
__device__ float g_W2R[DD*AA];         // rounded
__device__ float g_Tep[AA*HH];         // w_eproj^T, rounded
__device__ float g_Tap[AA*HH];         // w_aproj^T, rounded
// rounded raw inputs
__device__ float g_xR[MM*DD];
__device__ float g_WgR[HH*DD];
__device__ float g_WuR[HH*DD];
__device__ float g_WdR[DD*HH];
__device__ float g_WoutR[DD*HH];
__device__ float g_WpreR[AA*DD];
__device__ float g_WpostR[AA*HH];
__device__ float g_WexpR[EE*AA*AA];

// ============================================================
// common helpers
// ============================================================
__device__ __forceinline__ float silu_f(float v) {
    return v * __frcp_rn(1.f + __expf(-v));
}

__device__ __forceinline__ uint32_t f2tf32(float f) {
    uint32_t u;
    asm("cvt.rna.tf32.f32 %0, %1;" : "=r"(u) : "f"(f));
    return u;
}
__device__ __forceinline__ float rndf(float f) {
    return __uint_as_float(f2tf32(f));
}

#ifdef TCPATH
// ============================================================
// tcgen05 helpers (sm_103a-specific pass only)
// ============================================================
__device__ __forceinline__ uint32_t smem_u32(const void* p) {
    uint32_t a;
    asm("{ .reg .u64 t; cvta.to.shared.u64 t, %1; cvt.u32.u64 %0, t; }"
        : "=r"(a) : "l"(p));
    return a;
}

__device__ __forceinline__ uint32_t elect1() {
    uint32_t p;
    asm volatile("{\n\t.reg .pred p;\n\telect.sync _|p, 0xFFFFFFFF;\n\t"
                 "selp.b32 %0, 1, 0, p;\n\t}" : "=r"(p));
    return p;
}

#define MBAR_INIT(addr, cnt) \
    asm volatile("mbarrier.init.shared.b64 [%0], %1;" :: "r"(addr), "r"(cnt) : "memory")

__device__ __forceinline__ void mbar_wait(uint32_t mbar, uint32_t parity) {
    uint32_t done;
    asm volatile("{\n\t.reg .pred p;\n\t"
                 "mbarrier.try_wait.parity.acquire.cta.shared::cta.b64 p, [%1], %2;\n\t"
                 "selp.b32 %0, 1, 0, p;\n\t}"
                 : "=r"(done) : "r"(mbar), "r"(parity) : "memory");
    while (!done) {
        asm volatile("{\n\t.reg .pred p;\n\t"
                     "mbarrier.try_wait.parity.acquire.cta.shared::cta.b64 p, [%1], %2, 0x989680;\n\t"
                     "selp.b32 %0, 1, 0, p;\n\t}"
                     : "=r"(done) : "r"(mbar), "r"(parity) : "memory");
    }
}

__device__ __forceinline__ void mma_tf32(uint32_t d, uint64_t da, uint64_t db,
                                         uint32_t idesc, uint32_t en) {
    asm volatile(
        "{\n\t.reg .pred p;\n\tsetp.ne.u32 p, %4, 0;\n\t"
        "tcgen05.mma.cta_group::1.kind::tf32 [%0], %1, %2, %3, {%5, %5, %5, %5}, p;\n\t}"
        :: "r"(d), "l"(da), "l"(db), "r"(idesc), "r"(en), "r"(0u)
        : "memory");
}

#define TC_COMMIT(mbar) \
    asm volatile("tcgen05.commit.cta_group::1.mbarrier::arrive::one.shared::cluster.b64 [%0];" \
                 :: "r"(mbar) : "memory")

#define LDTM_X32(r, addr) \
    asm volatile("tcgen05.ld.sync.aligned.32x32b.x32.b32 " \
        "{%0,%1,%2,%3,%4,%5,%6,%7,%8,%9,%10,%11,%12,%13,%14,%15," \
        "%16,%17,%18,%19,%20,%21,%22,%23,%24,%25,%26,%27,%28,%29,%30,%31}, [%32];" \
        : "=r"((r)[0]),  "=r"((r)[1]),  "=r"((r)[2]),  "=r"((r)[3]), \
          "=r"((r)[4]),  "=r"((r)[5]),  "=r"((r)[6]),  "=r"((r)[7]), \
          "=r"((r)[8]),  "=r"((r)[9]),  "=r"((r)[10]), "=r"((r)[11]), \
          "=r"((r)[12]), "=r"((r)[13]), "=r"((r)[14]), "=r"((r)[15]), \
          "=r"((r)[16]), "=r"((r)[17]), "=r"((r)[18]), "=r"((r)[19]), \
          "=r"((r)[20]), "=r"((r)[21]), "=r"((r)[22]), "=r"((r)[23]), \
          "=r"((r)[24]), "=r"((r)[25]), "=r"((r)[26]), "=r"((r)[27]), \
          "=r"((r)[28]), "=r"((r)[29]), "=r"((r)[30]), "=r"((r)[31]) \
        : "r"(addr))

static __device__ __forceinline__ uint64_t make_desc(uint32_t addr) {
    const uint64_t base = (2ULL << 61) | (1ULL << 46) | (64ULL << 32) | (1ULL << 16);
    return base | ((uint64_t)(addr >> 4) & 0x3FFF);
}

// idesc: dtype=F32(1<<4), atype=btype=TF32(2), N=128 ((N/8)<<17), M=128 ((M/16)<<24)
#define IDESC_TF32 ((1u << 4) | (2u << 7) | (2u << 10) | (16u << 17) | (8u << 24))

// Shared mainloop: stages A/B 128x32 chunks via 3-buffer cp.async pipe and
// issues MMAs into tmem (cols 0-127). Requires nch >= 4.
#define TC_MAINLOOP(Ap, Bp, ldA, nch, data0, tmem, MB0, MB1, MB2)            \
    int ph0 = 0, ph1 = 0, ph2 = 0;                                           \
    {                                                                        \
    __extension__ auto issue_cp = [&](int c, int b) {                        \
        const int k0_ = c << 5;                                              \
        const uint32_t so_ = (uint32_t)b * 32768u;                           \
        _Pragma("unroll")                                                    \
        for (int it_ = 0; it_ < 8; it_++) {                                  \
            int idx_ = it_ * 256 + tid;                                      \
            int r_ = idx_ >> 3, q_ = idx_ & 7;                               \
            const float* src_ = (r_ < 128)                                   \
                ? ((Ap) + (long)r_ * (ldA) + k0_ + q_ * 4)                   \
                : ((Bp) + (long)(r_ - 128) * (ldA) + k0_ + q_ * 4);          \
            uint32_t off_ = (uint32_t)(r_ * 128 + q_ * 16);                  \
            uint32_t sw_ = off_ ^ ((off_ >> 3) & 0x70u);                     \
            asm volatile("cp.async.cg.shared.global [%0], [%1], 16;"         \
                :: "r"((data0) + so_ + sw_), "l"(src_) : "memory");          \
        }                                                                    \
        asm volatile("cp.async.commit_group;" ::: "memory");                 \
    };                                                                       \
    issue_cp(0, 0);                                                          \
    issue_cp(1, 1);                                                          \
    for (int i = 0; i < (nch); i++) {                                        \
        const int ip2 = i + 2;                                               \
        if (ip2 < (nch)) {                                                   \
            const int b = ip2 % 3;                                           \
            if (i >= 1) {                                                    \
                if (b == 0)      { mbar_wait(MB0, ph0); ph0 ^= 1; }          \
                else if (b == 1) { mbar_wait(MB1, ph1); ph1 ^= 1; }          \
                else             { mbar_wait(MB2, ph2); ph2 ^= 1; }          \
            }                                                                \
            issue_cp(ip2, b);                                                \
        }                                                                    \
        if (ip2 < (nch))          asm volatile("cp.async.wait_group 2;" ::: "memory"); \
        else if (i + 1 < (nch))   asm volatile("cp.async.wait_group 1;" ::: "memory"); \
        else                      asm volatile("cp.async.wait_group 0;" ::: "memory"); \
        asm volatile("fence.proxy.async.shared::cta;" ::: "memory");         \
        __syncthreads();                                                     \
        if (wid == 0 && elect1()) {                                          \
            const int bi = i % 3;                                            \
            uint64_t da = make_desc((data0) + (uint32_t)bi * 32768u);        \
            uint64_t db = make_desc((data0) + (uint32_t)bi * 32768u + 16384u); \
            _Pragma("unroll")                                                \
            for (int ks = 0; ks < 4; ks++)                                   \
                mma_tf32(tmem, da + ks * 2, db + ks * 2, IDESC_TF32,         \
                         (i > 0 || ks > 0) ? 1u : 0u);                       \
            if (bi == 0)      TC_COMMIT(MB0);                                \
            else if (bi == 1) TC_COMMIT(MB1);                                \
            else              TC_COMMIT(MB2);                                \
        }                                                                    \
    }                                                                        \
    }                                                                        \
    mbar_wait(MB0, ph0);                                                     \
    mbar_wait(MB1, ph1);                                                     \
    mbar_wait(MB2, ph2);                                                     \
    asm volatile("tcgen05.fence::after_thread_sync;" ::: "memory");
#endif  // TCPATH

// ============================================================
// tc_gemm: 128x128 tile (validated path)
// ============================================================
#define TCG_SMEM (2048 + 3 * 32768)   // 100352

__global__ __launch_bounds__(256)
void tc_gemm(const float* __restrict__ A, const float* __restrict__ B,
             float* __restrict__ C, const float* __restrict__ G,
             int M, int N, int K, long sA, long sB, long sC,
             float alpha, int mode, int ksplit, int rnd)
{
    extern __shared__ char smem[];
    const int tid  = threadIdx.x;
    const int wid  = tid >> 5;
    const int lane = tid & 31;

    int Kc;
    {
        int bz = blockIdx.z;
        long b = bz / ksplit;
        int ik = bz - (int)b * ksplit;
        Kc = K / ksplit;
        A += b * sA + (long)ik * Kc;
        B += b * sB + (long)ik * Kc;
        C += b * sC;
        if (mode == 3) G += b * sC;
    }
    const int m0 = blockIdx.y * 128, n0 = blockIdx.x * 128;
    const float* Ap = A + (long)m0 * K;
    const float* Bp = B + (long)n0 * K;
    const int nch = Kc >> 5;

#ifdef TCPATH
    uint32_t sbase = smem_u32(smem);
    const uint32_t TM_PTR = sbase;
    const uint32_t MB0 = sbase + 16;
    const uint32_t MB1 = sbase + 24;
    const uint32_t MB2 = sbase + 32;
    uint32_t data0 = (sbase + 1024 + 1023) & ~1023u;

    if (wid == 0) {
        asm volatile("tcgen05.alloc.cta_group::1.sync.aligned.shared::cta.b32 [%0], %1;"
                     :: "r"(TM_PTR), "r"(128u) : "memory");
        asm volatile("tcgen05.relinquish_alloc_permit.cta_group::1.sync.aligned;");
    }
    if (tid == 0) { MBAR_INIT(MB0, 1); MBAR_INIT(MB1, 1); MBAR_INIT(MB2, 1); }
    __syncthreads();
    uint32_t tmem;
    asm volatile("ld.shared.b32 %0, [%1];" : "=r"(tmem) : "r"(TM_PTR));

    TC_MAINLOOP(Ap, Bp, K, nch, data0, tmem, MB0, MB1, MB2);

    if (wid < 4) {
        float* Crow = C + (long)(m0 + wid * 32 + lane) * N + n0;
        const float* Grow = (mode == 3)
            ? (G + (long)(m0 + wid * 32 + lane) * N + n0) : nullptr;
#pragma unroll
        for (int cb = 0; cb < 128; cb += 32) {
            uint32_t r[32];
            LDTM_X32(r, tmem + cb);
            asm volatile("tcgen05.wait::ld.sync.aligned;" ::: "memory");
            if (mode == 4) {
#pragma unroll
                for (int j = 0; j < 32; j++)
                    atomicAdd(Crow + cb + j, alpha * __uint_as_float(r[j]));
            } else {
#pragma unroll
                for (int j = 0; j < 32; j += 4) {
                    float4 v;
                    v.x = __uint_as_float(r[j + 0]);
                    v.y = __uint_as_float(r[j + 1]);
                    v.z = __uint_as_float(r[j + 2]);
                    v.w = __uint_as_float(r[j + 3]);
                    if (mode == 0) {
                        v.x *= alpha; v.y *= alpha; v.z *= alpha; v.w *= alpha;
                    } else if (mode == 1) {
                        float4 c = *(const float4*)(Crow + cb + j);
                        v.x = fmaf(alpha, v.x, c.x); v.y = fmaf(alpha, v.y, c.y);
                        v.z = fmaf(alpha, v.z, c.z); v.w = fmaf(alpha, v.w, c.w);
                    } else if (mode == 2) {
                        v.x = silu_f(fminf(5.f, fmaxf(-5.f, v.x)));
                        v.y = silu_f(fminf(5.f, fmaxf(-5.f, v.y)));
                        v.z = silu_f(fminf(5.f, fmaxf(-5.f, v.z)));
                        v.w = silu_f(fminf(5.f, fmaxf(-5.f, v.w)));
                    } else {
                        float4 g = *(const float4*)(Grow + cb + j);
                        v.x *= silu_f(g.x); v.y *= silu_f(g.y);
                        v.z *= silu_f(g.z); v.w *= silu_f(g.w);
                    }
                    if (rnd) {
                        v.x = rndf(v.x); v.y = rndf(v.y);
                        v.z = rndf(v.z); v.w = rndf(v.w);
                    }
                    *(float4*)(Crow + cb + j) = v;
                }
            }
        }
    }
    asm volatile("tcgen05.fence::before_thread_sync;" ::: "memory");
    __syncthreads();
    if (wid == 0) {
        asm volatile("tcgen05.dealloc.cta_group::1.sync.aligned.b32 %0, %1;"
                     :: "r"(tmem), "r"(128u));
    }
#else
    for (int idx = tid; idx < 128 * 128; idx += 256) {
        int rr = idx >> 7, cc = idx & 127;
        long ci = (long)(m0 + rr) * N + n0 + cc;
        float acc = 0.f;
        for (int k = 0; k < Kc; k++)
            acc += A[(long)(m0 + rr) * K + k] * B[(long)(n0 + cc) * K + k];
        float v;
        if (mode == 4) { atomicAdd(C + ci, alpha * acc); continue; }
        else if (mode == 0) v = alpha * acc;
        else if (mode == 1) v = fmaf(alpha, acc, C[ci]);
        else if (mode == 2) v = silu_f(fminf(5.f, fmaxf(-5.f, acc)));
        else                v = silu_f(G[ci]) * acc;
        if (rnd) v = rndf(v);
        C[ci] = v;
    }
#endif
}

// ============================================================
// tc_preln: GEMM (M x 128, grid=(1, M/128)) + LN epilogue.
//   acc row -> rnd -> (optional PreOut store) -> LN(g,b) -> OutLN
//   (optional transposed store to TOut[b][c][s], b=batch of row)
// ============================================================
__global__ __launch_bounds__(256)
void tc_preln(const float* __restrict__ A, const float* __restrict__ B,
              float* __restrict__ OutLN, float* __restrict__ PreOut,
              float* __restrict__ TOut,
              const float* __restrict__ lg, const float* __restrict__ lb,
              int K)
{
    extern __shared__ char smem[];
    const int tid  = threadIdx.x;
    const int wid  = tid >> 5;
    const int lane = tid & 31;
    const int m0 = blockIdx.y * 128;
    const float* Ap = A + (long)m0 * K;
    const float* Bp = B;
    const int nch = K >> 5;

#ifdef TCPATH
    uint32_t sbase = smem_u32(smem);
    const uint32_t TM_PTR = sbase;
    const uint32_t MB0 = sbase + 16;
    const uint32_t MB1 = sbase + 24;
    const uint32_t MB2 = sbase + 32;
    uint32_t data0 = (sbase + 1024 + 1023) & ~1023u;

    if (wid == 0) {
        asm volatile("tcgen05.alloc.cta_group::1.sync.aligned.shared::cta.b32 [%0], %1;"
                     :: "r"(TM_PTR), "r"(128u) : "memory");
        asm volatile("tcgen05.relinquish_alloc_permit.cta_group::1.sync.aligned;");
    }
    if (tid == 0) { MBAR_INIT(MB0, 1); MBAR_INIT(MB1, 1); MBAR_INIT(MB2, 1); }
    __syncthreads();
    uint32_t tmem;
    asm volatile("ld.shared.b32 %0, [%1];" : "=r"(tmem) : "r"(TM_PTR));

    TC_MAINLOOP(Ap, Bp, K, nch, data0, tmem, MB0, MB1, MB2);

    if (wid < 4) {
        const int rl = wid * 32 + lane;
        const long rg = m0 + rl;
        // pass 1: mean/var over the row (values = rnd(acc), same as before)
        float s = 0.f, s2 = 0.f;
#pragma unroll
        for (int cb = 0; cb < 128; cb += 32) {
            uint32_t r[32];
            LDTM_X32(r, tmem + cb);
            asm volatile("tcgen05.wait::ld.sync.aligned;" ::: "memory");
#pragma unroll
            for (int j = 0; j < 32; j++) {
                float v = rndf(__uint_as_float(r[j]));
                s += v; s2 += v * v;
            }
        }
        float mean = s * (1.f / 128.f);
        float var  = s2 * (1.f / 128.f) - mean * mean;
        float inv  = rsqrtf(var + 1e-5f);
        int bb = (int)(rg / SS);
        long ss = rg - (long)bb * SS;
        float* Trow = TOut ? (TOut + (long)bb * AA * SS + ss) : nullptr;
        // pass 2: write
#pragma unroll
        for (int cb = 0; cb < 128; cb += 32) {
            uint32_t r[32];
            LDTM_X32(r, tmem + cb);
            asm volatile("tcgen05.wait::ld.sync.aligned;" ::: "memory");
#pragma unroll
            for (int j = 0; j < 32; j += 4) {
                int c = cb + j;
                float4 v;
                v.x = rndf(__uint_as_float(r[j + 0]));
                v.y = rndf(__uint_as_float(r[j + 1]));
                v.z = rndf(__uint_as_float(r[j + 2]));
                v.w = rndf(__uint_as_float(r[j + 3]));
                if (PreOut) *(float4*)(PreOut + rg * 128 + c) = v;
                float4 o;
                o.x = rndf((v.x - mean) * inv * lg[c + 0] + lb[c + 0]);
                o.y = rndf((v.y - mean) * inv * lg[c + 1] + lb[c + 1]);
                o.z = rndf((v.z - mean) * inv * lg[c + 2] + lb[c + 2]);
                o.w = rndf((v.w - mean) * inv * lg[c + 3] + lb[c + 3]);
                *(float4*)(OutLN + rg * 128 + c) = o;
                if (Trow) {
                    Trow[(long)(c + 0) * SS] = o.x;
                    Trow[(long)(c + 1) * SS] = o.y;
                    Trow[(long)(c + 2) * SS] = o.z;
                    Trow[(long)(c + 3) * SS] = o.w;
                }
            }
        }
    }
    asm volatile("tcgen05.fence::before_thread_sync;" ::: "memory");
    __syncthreads();
    if (wid == 0) {
        asm volatile("tcgen05.dealloc.cta_group::1.sync.aligned.b32 %0, %1;"
                     :: "r"(tmem), "r"(128u));
    }
#else
    for (int rl = tid; rl < 128; rl += 256) {
        long rg = m0 + rl;
        float row[128];
        float s = 0.f, s2 = 0.f;
        for (int c = 0; c < 128; c++) {
            float acc = 0.f;
            for (int k = 0; k < K; k++)
                acc += A[rg * K + k] * B[(long)c * K + k];
            row[c] = rndf(acc);
            s += row[c]; s2 += row[c] * row[c];
        }
        float mean = s / 128.f, var = s2 / 128.f - mean * mean;
        float inv = rsqrtf(var + 1e-5f);
        int bb = (int)(rg / SS); long ss = rg - (long)bb * SS;
        for (int c = 0; c < 128; c++) {
            if (PreOut) PreOut[rg * 128 + c] = row[c];
            float o = rndf((row[c] - mean) * inv * lg[c] + lb[c]);
            OutLN[rg * 128 + c] = o;
            if (TOut) TOut[(long)bb * AA * SS + (long)c * SS + ss] = o;
        }
    }
#endif
}

// ============================================================
// tc_eall: experts GEMM (A=Pre, B=WexpR) + fused select/LN epilogue.
// grid = (EE, M/128). Tile n0 = expert e * 128. For rows whose
// selected expert == e: EcompS[row] = rnd(0.1 * LN_e(acc)).
// EcompS must be pre-zeroed.
// ============================================================
__global__ __launch_bounds__(256)
void tc_eall(const float* __restrict__ A, const float* __restrict__ B,
             const float* __restrict__ ew,
             const float* __restrict__ eg, const float* __restrict__ eb,
             float* __restrict__ EcompS)
{
    extern __shared__ char smem[];
    const int tid  = threadIdx.x;
    const int wid  = tid >> 5;
    const int lane = tid & 31;
    const int e  = blockIdx.x;
    const int m0 = blockIdx.y * 128;
    const float* Ap = A + (long)m0 * AA;
    const float* Bp = B + (long)e * 128 * AA;
    const int nch = AA >> 5;   // 4

#ifdef TCPATH
    uint32_t sbase = smem_u32(smem);
    const uint32_t TM_PTR = sbase;
    const uint32_t MB0 = sbase + 16;
    const uint32_t MB1 = sbase + 24;
    const uint32_t MB2 = sbase + 32;
    uint32_t data0 = (sbase + 1024 + 1023) & ~1023u;

    if (wid == 0) {
        asm volatile("tcgen05.alloc.cta_group::1.sync.aligned.shared::cta.b32 [%0], %1;"
                     :: "r"(TM_PTR), "r"(128u) : "memory");
        asm volatile("tcgen05.relinquish_alloc_permit.cta_group::1.sync.aligned;");
    }
    if (tid == 0) { MBAR_INIT(MB0, 1); MBAR_INIT(MB1, 1); MBAR_INIT(MB2, 1); }
    __syncthreads();
    uint32_t tmem;
    asm volatile("ld.shared.b32 %0, [%1];" : "=r"(tmem) : "r"(TM_PTR));

    TC_MAINLOOP(Ap, Bp, AA, nch, data0, tmem, MB0, MB1, MB2);

    if (wid < 4) {
        const int rl = wid * 32 + lane;
        const long rg = m0 + rl;
        // selection: last expert with ew>0 (later wins)
        int idx = -1;
        const float* w = ew + rg * EE;
#pragma unroll
        for (int i = 0; i < EE; i++) if (w[i] > 0.f) idx = i;
        const bool sel = (idx == e);
        // pass 1 (exact values — Eall was stored unrounded before)
        float s = 0.f, s2 = 0.f;
#pragma unroll
        for (int cb = 0; cb < 128; cb += 32) {
            uint32_t r[32];
            LDTM_X32(r, tmem + cb);
            asm volatile("tcgen05.wait::ld.sync.aligned;" ::: "memory");
#pragma unroll
            for (int j = 0; j < 32; j++) {
                float v = __uint_as_float(r[j]);
                s += v; s2 += v * v;
            }
        }
        float mean = s * (1.f / 128.f);
        float var  = s2 * (1.f / 128.f) - mean * mean;
        float inv  = rsqrtf(var + 1e-5f);
        // pass 2: predicated store
#pragma unroll
        for (int cb = 0; cb < 128; cb += 32) {
            uint32_t r[32];
            LDTM_X32(r, tmem + cb);
            asm volatile("tcgen05.wait::ld.sync.aligned;" ::: "memory");
            if (sel) {
#pragma unroll
                for (int j = 0; j < 32; j += 4) {
                    int c = cb + j;
                    float4 o;
                    o.x = rndf(0.1f * ((__uint_as_float(r[j + 0]) - mean) * inv
                               * eg[e * AA + c + 0] + eb[e * AA + c + 0]));
                    o.y = rndf(0.1f * ((__uint_as_float(r[j + 1]) - mean) * inv
                               * eg[e * AA + c + 1] + eb[e * AA + c + 1]));
                    o.z = rndf(0.1f * ((__uint_as_float(r[j + 2]) - mean) * inv
                               * eg[e * AA + c + 2] + eb[e * AA + c + 2]));
                    o.w = rndf(0.1f * ((__uint_as_float(r[j + 3]) - mean) * inv
                               * eg[e * AA + c + 3] + eb[e * AA + c + 3]));
                    *(float4*)(EcompS + rg * 128 + c) = o;
                }
            }
        }
    }
    asm volatile("tcgen05.fence::before_thread_sync;" ::: "memory");
    __syncthreads();
    if (wid == 0) {
        asm volatile("tcgen05.dealloc.cta_group::1.sync.aligned.b32 %0, %1;"
                     :: "r"(tmem), "r"(128u));
    }
#else
    for (int rl = tid; rl < 128; rl += 256) {
        long rg = m0 + rl;
        int idx = -1;
        for (int i = 0; i < EE; i++) if (ew[rg * EE + i] > 0.f) idx = i;
        if (idx != e) continue;
        float row[128];
        float s = 0.f, s2 = 0.f;
        for (int c = 0; c < 128; c++) {
            float acc = 0.f;
            for (int k = 0; k < AA; k++)
                acc += A[rg * AA + k] * B[((long)e * 128 + c) * AA + k];
            row[c] = acc; s += acc; s2 += acc * acc;
        }
        float mean = s / 128.f, var = s2 / 128.f - mean * mean;
        float inv = rsqrtf(var + 1e-5f);
        for (int c = 0; c < 128; c++)
            EcompS[rg * 128 + c] = rndf(0.1f * ((row[c] - mean) * inv
                                   * eg[e * AA + c] + eb[e * AA + c]));
    }
#endif
}

// ============================================================
// tc_out: single-pass output GEMM (validated R13 path, unchanged)
// ============================================================
__global__ __launch_bounds__(256)
void tc_out(const float* __restrict__ Hid, const float* __restrict__ WdR,
            const float* __restrict__ AdS, const float* __restrict__ W2R,
            const float* __restrict__ EcS, const float* __restrict__ WcR,
            float* __restrict__ C)
{
    extern __shared__ char smem[];
    const int tid  = threadIdx.x;
    const int wid  = tid >> 5;
    const int lane = tid & 31;
    const int m0 = blockIdx.y * 128, n0 = blockIdx.x * 128;
    const int N = DD;
    const int nch = 72;

#ifdef TCPATH
    uint32_t sbase = smem_u32(smem);
    const uint32_t TM_PTR = sbase;
    const uint32_t MB0 = sbase + 16;
    const uint32_t MB1 = sbase + 24;
    const uint32_t MB2 = sbase + 32;
    uint32_t data0 = (sbase + 1024 + 1023) & ~1023u;

    if (wid == 0) {
        asm volatile("tcgen05.alloc.cta_group::1.sync.aligned.shared::cta.b32 [%0], %1;"
                     :: "r"(TM_PTR), "r"(128u) : "memory");
        asm volatile("tcgen05.relinquish_alloc_permit.cta_group::1.sync.aligned;");
    }
    if (tid == 0) { MBAR_INIT(MB0, 1); MBAR_INIT(MB1, 1); MBAR_INIT(MB2, 1); }
    __syncthreads();
    uint32_t tmem;
    asm volatile("ld.shared.b32 %0, [%1];" : "=r"(tmem) : "r"(TM_PTR));

#define OUT_CP(c, b) do {                                                    \
        const float* aB_; const float* bB_; int ldA_, k0_;                   \
        if ((c) < 64)      { aB_ = Hid + (long)m0 * HH; bB_ = WdR + (long)n0 * HH; \
                             ldA_ = HH; k0_ = (c) << 5; }                    \
        else if ((c) < 68) { aB_ = AdS + (long)m0 * AA; bB_ = W2R + (long)n0 * AA; \
                             ldA_ = AA; k0_ = ((c) - 64) << 5; }             \
        else               { aB_ = EcS + (long)m0 * AA; bB_ = WcR + (long)n0 * AA; \
                             ldA_ = AA; k0_ = ((c) - 68) << 5; }             \
        const uint32_t so_ = (uint32_t)(b) * 32768u;                         \
        _Pragma("unroll")                                                    \
        for (int it_ = 0; it_ < 8; it_++) {                                  \
            int idx_ = it_ * 256 + tid;                                      \
            int r_ = idx_ >> 3, q_ = idx_ & 7;                               \
            const float* src_ = (r_ < 128)                                   \
                ? (aB_ + (long)r_ * ldA_ + k0_ + q_ * 4)                     \
                : (bB_ + (long)(r_ - 128) * ldA_ + k0_ + q_ * 4);            \
            uint32_t off_ = (uint32_t)(r_ * 128 + q_ * 16);                  \
            uint32_t sw_ = off_ ^ ((off_ >> 3) & 0x70u);                     \
            asm volatile("cp.async.cg.shared.global [%0], [%1], 16;"         \
                :: "r"(data0 + so_ + sw_), "l"(src_) : "memory");            \
        }                                                                    \
        asm volatile("cp.async.commit_group;" ::: "memory");                 \
    } while (0)

    int ph0 = 0, ph1 = 0, ph2 = 0;
    OUT_CP(0, 0);
    OUT_CP(1, 1);

    for (int i = 0; i < nch; i++) {
        const int ip2 = i + 2;
        if (ip2 < nch) {
            const int b = ip2 % 3;
            if (i >= 1) {
                if (b == 0)      { mbar_wait(MB0, ph0); ph0 ^= 1; }
                else if (b == 1) { mbar_wait(MB1, ph1); ph1 ^= 1; }
                else             { mbar_wait(MB2, ph2); ph2 ^= 1; }
            }
            OUT_CP(ip2, b);
        }
        if (ip2 < nch)          asm volatile("cp.async.wait_group 2;" ::: "memory");
        else if (i + 1 < nch)   asm volatile("cp.async.wait_group 1;" ::: "memory");
        else                    asm volatile("cp.async.wait_group 0;" ::: "memory");
        asm volatile("fence.proxy.async.shared::cta;" ::: "memory");
        __syncthreads();
        if (wid == 0 && elect1()) {
            const int bi = i % 3;
            uint64_t da = make_desc(data0 + (uint32_t)bi * 32768u);
            uint64_t db = make_desc(data0 + (uint32_t)bi * 32768u + 16384u);
#pragma unroll
            for (int ks = 0; ks < 4; ks++)
                mma_tf32(tmem, da + ks * 2, db + ks * 2, IDESC_TF32,
                         (i > 0 || ks > 0) ? 1u : 0u);
            if (bi == 0)      TC_COMMIT(MB0);
            else if (bi == 1) TC_COMMIT(MB1);
            else              TC_COMMIT(MB2);
        }
    }
    mbar_wait(MB0, ph0);
    mbar_wait(MB1, ph1);
    mbar_wait(MB2, ph2);
    asm volatile("tcgen05.fence::after_thread_sync;" ::: "memory");
#undef OUT_CP

    if (wid < 4) {
        float* Crow = C + (long)(m0 + wid * 32 + lane) * N + n0;
#pragma unroll
        for (int cb = 0; cb < 128; cb += 32) {
            uint32_t r[32];
            LDTM_X32(r, tmem + cb);
            asm volatile("tcgen05.wait::ld.sync.aligned;" ::: "memory");
#pragma unroll
            for (int j = 0; j < 32; j += 4) {
                float4 v;
                v.x = __uint_as_float(r[j + 0]);
                v.y = __uint_as_float(r[j + 1]);
                v.z = __uint_as_float(r[j + 2]);
                v.w = __uint_as_float(r[j + 3]);
                *(float4*)(Crow + cb + j) = v;
            }
        }
    }
    asm volatile("tcgen05.fence::before_thread_sync;" ::: "memory");
    __syncthreads();
    if (wid == 0) {
        asm volatile("tcgen05.dealloc.cta_group::1.sync.aligned.b32 %0, %1;"
                     :: "r"(tmem), "r"(128u));
    }
#else
    for (int idx = tid; idx < 128 * 128; idx += 256) {
        int rr = idx >> 7, cc = idx & 127;
        float acc = 0.f;
        for (int k = 0; k < HH; k++)
            acc += Hid[(long)(m0 + rr) * HH + k] * WdR[(long)(n0 + cc) * HH + k];
        for (int k = 0; k < AA; k++)
            acc += AdS[(long)(m0 + rr) * AA + k] * W2R[(long)(n0 + cc) * AA + k];
        for (int k = 0; k < AA; k++)
            acc += EcS[(long)(m0 + rr) * AA + k] * WcR[(long)(n0 + cc) * AA + k];
        C[(long)(m0 + rr) * DD + n0 + cc] = acc;
    }
#endif
}

// ============================================================
// tc_swiglu: fused gate+up GEMM + SwiGLU epilogue (validated, unchanged)
// ============================================================
#define SWI_SMEM (2048 + 3 * 49152)   // 149504

__global__ __launch_bounds__(256)
void tc_swiglu(const float* __restrict__ A, const float* __restrict__ Bg,
               const float* __restrict__ Bu, float* __restrict__ C, int K)
{
    extern __shared__ char smem[];
    const int tid  = threadIdx.x;
    const int wid  = tid >> 5;
    const int lane = tid & 31;
    const int m0 = blockIdx.y * 128, n0 = blockIdx.x * 128;
    const int N = HH;
    const float* Ap  = A  + (long)m0 * K;
    const float* Bgp = Bg + (long)n0 * K;
    const float* Bup = Bu + (long)n0 * K;
    const int nch = K >> 5;   // 32

#ifdef TCPATH
    uint32_t sbase = smem_u32(smem);
    const uint32_t TM_PTR = sbase;
    const uint32_t MB0 = sbase + 16;
    const uint32_t MB1 = sbase + 24;
    const uint32_t MB2 = sbase + 32;
    uint32_t data0 = (sbase + 1024 + 1023) & ~1023u;

    if (wid == 0) {
        asm volatile("tcgen05.alloc.cta_group::1.sync.aligned.shared::cta.b32 [%0], %1;"
                     :: "r"(TM_PTR), "r"(256u) : "memory");
        asm volatile("tcgen05.relinquish_alloc_permit.cta_group::1.sync.aligned;");
    }
    if (tid == 0) { MBAR_INIT(MB0, 1); MBAR_INIT(MB1, 1); MBAR_INIT(MB2, 1); }
    __syncthreads();
    uint32_t tmem;
    asm volatile("ld.shared.b32 %0, [%1];" : "=r"(tmem) : "r"(TM_PTR));

#define SWI_CP(c, b) do {                                                    \
        const int k0_ = (c) << 5;                                            \
        const uint32_t so_ = (uint32_t)(b) * 49152u;                         \
        _Pragma("unroll")                                                    \
        for (int it_ = 0; it_ < 12; it_++) {                                 \
            int idx_ = it_ * 256 + tid;                                      \
            int r_ = idx_ >> 3, q_ = idx_ & 7;                               \
            int rr_ = r_ & 127;                                              \
            const float* src_;                                               \
            if (r_ < 128)       src_ = Ap  + (long)rr_ * K + k0_ + q_ * 4;   \
            else if (r_ < 256)  src_ = Bgp + (long)rr_ * K + k0_ + q_ * 4;   \
            else                src_ = Bup + (long)rr_ * K + k0_ + q_ * 4;   \
            uint32_t off_ = (uint32_t)(rr_ * 128 + q_ * 16);                 \
            uint32_t sw_ = off_ ^ ((off_ >> 3) & 0x70u);                     \
            asm volatile("cp.async.cg.shared.global [%0], [%1], 16;"         \
                :: "r"(data0 + so_ + (uint32_t)(r_ >> 7) * 16384u + sw_),    \
                   "l"(src_) : "memory");                                    \
        }                                                                    \
        asm volatile("cp.async.commit_group;" ::: "memory");                 \
    } while (0)

    int ph0 = 0, ph1 = 0, ph2 = 0;
    SWI_CP(0, 0);
    SWI_CP(1, 1);

    for (int i = 0; i < nch; i++) {
        const int ip2 = i + 2;
        if (ip2 < nch) {
            const int b = ip2 % 3;
            if (i >= 1) {
                if (b == 0)      { mbar_wait(MB0, ph0); ph0 ^= 1; }
                else if (b == 1) { mbar_wait(MB1, ph1); ph1 ^= 1; }
                else             { mbar_wait(MB2, ph2); ph2 ^= 1; }
            }
            SWI_CP(ip2, b);
        }
        if (ip2 < nch)          asm volatile("cp.async.wait_group 2;" ::: "memory");
        else if (i + 1 < nch)   asm volatile("cp.async.wait_group 1;" ::: "memory");
        else                    asm volatile("cp.async.wait_group 0;" ::: "memory");
        asm volatile("fence.proxy.async.shared::cta;" ::: "memory");
        __syncthreads();
        if (wid == 0 && elect1()) {
            const int bi = i % 3;
            uint64_t da  = make_desc(data0 + (uint32_t)bi * 49152u);
            uint64_t dbg = make_desc(data0 + (uint32_t)bi * 49152u + 16384u);
            uint64_t dbu = make_desc(data0 + (uint32_t)bi * 49152u + 32768u);
            uint32_t en0 = (i > 0) ? 1u : 0u;
#pragma unroll
            for (int ks = 0; ks < 4; ks++) {
                uint32_t en = (en0 || ks > 0) ? 1u : 0u;
                mma_tf32(tmem,       da + ks * 2, dbg + ks * 2, IDESC_TF32, en);
                mma_tf32(tmem + 128, da + ks * 2, dbu + ks * 2, IDESC_TF32, en);
            }
            if (bi == 0)      TC_COMMIT(MB0);
            else if (bi == 1) TC_COMMIT(MB1);
            else              TC_COMMIT(MB2);
        }
    }
    mbar_wait(MB0, ph0);
    mbar_wait(MB1, ph1);
    mbar_wait(MB2, ph2);
    asm volatile("tcgen05.fence::after_thread_sync;" ::: "memory");
#undef SWI_CP

    {
        const int sp   = wid & 3;
        const int half = wid >> 2;
        const int row  = m0 + sp * 32 + lane;
        float* Crow = C + (long)row * N + n0;
#pragma unroll
        for (int c = 0; c < 2; c++) {
            const int cb = half * 64 + c * 32;
            uint32_t gr[32], ur[32];
            LDTM_X32(gr, tmem + cb);
            LDTM_X32(ur, tmem + 128 + cb);
            asm volatile("tcgen05.wait::ld.sync.aligned;" ::: "memory");
#pragma unroll
            for (int j = 0; j < 32; j += 4) {
                float4 v;
                v.x = rndf(silu_f(__uint_as_float(gr[j + 0])) * __uint_as_float(ur[j + 0]));
                v.y = rndf(silu_f(__uint_as_float(gr[j + 1])) * __uint_as_float(ur[j + 1]));
                v.z = rndf(silu_f(__uint_as_float(gr[j + 2])) * __uint_as_float(ur[j + 2]));
                v.w = rndf(silu_f(__uint_as_float(gr[j + 3])) * __uint_as_float(ur[j + 3]));
                *(float4*)(Crow + cb + j) = v;
            }
        }
    }
    asm volatile("tcgen05.fence::before_thread_sync;" ::: "memory");
    __syncthreads();
    if (wid == 0) {
        asm volatile("tcgen05.dealloc.cta_group::1.sync.aligned.b32 %0, %1;"
                     :: "r"(tmem), "r"(256u));
    }
#else
    for (int idx = tid; idx < 128 * 128; idx += 256) {
        int rr = idx >> 7, cc = idx & 127;
        float g = 0.f, u = 0.f;
        for (int k = 0; k < K; k++) {
            float a = A[(long)(m0 + rr) * K + k];
            g += a * Bg[(long)(n0 + cc) * K + k];
            u += a * Bu[(long)(n0 + cc) * K + k];
        }
        C[(long)(m0 + rr) * N + n0 + cc] = rndf(silu_f(g) * u);
    }
#endif
}

// ============================================================
// tc_adapt: fused adapt attention; output PRE-SCALED by 0.1 (validated)
// ============================================================
#define ADP_SMEM (2048 + 3 * 65536)   // 198656

__global__ __launch_bounds__(256)
void tc_adapt(const float* __restrict__ Ain,   // [B][S][A] tf32
              const float* __restrict__ Aout,  // [B][S][A] tf32
              const float* __restrict__ AiT,   // [B][A][S] tf32
              float* __restrict__ AdaptS)      // [B][S][A] out = rnd(0.1*acc)
{
    extern __shared__ char smem[];
    const int tid  = threadIdx.x;
    const int wid  = tid >> 5;
    const int lane = tid & 31;
    const int b    = blockIdx.y;
    const int m0   = blockIdx.x * 128;

    const float* AinB  = Ain  + (long)b * SS * AA;
    const float* AoutB = Aout + (long)b * SS * AA;
    const float* AiTB  = AiT  + (long)b * AA * SS;
    float*       AdB   = AdaptS + (long)b * SS * AA;

#ifdef TCPATH
    uint32_t sbase = smem_u32(smem);
    const uint32_t TM_PTR = sbase;
    const uint32_t MB0 = sbase + 16;
    const uint32_t MB1 = sbase + 24;
    uint32_t data0 = (sbase + 1024 + 1023) & ~1023u;
    const uint32_t AinS = data0;
    const uint32_t Bsh  = data0 + 65536u;
    const uint32_t Psh  = data0 + 131072u;

    if (wid == 0) {
        asm volatile("tcgen05.alloc.cta_group::1.sync.aligned.shared::cta.b32 [%0], %1;"
                     :: "r"(TM_PTR), "r"(256u) : "memory");
        asm volatile("tcgen05.relinquish_alloc_permit.cta_group::1.sync.aligned;");
    }
    if (tid == 0) { MBAR_INIT(MB0, 1); MBAR_INIT(MB1, 1); }
    __syncthreads();
    uint32_t tmem;
    asm volatile("ld.shared.b32 %0, [%1];" : "=r"(tmem) : "r"(TM_PTR));

#define ADP_LOAD256(base, gptr, ldg) do {                                    \
        _Pragma("unroll")                                                    \
        for (int it_ = 0; it_ < 16; it_++) {                                 \
            int idx_ = it_ * 256 + tid;                                      \
            int c_ = idx_ >> 10, r_ = (idx_ >> 3) & 127, q_ = idx_ & 7;      \
            const float* src_ = (gptr) + (long)r_ * (ldg) + c_ * 32 + q_ * 4;\
            uint32_t off_ = (uint32_t)(r_ * 128 + q_ * 16);                  \
            uint32_t sw_ = off_ ^ ((off_ >> 3) & 0x70u);                     \
            asm volatile("cp.async.cg.shared.global [%0], [%1], 16;"         \
                :: "r"((base) + (uint32_t)c_ * 16384u + sw_), "l"(src_)      \
                : "memory");                                                 \
        }                                                                    \
        asm volatile("cp.async.commit_group;" ::: "memory");                 \
    } while (0)

    ADP_LOAD256(AinS, AinB + (long)m0 * AA, AA);
    ADP_LOAD256(Bsh,  AoutB, AA);
    asm volatile("cp.async.wait_group 0;" ::: "memory");
    asm volatile("fence.proxy.async.shared::cta;" ::: "memory");
    __syncthreads();

    int ph0 = 0, ph1 = 0;
    for (int kt = 0; kt < 16; kt++) {
        if (wid == 0 && elect1()) {
#pragma unroll
            for (int c = 0; c < 4; c++) {
                uint64_t da = make_desc(AinS + (uint32_t)c * 16384u);
                uint64_t db = make_desc(Bsh  + (uint32_t)c * 16384u);
#pragma unroll
                for (int ks = 0; ks < 4; ks++)
                    mma_tf32(tmem, da + ks * 2, db + ks * 2, IDESC_TF32,
                             (c > 0 || ks > 0) ? 1u : 0u);
            }
            TC_COMMIT(MB0);
        }
        mbar_wait(MB0, ph0); ph0 ^= 1;
        asm volatile("tcgen05.fence::after_thread_sync;" ::: "memory");

        if (wid < 4) {
            const int r = wid * 32 + lane;
#pragma unroll
            for (int cb = 0; cb < 4; cb++) {
                uint32_t rg[32];
                LDTM_X32(rg, tmem + cb * 32);
                asm volatile("tcgen05.wait::ld.sync.aligned;" ::: "memory");
#pragma unroll
                for (int j = 0; j < 32; j += 4) {
                    float4 v;
                    v.x = rndf(silu_f(fminf(5.f, fmaxf(-5.f, __uint_as_float(rg[j + 0])))));
                    v.y = rndf(silu_f(fminf(5.f, fmaxf(-5.f, __uint_as_float(rg[j + 1])))));
                    v.z = rndf(silu_f(fminf(5.f, fmaxf(-5.f, __uint_as_float(rg[j + 2])))));
                    v.w = rndf(silu_f(fminf(5.f, fmaxf(-5.f, __uint_as_float(rg[j + 3])))));
                    uint32_t off = (uint32_t)(r * 128 + j * 4);
                    uint32_t sw = off ^ ((off >> 3) & 0x70u);
                    uint32_t addr = Psh + (uint32_t)cb * 16384u + sw;
                    asm volatile("st.shared.v4.b32 [%0], {%1, %2, %3, %4};"
                        :: "r"(addr), "r"(__float_as_uint(v.x)), "r"(__float_as_uint(v.y)),
                           "r"(__float_as_uint(v.z)), "r"(__float_as_uint(v.w)) : "memory");
                }
            }
        } else {
            const int tid2 = tid - 128;
#pragma unroll
            for (int it = 0; it < 32; it++) {
                int idx = it * 128 + tid2;
                int c = idx >> 10, r = (idx >> 3) & 127, q = idx & 7;
                const float* src = AiTB + (long)r * SS + kt * 128 + c * 32 + q * 4;
                uint32_t off = (uint32_t)(r * 128 + q * 16);
                uint32_t sw = off ^ ((off >> 3) & 0x70u);
                asm volatile("cp.async.cg.shared.global [%0], [%1], 16;"
                    :: "r"(Bsh + (uint32_t)c * 16384u + sw), "l"(src) : "memory");
            }
            asm volatile("cp.async.commit_group;" ::: "memory");
        }
        asm volatile("cp.async.wait_group 0;" ::: "memory");
        asm volatile("fence.proxy.async.shared::cta;" ::: "memory");
        __syncthreads();

        if (wid == 0 && elect1()) {
#pragma unroll
            for (int c = 0; c < 4; c++) {
                uint64_t da = make_desc(Psh + (uint32_t)c * 16384u);
                uint64_t db = make_desc(Bsh + (uint32_t)c * 16384u);
#pragma unroll
                for (int ks = 0; ks < 4; ks++)
                    mma_tf32(tmem + 128, da + ks * 2, db + ks * 2, IDESC_TF32,
                             (kt > 0 || c > 0 || ks > 0) ? 1u : 0u);
            }
            TC_COMMIT(MB1);
        }
        mbar_wait(MB1, ph1); ph1 ^= 1;

        if (kt < 15) {
            ADP_LOAD256(Bsh, AoutB + (long)(kt + 1) * 128 * AA, AA);
            asm volatile("cp.async.wait_group 0;" ::: "memory");
            asm volatile("fence.proxy.async.shared::cta;" ::: "memory");
            __syncthreads();
        }
    }
#undef ADP_LOAD256

    asm volatile("tcgen05.fence::after_thread_sync;" ::: "memory");
    if (wid < 4) {
        const int r = wid * 32 + lane;
        float* Crow = AdB + (long)(m0 + r) * AA;
#pragma unroll
        for (int cb = 0; cb < 128; cb += 32) {
            uint32_t rg[32];
            LDTM_X32(rg, tmem + 128 + cb);
            asm volatile("tcgen05.wait::ld.sync.aligned;" ::: "memory");
#pragma unroll
            for (int j = 0; j < 32; j += 4) {
                float4 v;
                v.x = rndf(0.1f * __uint_as_float(rg[j + 0]));
                v.y = rndf(0.1f * __uint_as_float(rg[j + 1]));
                v.z = rndf(0.1f * __uint_as_float(rg[j + 2]));
                v.w = rndf(0.1f * __uint_as_float(rg[j + 3]));
                *(float4*)(Crow + cb + j) = v;
            }
        }
    }
    asm volatile("tcgen05.fence::before_thread_sync;" ::: "memory");
    __syncthreads();
    if (wid == 0) {
        asm volatile("tcgen05.dealloc.cta_group::1.sync.aligned.b32 %0, %1;"
                     :: "r"(tmem), "r"(256u));
    }
#else
    for (int r = tid; r < 128; r += 256) {
        float acc[AA];
        for (int a = 0; a < AA; a++) acc[a] = 0.f;
        for (int s = 0; s < SS; s++) {
            float p = 0.f;
            for (int a = 0; a < AA; a++)
                p += AinB[(long)(m0 + r) * AA + a] * AoutB[(long)s * AA + a];
            p = silu_f(fminf(5.f, fmaxf(-5.f, p)));
            for (int a = 0; a < AA; a++)
                acc[a] += p * AinB[(long)s * AA + a];
        }
        for (int a = 0; a < AA; a++)
            AdB[(long)(m0 + r) * AA + a] = rndf(0.1f * acc[a]);
    }
#endif
}

// ============================================================
// Small helpers
// ============================================================
__global__ void zero_kernel(float* p, long n)
{
    long i = (long)blockIdx.x * blockDim.x + threadIdx.x;
    long stride = (long)gridDim.x * blockDim.x;
    for (; i < n; i += stride) p[i] = 0.f;
}

// one float4 per thread, exact grid
__global__ void rnd_kernel(const float* __restrict__ in, float* __restrict__ out, long n)
{
    long j = ((long)blockIdx.x * blockDim.x + threadIdx.x) * 4;
    if (j < n) {
        float4 v = *(const float4*)(in + j);
        v.x = rndf(v.x); v.y = rndf(v.y); v.z = rndf(v.z); v.w = rndf(v.w);
        *(float4*)(out + j) = v;
    }
}
#define RND_GRID(n) ((int)(((n) / 4 + 255) / 256))

__global__ void transpose_kernel(const float* __restrict__ in, float* __restrict__ out,
                                 int R, int C, long sIn, long sOut)
{
    __shared__ float tile[32][33];
    in  += (long)blockIdx.z * sIn;
    out += (long)blockIdx.z * sOut;
    int r0 = blockIdx.y * 32, c0 = blockIdx.x * 32;
    int tx = threadIdx.x, ty = threadIdx.y;
#pragma unroll
    for (int i = 0; i < 32; i += 8)
        tile[ty + i][tx] = in[(long)(r0 + ty + i) * C + c0 + tx];
    __syncthreads();
#pragma unroll
    for (int i = 0; i < 32; i += 8)
        out[(long)(c0 + ty + i) * R + r0 + tx] = rndf(tile[tx][ty + i]);
}

// ============================================================
// Launch
// ============================================================
extern "C" void kernel_launch(void* const* d_in, const int* in_sizes, int n_in,
                              void* d_out, int out_size)
{
    const float* x       = (const float*)d_in[0];
    const float* ew      = (const float*)d_in[1];
    const float* w_up    = (const float*)d_in[2];
    const float* w_gate  = (const float*)d_in[3];
    const float* w_down  = (const float*)d_in[4];
    const float* w_pre   = (const float*)d_in[5];
    const float* w_post  = (const float*)d_in[6];
    const float* an_g    = (const float*)d_in[7];
    const float* an_b    = (const float*)d_in[8];
    const float* w_aproj = (const float*)d_in[9];
    const float* w_exp   = (const float*)d_in[10];
    const float* eln_g   = (const float*)d_in[11];
    const float* eln_b   = (const float*)d_in[12];
    const float* w_eproj = (const float*)d_in[13];
    const float* w_out   = (const float*)d_in[14];
    float* out = (float*)d_out;

    float *Hid, *Pre, *Ain, *Aout, *AiT, *AdaptS,
          *EcompS, *Wcomb, *WcombR, *W2, *W2R, *Tep, *Tap,
          *xR, *WgR, *WuR, *WdR, *WoutR, *WpreR, *WpostR, *WexpR;
    cudaGetSymbolAddress((void**)&Hid,    g_Hid);
    cudaGetSymbolAddress((void**)&Pre,    g_Pre);
    cudaGetSymbolAddress((void**)&Ain,    g_Ain);
    cudaGetSymbolAddress((void**)&Aout,   g_Aout);
    cudaGetSymbolAddress((void**)&AiT,    g_AiT);
    cudaGetSymbolAddress((void**)&AdaptS, g_AdaptS);
    cudaGetSymbolAddress((void**)&EcompS, g_EcompS);
    cudaGetSymbolAddress((void**)&Wcomb,  g_Wcomb);
    cudaGetSymbolAddress((void**)&WcombR, g_WcombR);
    cudaGetSymbolAddress((void**)&W2,     g_W2);
    cudaGetSymbolAddress((void**)&W2R,    g_W2R);
    cudaGetSymbolAddress((void**)&Tep,    g_Tep);
    cudaGetSymbolAddress((void**)&Tap,    g_Tap);
    cudaGetSymbolAddress((void**)&xR,     g_xR);
    cudaGetSymbolAddress((void**)&WgR,    g_WgR);
    cudaGetSymbolAddress((void**)&WuR,    g_WuR);
    cudaGetSymbolAddress((void**)&WdR,    g_WdR);
    cudaGetSymbolAddress((void**)&WoutR,  g_WoutR);
    cudaGetSymbolAddress((void**)&WpreR,  g_WpreR);
    cudaGetSymbolAddress((void**)&WpostR, g_WpostR);
    cudaGetSymbolAddress((void**)&WexpR,  g_WexpR);

    cudaFuncSetAttribute(tc_gemm,   cudaFuncAttributeMaxDynamicSharedMemorySize, TCG_SMEM);
    cudaFuncSetAttribute(tc_preln,  cudaFuncAttributeMaxDynamicSharedMemorySize, TCG_SMEM);
    cudaFuncSetAttribute(tc_eall,   cudaFuncAttributeMaxDynamicSharedMemorySize, TCG_SMEM);
    cudaFuncSetAttribute(tc_out,    cudaFuncAttributeMaxDynamicSharedMemorySize, TCG_SMEM);
    cudaFuncSetAttribute(tc_swiglu, cudaFuncAttributeMaxDynamicSharedMemorySize, SWI_SMEM);
    cudaFuncSetAttribute(tc_adapt,  cudaFuncAttributeMaxDynamicSharedMemorySize, ADP_SMEM);

    dim3 tb32(32, 8);

    // ---- round raw inputs to tf32 once ----
    rnd_kernel<<<RND_GRID((long)MM * DD), 256>>>(x,      xR,     (long)MM * DD);
    rnd_kernel<<<RND_GRID((long)HH * DD), 256>>>(w_gate, WgR,    (long)HH * DD);
    rnd_kernel<<<RND_GRID((long)HH * DD), 256>>>(w_up,   WuR,    (long)HH * DD);
    rnd_kernel<<<RND_GRID((long)DD * HH), 256>>>(w_down, WdR,    (long)DD * HH);
    rnd_kernel<<<RND_GRID((long)DD * HH), 256>>>(w_out,  WoutR,  (long)DD * HH);
    rnd_kernel<<<RND_GRID((long)AA * DD), 256>>>(w_pre,  WpreR,  (long)AA * DD);
    rnd_kernel<<<RND_GRID((long)AA * HH), 256>>>(w_post, WpostR, (long)AA * HH);
    rnd_kernel<<<RND_GRID((long)EE * AA * AA), 256>>>(w_exp, WexpR, (long)EE * AA * AA);

    // ---- zero atomic / sparse-write targets ----
    zero_kernel<<<64,   256>>>(Wcomb,  (long)DD * AA);
    zero_kernel<<<64,   256>>>(W2,     (long)DD * AA);
    zero_kernel<<<2048, 256>>>(EcompS, (long)MM * AA);

    // ---- weight-only precomputes (split-K 16, atomic) ----
    transpose_kernel<<<dim3(AA / 32, HH / 32, 1), tb32>>>(w_eproj, Tep, HH, AA, 0, 0);
    transpose_kernel<<<dim3(AA / 32, HH / 32, 1), tb32>>>(w_aproj, Tap, HH, AA, 0, 0);
    tc_gemm<<<dim3(1, DD / 128, 16), 256, TCG_SMEM>>>(WoutR, Tep, Wcomb, nullptr,
                                                      DD, AA, HH, 0, 0, 0, 1.f, 4, 16, 0);
    tc_gemm<<<dim3(1, DD / 128, 16), 256, TCG_SMEM>>>(WdR, Tap, W2, nullptr,
                                                      DD, AA, HH, 0, 0, 0, 1.f, 4, 16, 0);
    rnd_kernel<<<RND_GRID((long)DD * AA), 256>>>(Wcomb, WcombR, (long)DD * AA);
    rnd_kernel<<<RND_GRID((long)DD * AA), 256>>>(W2,    W2R,    (long)DD * AA);

    // ---- fused gate+up+SwiGLU -> Hid ----
    tc_swiglu<<<dim3(HH / 128, MM / 128, 1), 256, SWI_SMEM>>>(xR, WgR, WuR, Hid, DD);

    // ---- pre GEMM + LN + transpose fused: Pre, Ain, AiT in one pass ----
    tc_preln<<<dim3(1, MM / 128, 1), 256, TCG_SMEM>>>(xR, WpreR, Ain, Pre, AiT,
                                                      an_g, an_b, DD);

    // ---- post GEMM + LN fused: Aout ----
    tc_preln<<<dim3(1, MM / 128, 1), 256, TCG_SMEM>>>(Hid, WpostR, Aout, nullptr, nullptr,
                                                      an_g, an_b, HH);

    // ---- fused adapt attention -> AdaptS (pre-scaled 0.1) ----
    tc_adapt<<<dim3(SS / 128, BB, 1), 256, ADP_SMEM>>>(Ain, Aout, AiT, AdaptS);

    // ---- experts: GEMM + select + LN fused -> EcompS (pre-scaled 0.1) ----
    tc_eall<<<dim3(EE, MM / 128, 1), 256, TCG_SMEM>>>(Pre, WexpR, ew, eln_g, eln_b, EcompS);

    // ---- single-pass output: out = Hid@WdR^T + AdaptS@W2R^T + EcompS@WcombR^T ----
    tc_out<<<dim3(DD / 128, MM / 128, 1), 256, TCG_SMEM>>>(Hid, WdR, AdaptS, W2R,
                                                           EcompS, WcombR, out);
}

// round 16
// speedup vs baseline: 1.6752x; 1.1956x over previous
#include <cuda_runtime.h>
#include <cuda_bf16.h>
#include <cstdint>

// Problem dims (fixed)
#define BB 8
#define SS 2048
#define DD 1024
#define HH 2048
#define AA 128
#define EE 8
#define MM (BB*SS)   // 16384 tokens

// tcgen05 is arch-SPECIFIC (sm_103a). Only use it in an arch-specific pass.
#if defined(__CUDA_ARCH_FEAT_SM103_ALL)
#define TCPATH 1
#endif

// -------- scratch (device globals; no allocation allowed) --------
__device__ float g_Hid[MM*HH];         // hidden0 = silu(gate)*up (tf32-rounded)
__device__ float g_Pre[MM*AA];         // rounded (feeds Eall GEMM)
__device__ float g_Ain[MM*AA];         // LN(pre), rounded
__device__ float g_Aout[MM*AA];        // LN(post), rounded
__device__ float g_AiT[BB*AA*SS];      // adapt_in transposed per batch [A,S], rounded
__device__ float g_AdaptS[MM*AA];      // fused adapt output, PRE-SCALED by 0.1, rounded
__device__ float g_EcompS[MM*AA];      // selected+LN'd expert act, PRE-SCALED 0.1, rounded
__device__ float g_Wcomb[DD*AA];       // w_out @ w_eproj (exact, atomic)
__device__ float g_WcombR[DD*AA];      // rounded
__device__ float g_W2[DD*AA];          // w_down @ w_aproj (exact, atomic)
__device__ float g_W2R[DD*AA];         // rounded
__device__ float g_Tep[AA*HH];         // w_eproj^T, rounded
__device__ float g_Tap[AA*HH];         // w_aproj^T, rounded
// rounded raw inputs
__device__ float g_xR[MM*DD];
__device__ float g_WgR[HH*DD];
__device__ float g_WuR[HH*DD];
__device__ float g_WdR[DD*HH];
__device__ float g_WoutR[DD*HH];
__device__ float g_WpreR[AA*DD];
__device__ float g_WpostR[AA*HH];
__device__ float g_WexpR[EE*AA*AA];

// ============================================================
// common helpers
// ============================================================
__device__ __forceinline__ float silu_f(float v) {
    return v * __frcp_rn(1.f + __expf(-v));
}

__device__ __forceinline__ uint32_t f2tf32(float f) {
    uint32_t u;
    asm("cvt.rna.tf32.f32 %0, %1;" : "=r"(u) : "f"(f));
    return u;
}
__device__ __forceinline__ float rndf(float f) {
    return __uint_as_float(f2tf32(f));
}

#ifdef TCPATH
// ============================================================
// tcgen05 helpers (sm_103a-specific pass only)
// ============================================================
__device__ __forceinline__ uint32_t smem_u32(const void* p) {
    uint32_t a;
    asm("{ .reg .u64 t; cvta.to.shared.u64 t, %1; cvt.u32.u64 %0, t; }"
        : "=r"(a) : "l"(p));
    return a;
}

__device__ __forceinline__ uint32_t elect1() {
    uint32_t p;
    asm volatile("{\n\t.reg .pred p;\n\telect.sync _|p, 0xFFFFFFFF;\n\t"
                 "selp.b32 %0, 1, 0, p;\n\t}" : "=r"(p));
    return p;
}

#define MBAR_INIT(addr, cnt) \
    asm volatile("mbarrier.init.shared.b64 [%0], %1;" :: "r"(addr), "r"(cnt) : "memory")

__device__ __forceinline__ void mbar_wait(uint32_t mbar, uint32_t parity) {
    uint32_t done;
    asm volatile("{\n\t.reg .pred p;\n\t"
                 "mbarrier.try_wait.parity.acquire.cta.shared::cta.b64 p, [%1], %2;\n\t"
                 "selp.b32 %0, 1, 0, p;\n\t}"
                 : "=r"(done) : "r"(mbar), "r"(parity) : "memory");
    while (!done) {
        asm volatile("{\n\t.reg .pred p;\n\t"
                     "mbarrier.try_wait.parity.acquire.cta.shared::cta.b64 p, [%1], %2, 0x989680;\n\t"
                     "selp.b32 %0, 1, 0, p;\n\t}"
                     : "=r"(done) : "r"(mbar), "r"(parity) : "memory");
    }
}

__device__ __forceinline__ void mma_tf32(uint32_t d, uint64_t da, uint64_t db,
                                         uint32_t idesc, uint32_t en) {
    asm volatile(
        "{\n\t.reg .pred p;\n\tsetp.ne.u32 p, %4, 0;\n\t"
        "tcgen05.mma.cta_group::1.kind::tf32 [%0], %1, %2, %3, {%5, %5, %5, %5}, p;\n\t}"
        :: "r"(d), "l"(da), "l"(db), "r"(idesc), "r"(en), "r"(0u)
        : "memory");
}

#define TC_COMMIT(mbar) \
    asm volatile("tcgen05.commit.cta_group::1.mbarrier::arrive::one.shared::cluster.b64 [%0];" \
                 :: "r"(mbar) : "memory")

#define LDTM_X32(r, addr) \
    asm volatile("tcgen05.ld.sync.aligned.32x32b.x32.b32 " \
        "{%0,%1,%2,%3,%4,%5,%6,%7,%8,%9,%10,%11,%12,%13,%14,%15," \
        "%16,%17,%18,%19,%20,%21,%22,%23,%24,%25,%26,%27,%28,%29,%30,%31}, [%32];" \
        : "=r"((r)[0]),  "=r"((r)[1]),  "=r"((r)[2]),  "=r"((r)[3]), \
          "=r"((r)[4]),  "=r"((r)[5]),  "=r"((r)[6]),  "=r"((r)[7]), \
          "=r"((r)[8]),  "=r"((r)[9]),  "=r"((r)[10]), "=r"((r)[11]), \
          "=r"((r)[12]), "=r"((r)[13]), "=r"((r)[14]), "=r"((r)[15]), \
          "=r"((r)[16]), "=r"((r)[17]), "=r"((r)[18]), "=r"((r)[19]), \
          "=r"((r)[20]), "=r"((r)[21]), "=r"((r)[22]), "=r"((r)[23]), \
          "=r"((r)[24]), "=r"((r)[25]), "=r"((r)[26]), "=r"((r)[27]), \
          "=r"((r)[28]), "=r"((r)[29]), "=r"((r)[30]), "=r"((r)[31]) \
        : "r"(addr))

static __device__ __forceinline__ uint64_t make_desc(uint32_t addr) {
    const uint64_t base = (2ULL << 61) | (1ULL << 46) | (64ULL << 32) | (1ULL << 16);
    return base | ((uint64_t)(addr >> 4) & 0x3FFF);
}

// idesc: dtype=F32(1<<4), atype=btype=TF32(2), N=128 ((N/8)<<17), M=128 ((M/16)<<24)
#define IDESC_TF32 ((1u << 4) | (2u << 7) | (2u << 10) | (16u << 17) | (8u << 24))

// Shared mainloop: stages A/B 128x32 chunks via 3-buffer cp.async pipe and
// issues MMAs into tmem (cols 0-127). Requires nch >= 4.
#define TC_MAINLOOP(Ap, Bp, ldA, nch, data0, tmem, MB0, MB1, MB2)            \
    int ph0 = 0, ph1 = 0, ph2 = 0;                                           \
    {                                                                        \
    __extension__ auto issue_cp = [&](int c, int b) {                        \
        const int k0_ = c << 5;                                              \
        const uint32_t so_ = (uint32_t)b * 32768u;                           \
        _Pragma("unroll")                                                    \
        for (int it_ = 0; it_ < 8; it_++) {                                  \
            int idx_ = it_ * 256 + tid;                                      \
            int r_ = idx_ >> 3, q_ = idx_ & 7;                               \
            const float* src_ = (r_ < 128)                                   \
                ? ((Ap) + (long)r_ * (ldA) + k0_ + q_ * 4)                   \
                : ((Bp) + (long)(r_ - 128) * (ldA) + k0_ + q_ * 4);          \
            uint32_t off_ = (uint32_t)(r_ * 128 + q_ * 16);                  \
            uint32_t sw_ = off_ ^ ((off_ >> 3) & 0x70u);                     \
            asm volatile("cp.async.cg.shared.global [%0], [%1], 16;"         \
                :: "r"((data0) + so_ + sw_), "l"(src_) : "memory");          \
        }                                                                    \
        asm volatile("cp.async.commit_group;" ::: "memory");                 \
    };                                                                       \
    issue_cp(0, 0);                                                          \
    issue_cp(1, 1);                                                          \
    for (int i = 0; i < (nch); i++) {                                        \
        const int ip2 = i + 2;                                               \
        if (ip2 < (nch)) {                                                   \
            const int b = ip2 % 3;                                           \
            if (i >= 1) {                                                    \
                if (b == 0)      { mbar_wait(MB0, ph0); ph0 ^= 1; }          \
                else if (b == 1) { mbar_wait(MB1, ph1); ph1 ^= 1; }          \
                else             { mbar_wait(MB2, ph2); ph2 ^= 1; }          \
            }                                                                \
            issue_cp(ip2, b);                                                \
        }                                                                    \
        if (ip2 < (nch))          asm volatile("cp.async.wait_group 2;" ::: "memory"); \
        else if (i + 1 < (nch))   asm volatile("cp.async.wait_group 1;" ::: "memory"); \
        else                      asm volatile("cp.async.wait_group 0;" ::: "memory"); \
        asm volatile("fence.proxy.async.shared::cta;" ::: "memory");         \
        __syncthreads();                                                     \
        if (wid == 0 && elect1()) {                                          \
            const int bi = i % 3;                                            \
            uint64_t da = make_desc((data0) + (uint32_t)bi * 32768u);        \
            uint64_t db = make_desc((data0) + (uint32_t)bi * 32768u + 16384u); \
            _Pragma("unroll")                                                \
            for (int ks = 0; ks < 4; ks++)                                   \
                mma_tf32(tmem, da + ks * 2, db + ks * 2, IDESC_TF32,         \
                         (i > 0 || ks > 0) ? 1u : 0u);                       \
            if (bi == 0)      TC_COMMIT(MB0);                                \
            else if (bi == 1) TC_COMMIT(MB1);                                \
            else              TC_COMMIT(MB2);                                \
        }                                                                    \
    }                                                                        \
    }                                                                        \
    mbar_wait(MB0, ph0);                                                     \
    mbar_wait(MB1, ph1);                                                     \
    mbar_wait(MB2, ph2);                                                     \
    asm volatile("tcgen05.fence::after_thread_sync;" ::: "memory");
#endif  // TCPATH

// ============================================================
// tc_gemm: 128x128 tile (validated path)
// ============================================================
#define TCG_SMEM (2048 + 3 * 32768)   // 100352

__global__ __launch_bounds__(256)
void tc_gemm(const float* __restrict__ A, const float* __restrict__ B,
             float* __restrict__ C, const float* __restrict__ G,
             int M, int N, int K, long sA, long sB, long sC,
             float alpha, int mode, int ksplit, int rnd)
{
    extern __shared__ char smem[];
    const int tid  = threadIdx.x;
    const int wid  = tid >> 5;
    const int lane = tid & 31;

    int Kc;
    {
        int bz = blockIdx.z;
        long b = bz / ksplit;
        int ik = bz - (int)b * ksplit;
        Kc = K / ksplit;
        A += b * sA + (long)ik * Kc;
        B += b * sB + (long)ik * Kc;
        C += b * sC;
        if (mode == 3) G += b * sC;
    }
    const int m0 = blockIdx.y * 128, n0 = blockIdx.x * 128;
    const float* Ap = A + (long)m0 * K;
    const float* Bp = B + (long)n0 * K;
    const int nch = Kc >> 5;

#ifdef TCPATH
    uint32_t sbase = smem_u32(smem);
    const uint32_t TM_PTR = sbase;
    const uint32_t MB0 = sbase + 16;
    const uint32_t MB1 = sbase + 24;
    const uint32_t MB2 = sbase + 32;
    uint32_t data0 = (sbase + 1024 + 1023) & ~1023u;

    if (wid == 0) {
        asm volatile("tcgen05.alloc.cta_group::1.sync.aligned.shared::cta.b32 [%0], %1;"
                     :: "r"(TM_PTR), "r"(128u) : "memory");
        asm volatile("tcgen05.relinquish_alloc_permit.cta_group::1.sync.aligned;");
    }
    if (tid == 0) { MBAR_INIT(MB0, 1); MBAR_INIT(MB1, 1); MBAR_INIT(MB2, 1); }
    __syncthreads();
    uint32_t tmem;
    asm volatile("ld.shared.b32 %0, [%1];" : "=r"(tmem) : "r"(TM_PTR));

    TC_MAINLOOP(Ap, Bp, K, nch, data0, tmem, MB0, MB1, MB2);

    if (wid < 4) {
        float* Crow = C + (long)(m0 + wid * 32 + lane) * N + n0;
        const float* Grow = (mode == 3)
            ? (G + (long)(m0 + wid * 32 + lane) * N + n0) : nullptr;
#pragma unroll
        for (int cb = 0; cb < 128; cb += 32) {
            uint32_t r[32];
            LDTM_X32(r, tmem + cb);
            asm volatile("tcgen05.wait::ld.sync.aligned;" ::: "memory");
            if (mode == 4) {
#pragma unroll
                for (int j = 0; j < 32; j++)
                    atomicAdd(Crow + cb + j, alpha * __uint_as_float(r[j]));
            } else {
#pragma unroll
                for (int j = 0; j < 32; j += 4) {
                    float4 v;
                    v.x = __uint_as_float(r[j + 0]);
                    v.y = __uint_as_float(r[j + 1]);
                    v.z = __uint_as_float(r[j + 2]);
                    v.w = __uint_as_float(r[j + 3]);
                    if (mode == 0) {
                        v.x *= alpha; v.y *= alpha; v.z *= alpha; v.w *= alpha;
                    } else if (mode == 1) {
                        float4 c = *(const float4*)(Crow + cb + j);
                        v.x = fmaf(alpha, v.x, c.x); v.y = fmaf(alpha, v.y, c.y);
                        v.z = fmaf(alpha, v.z, c.z); v.w = fmaf(alpha, v.w, c.w);
                    } else if (mode == 2) {
                        v.x = silu_f(fminf(5.f, fmaxf(-5.f, v.x)));
                        v.y = silu_f(fminf(5.f, fmaxf(-5.f, v.y)));
                        v.z = silu_f(fminf(5.f, fmaxf(-5.f, v.z)));
                        v.w = silu_f(fminf(5.f, fmaxf(-5.f, v.w)));
                    } else {
                        float4 g = *(const float4*)(Grow + cb + j);
                        v.x *= silu_f(g.x); v.y *= silu_f(g.y);
                        v.z *= silu_f(g.z); v.w *= silu_f(g.w);
                    }
                    if (rnd) {
                        v.x = rndf(v.x); v.y = rndf(v.y);
                        v.z = rndf(v.z); v.w = rndf(v.w);
                    }
                    *(float4*)(Crow + cb + j) = v;
                }
            }
        }
    }
    asm volatile("tcgen05.fence::before_thread_sync;" ::: "memory");
    __syncthreads();
    if (wid == 0) {
        asm volatile("tcgen05.dealloc.cta_group::1.sync.aligned.b32 %0, %1;"
                     :: "r"(tmem), "r"(128u));
    }
#else
    for (int idx = tid; idx < 128 * 128; idx += 256) {
        int rr = idx >> 7, cc = idx & 127;
        long ci = (long)(m0 + rr) * N + n0 + cc;
        float acc = 0.f;
        for (int k = 0; k < Kc; k++)
            acc += A[(long)(m0 + rr) * K + k] * B[(long)(n0 + cc) * K + k];
        float v;
        if (mode == 4) { atomicAdd(C + ci, alpha * acc); continue; }
        else if (mode == 0) v = alpha * acc;
        else if (mode == 1) v = fmaf(alpha, acc, C[ci]);
        else if (mode == 2) v = silu_f(fminf(5.f, fmaxf(-5.f, acc)));
        else                v = silu_f(G[ci]) * acc;
        if (rnd) v = rndf(v);
        C[ci] = v;
    }
#endif
}

// ============================================================
// tc_preln: GEMM (M x 128, grid=(1, M/128)) + LN epilogue (validated R14).
// ============================================================
__global__ __launch_bounds__(256)
void tc_preln(const float* __restrict__ A, const float* __restrict__ B,
              float* __restrict__ OutLN, float* __restrict__ PreOut,
              float* __restrict__ TOut,
              const float* __restrict__ lg, const float* __restrict__ lb,
              int K)
{
    extern __shared__ char smem[];
    const int tid  = threadIdx.x;
    const int wid  = tid >> 5;
    const int lane = tid & 31;
    const int m0 = blockIdx.y * 128;
    const float* Ap = A + (long)m0 * K;
    const float* Bp = B;
    const int nch = K >> 5;

#ifdef TCPATH
    uint32_t sbase = smem_u32(smem);
    const uint32_t TM_PTR = sbase;
    const uint32_t MB0 = sbase + 16;
    const uint32_t MB1 = sbase + 24;
    const uint32_t MB2 = sbase + 32;
    uint32_t data0 = (sbase + 1024 + 1023) & ~1023u;

    if (wid == 0) {
        asm volatile("tcgen05.alloc.cta_group::1.sync.aligned.shared::cta.b32 [%0], %1;"
                     :: "r"(TM_PTR), "r"(128u) : "memory");
        asm volatile("tcgen05.relinquish_alloc_permit.cta_group::1.sync.aligned;");
    }
    if (tid == 0) { MBAR_INIT(MB0, 1); MBAR_INIT(MB1, 1); MBAR_INIT(MB2, 1); }
    __syncthreads();
    uint32_t tmem;
    asm volatile("ld.shared.b32 %0, [%1];" : "=r"(tmem) : "r"(TM_PTR));

    TC_MAINLOOP(Ap, Bp, K, nch, data0, tmem, MB0, MB1, MB2);

    if (wid < 4) {
        const int rl = wid * 32 + lane;
        const long rg = m0 + rl;
        float s = 0.f, s2 = 0.f;
#pragma unroll
        for (int cb = 0; cb < 128; cb += 32) {
            uint32_t r[32];
            LDTM_X32(r, tmem + cb);
            asm volatile("tcgen05.wait::ld.sync.aligned;" ::: "memory");
#pragma unroll
            for (int j = 0; j < 32; j++) {
                float v = rndf(__uint_as_float(r[j]));
                s += v; s2 += v * v;
            }
        }
        float mean = s * (1.f / 128.f);
        float var  = s2 * (1.f / 128.f) - mean * mean;
        float inv  = rsqrtf(var + 1e-5f);
        int bb = (int)(rg / SS);
        long ss = rg - (long)bb * SS;
        float* Trow = TOut ? (TOut + (long)bb * AA * SS + ss) : nullptr;
#pragma unroll
        for (int cb = 0; cb < 128; cb += 32) {
            uint32_t r[32];
            LDTM_X32(r, tmem + cb);
            asm volatile("tcgen05.wait::ld.sync.aligned;" ::: "memory");
#pragma unroll
            for (int j = 0; j < 32; j += 4) {
                int c = cb + j;
                float4 v;
                v.x = rndf(__uint_as_float(r[j + 0]));
                v.y = rndf(__uint_as_float(r[j + 1]));
                v.z = rndf(__uint_as_float(r[j + 2]));
                v.w = rndf(__uint_as_float(r[j + 3]));
                if (PreOut) *(float4*)(PreOut + rg * 128 + c) = v;
                float4 o;
                o.x = rndf((v.x - mean) * inv * lg[c + 0] + lb[c + 0]);
                o.y = rndf((v.y - mean) * inv * lg[c + 1] + lb[c + 1]);
                o.z = rndf((v.z - mean) * inv * lg[c + 2] + lb[c + 2]);
                o.w = rndf((v.w - mean) * inv * lg[c + 3] + lb[c + 3]);
                *(float4*)(OutLN + rg * 128 + c) = o;
                if (Trow) {
                    Trow[(long)(c + 0) * SS] = o.x;
                    Trow[(long)(c + 1) * SS] = o.y;
                    Trow[(long)(c + 2) * SS] = o.z;
                    Trow[(long)(c + 3) * SS] = o.w;
                }
            }
        }
    }
    asm volatile("tcgen05.fence::before_thread_sync;" ::: "memory");
    __syncthreads();
    if (wid == 0) {
        asm volatile("tcgen05.dealloc.cta_group::1.sync.aligned.b32 %0, %1;"
                     :: "r"(tmem), "r"(128u));
    }
#else
    for (int rl = tid; rl < 128; rl += 256) {
        long rg = m0 + rl;
        float row[128];
        float s = 0.f, s2 = 0.f;
        for (int c = 0; c < 128; c++) {
            float acc = 0.f;
            for (int k = 0; k < K; k++)
                acc += A[rg * K + k] * B[(long)c * K + k];
            row[c] = rndf(acc);
            s += row[c]; s2 += row[c] * row[c];
        }
        float mean = s / 128.f, var = s2 / 128.f - mean * mean;
        float inv = rsqrtf(var + 1e-5f);
        int bb = (int)(rg / SS); long ss = rg - (long)bb * SS;
        for (int c = 0; c < 128; c++) {
            if (PreOut) PreOut[rg * 128 + c] = row[c];
            float o = rndf((row[c] - mean) * inv * lg[c] + lb[c]);
            OutLN[rg * 128 + c] = o;
            if (TOut) TOut[(long)bb * AA * SS + (long)c * SS + ss] = o;
        }
    }
#endif
}

// ============================================================
// tc_eall: experts GEMM + fused select/LN epilogue (R14) + zero-fill:
// expert-0 block also writes zeros for rows with no selected expert,
// so EcompS needs no separate zeroing pass.
// ============================================================
__global__ __launch_bounds__(256)
void tc_eall(const float* __restrict__ A, const float* __restrict__ B,
             const float* __restrict__ ew,
             const float* __restrict__ eg, const float* __restrict__ eb,
             float* __restrict__ EcompS)
{
    extern __shared__ char smem[];
    const int tid  = threadIdx.x;
    const int wid  = tid >> 5;
    const int lane = tid & 31;
    const int e  = blockIdx.x;
    const int m0 = blockIdx.y * 128;
    const float* Ap = A + (long)m0 * AA;
    const float* Bp = B + (long)e * 128 * AA;
    const int nch = AA >> 5;   // 4

#ifdef TCPATH
    uint32_t sbase = smem_u32(smem);
    const uint32_t TM_PTR = sbase;
    const uint32_t MB0 = sbase + 16;
    const uint32_t MB1 = sbase + 24;
    const uint32_t MB2 = sbase + 32;
    uint32_t data0 = (sbase + 1024 + 1023) & ~1023u;

    if (wid == 0) {
        asm volatile("tcgen05.alloc.cta_group::1.sync.aligned.shared::cta.b32 [%0], %1;"
                     :: "r"(TM_PTR), "r"(128u) : "memory");
        asm volatile("tcgen05.relinquish_alloc_permit.cta_group::1.sync.aligned;");
    }
    if (tid == 0) { MBAR_INIT(MB0, 1); MBAR_INIT(MB1, 1); MBAR_INIT(MB2, 1); }
    __syncthreads();
    uint32_t tmem;
    asm volatile("ld.shared.b32 %0, [%1];" : "=r"(tmem) : "r"(TM_PTR));

    TC_MAINLOOP(Ap, Bp, AA, nch, data0, tmem, MB0, MB1, MB2);

    if (wid < 4) {
        const int rl = wid * 32 + lane;
        const long rg = m0 + rl;
        int idx = -1;
        const float* w = ew + rg * EE;
#pragma unroll
        for (int i = 0; i < EE; i++) if (w[i] > 0.f) idx = i;
        const bool sel  = (idx == e);
        const bool zfill = (e == 0 && idx < 0);
        float s = 0.f, s2 = 0.f;
#pragma unroll
        for (int cb = 0; cb < 128; cb += 32) {
            uint32_t r[32];
            LDTM_X32(r, tmem + cb);
            asm volatile("tcgen05.wait::ld.sync.aligned;" ::: "memory");
#pragma unroll
            for (int j = 0; j < 32; j++) {
                float v = __uint_as_float(r[j]);
                s += v; s2 += v * v;
            }
        }
        float mean = s * (1.f / 128.f);
        float var  = s2 * (1.f / 128.f) - mean * mean;
        float inv  = rsqrtf(var + 1e-5f);
#pragma unroll
        for (int cb = 0; cb < 128; cb += 32) {
            uint32_t r[32];
            LDTM_X32(r, tmem + cb);
            asm volatile("tcgen05.wait::ld.sync.aligned;" ::: "memory");
            if (sel) {
#pragma unroll
                for (int j = 0; j < 32; j += 4) {
                    int c = cb + j;
                    float4 o;
                    o.x = rndf(0.1f * ((__uint_as_float(r[j + 0]) - mean) * inv
                               * eg[e * AA + c + 0] + eb[e * AA + c + 0]));
                    o.y = rndf(0.1f * ((__uint_as_float(r[j + 1]) - mean) * inv
                               * eg[e * AA + c + 1] + eb[e * AA + c + 1]));
                    o.z = rndf(0.1f * ((__uint_as_float(r[j + 2]) - mean) * inv
                               * eg[e * AA + c + 2] + eb[e * AA + c + 2]));
                    o.w = rndf(0.1f * ((__uint_as_float(r[j + 3]) - mean) * inv
                               * eg[e * AA + c + 3] + eb[e * AA + c + 3]));
                    *(float4*)(EcompS + rg * 128 + c) = o;
                }
            } else if (zfill) {
                float4 z = make_float4(0.f, 0.f, 0.f, 0.f);
#pragma unroll
                for (int j = 0; j < 32; j += 4)
                    *(float4*)(EcompS + rg * 128 + cb + j) = z;
            }
        }
    }
    asm volatile("tcgen05.fence::before_thread_sync;" ::: "memory");
    __syncthreads();
    if (wid == 0) {
        asm volatile("tcgen05.dealloc.cta_group::1.sync.aligned.b32 %0, %1;"
                     :: "r"(tmem), "r"(128u));
    }
#else
    for (int rl = tid; rl < 128; rl += 256) {
        long rg = m0 + rl;
        int idx = -1;
        for (int i = 0; i < EE; i++) if (ew[rg * EE + i] > 0.f) idx = i;
        if (idx < 0 && e == 0) {
            for (int c = 0; c < 128; c++) EcompS[rg * 128 + c] = 0.f;
            continue;
        }
        if (idx != e) continue;
        float row[128];
        float s = 0.f, s2 = 0.f;
        for (int c = 0; c < 128; c++) {
            float acc = 0.f;
            for (int k = 0; k < AA; k++)
                acc += A[rg * AA + k] * B[((long)e * 128 + c) * AA + k];
            row[c] = acc; s += acc; s2 += acc * acc;
        }
        float mean = s / 128.f, var = s2 / 128.f - mean * mean;
        float inv = rsqrtf(var + 1e-5f);
        for (int c = 0; c < 128; c++)
            EcompS[rg * 128 + c] = rndf(0.1f * ((row[c] - mean) * inv
                                   * eg[e * AA + c] + eb[e * AA + c]));
    }
#endif
}

// ============================================================
// tc_out: single-pass output GEMM (validated R13 path, unchanged)
// ============================================================
__global__ __launch_bounds__(256)
void tc_out(const float* __restrict__ Hid, const float* __restrict__ WdR,
            const float* __restrict__ AdS, const float* __restrict__ W2R,
            const float* __restrict__ EcS, const float* __restrict__ WcR,
            float* __restrict__ C)
{
    extern __shared__ char smem[];
    const int tid  = threadIdx.x;
    const int wid  = tid >> 5;
    const int lane = tid & 31;
    const int m0 = blockIdx.y * 128, n0 = blockIdx.x * 128;
    const int N = DD;
    const int nch = 72;

#ifdef TCPATH
    uint32_t sbase = smem_u32(smem);
    const uint32_t TM_PTR = sbase;
    const uint32_t MB0 = sbase + 16;
    const uint32_t MB1 = sbase + 24;
    const uint32_t MB2 = sbase + 32;
    uint32_t data0 = (sbase + 1024 + 1023) & ~1023u;

    if (wid == 0) {
        asm volatile("tcgen05.alloc.cta_group::1.sync.aligned.shared::cta.b32 [%0], %1;"
                     :: "r"(TM_PTR), "r"(128u) : "memory");
        asm volatile("tcgen05.relinquish_alloc_permit.cta_group::1.sync.aligned;");
    }
    if (tid == 0) { MBAR_INIT(MB0, 1); MBAR_INIT(MB1, 1); MBAR_INIT(MB2, 1); }
    __syncthreads();
    uint32_t tmem;
    asm volatile("ld.shared.b32 %0, [%1];" : "=r"(tmem) : "r"(TM_PTR));

#define OUT_CP(c, b) do {                                                    \
        const float* aB_; const float* bB_; int ldA_, k0_;                   \
        if ((c) < 64)      { aB_ = Hid + (long)m0 * HH; bB_ = WdR + (long)n0 * HH; \
                             ldA_ = HH; k0_ = (c) << 5; }                    \
        else if ((c) < 68) { aB_ = AdS + (long)m0 * AA; bB_ = W2R + (long)n0 * AA; \
                             ldA_ = AA; k0_ = ((c) - 64) << 5; }             \
        else               { aB_ = EcS + (long)m0 * AA; bB_ = WcR + (long)n0 * AA; \
                             ldA_ = AA; k0_ = ((c) - 68) << 5; }             \
        const uint32_t so_ = (uint32_t)(b) * 32768u;                         \
        _Pragma("unroll")                                                    \
        for (int it_ = 0; it_ < 8; it_++) {                                  \
            int idx_ = it_ * 256 + tid;                                      \
            int r_ = idx_ >> 3, q_ = idx_ & 7;                               \
            const float* src_ = (r_ < 128)                                   \
                ? (aB_ + (long)r_ * ldA_ + k0_ + q_ * 4)                     \
                : (bB_ + (long)(r_ - 128) * ldA_ + k0_ + q_ * 4);            \
            uint32_t off_ = (uint32_t)(r_ * 128 + q_ * 16);                  \
            uint32_t sw_ = off_ ^ ((off_ >> 3) & 0x70u);                     \
            asm volatile("cp.async.cg.shared.global [%0], [%1], 16;"         \
                :: "r"(data0 + so_ + sw_), "l"(src_) : "memory");            \
        }                                                                    \
        asm volatile("cp.async.commit_group;" ::: "memory");                 \
    } while (0)

    int ph0 = 0, ph1 = 0, ph2 = 0;
    OUT_CP(0, 0);
    OUT_CP(1, 1);

    for (int i = 0; i < nch; i++) {
        const int ip2 = i + 2;
        if (ip2 < nch) {
            const int b = ip2 % 3;
            if (i >= 1) {
                if (b == 0)      { mbar_wait(MB0, ph0); ph0 ^= 1; }
                else if (b == 1) { mbar_wait(MB1, ph1); ph1 ^= 1; }
                else             { mbar_wait(MB2, ph2); ph2 ^= 1; }
            }
            OUT_CP(ip2, b);
        }
        if (ip2 < nch)          asm volatile("cp.async.wait_group 2;" ::: "memory");
        else if (i + 1 < nch)   asm volatile("cp.async.wait_group 1;" ::: "memory");
        else                    asm volatile("cp.async.wait_group 0;" ::: "memory");
        asm volatile("fence.proxy.async.shared::cta;" ::: "memory");
        __syncthreads();
        if (wid == 0 && elect1()) {
            const int bi = i % 3;
            uint64_t da = make_desc(data0 + (uint32_t)bi * 32768u);
            uint64_t db = make_desc(data0 + (uint32_t)bi * 32768u + 16384u);
#pragma unroll
            for (int ks = 0; ks < 4; ks++)
                mma_tf32(tmem, da + ks * 2, db + ks * 2, IDESC_TF32,
                         (i > 0 || ks > 0) ? 1u : 0u);
            if (bi == 0)      TC_COMMIT(MB0);
            else if (bi == 1) TC_COMMIT(MB1);
            else              TC_COMMIT(MB2);
        }
    }
    mbar_wait(MB0, ph0);
    mbar_wait(MB1, ph1);
    mbar_wait(MB2, ph2);
    asm volatile("tcgen05.fence::after_thread_sync;" ::: "memory");
#undef OUT_CP

    if (wid < 4) {
        float* Crow = C + (long)(m0 + wid * 32 + lane) * N + n0;
#pragma unroll
        for (int cb = 0; cb < 128; cb += 32) {
            uint32_t r[32];
            LDTM_X32(r, tmem + cb);
            asm volatile("tcgen05.wait::ld.sync.aligned;" ::: "memory");
#pragma unroll
            for (int j = 0; j < 32; j += 4) {
                float4 v;
                v.x = __uint_as_float(r[j + 0]);
                v.y = __uint_as_float(r[j + 1]);
                v.z = __uint_as_float(r[j + 2]);
                v.w = __uint_as_float(r[j + 3]);
                *(float4*)(Crow + cb + j) = v;
            }
        }
    }
    asm volatile("tcgen05.fence::before_thread_sync;" ::: "memory");
    __syncthreads();
    if (wid == 0) {
        asm volatile("tcgen05.dealloc.cta_group::1.sync.aligned.b32 %0, %1;"
                     :: "r"(tmem), "r"(128u));
    }
#else
    for (int idx = tid; idx < 128 * 128; idx += 256) {
        int rr = idx >> 7, cc = idx & 127;
        float acc = 0.f;
        for (int k = 0; k < HH; k++)
            acc += Hid[(long)(m0 + rr) * HH + k] * WdR[(long)(n0 + cc) * HH + k];
        for (int k = 0; k < AA; k++)
            acc += AdS[(long)(m0 + rr) * AA + k] * W2R[(long)(n0 + cc) * AA + k];
        for (int k = 0; k < AA; k++)
            acc += EcS[(long)(m0 + rr) * AA + k] * WcR[(long)(n0 + cc) * AA + k];
        C[(long)(m0 + rr) * DD + n0 + cc] = acc;
    }
#endif
}

// ============================================================
// tc_swiglu: fused gate+up GEMM + SwiGLU epilogue.
// R15 change: 2-STAGE pipeline (SMEM 100KB) -> 2 CTAs/SM.
// ============================================================
#define SWI_SMEM (2048 + 2 * 49152)   // 100352

__global__ __launch_bounds__(256)
void tc_swiglu(const float* __restrict__ A, const float* __restrict__ Bg,
               const float* __restrict__ Bu, float* __restrict__ C, int K)
{
    extern __shared__ char smem[];
    const int tid  = threadIdx.x;
    const int wid  = tid >> 5;
    const int lane = tid & 31;
    const int m0 = blockIdx.y * 128, n0 = blockIdx.x * 128;
    const int N = HH;
    const float* Ap  = A  + (long)m0 * K;
    const float* Bgp = Bg + (long)n0 * K;
    const float* Bup = Bu + (long)n0 * K;
    const int nch = K >> 5;   // 32

#ifdef TCPATH
    uint32_t sbase = smem_u32(smem);
    const uint32_t TM_PTR = sbase;
    const uint32_t MB0 = sbase + 16;
    const uint32_t MB1 = sbase + 24;
    uint32_t data0 = (sbase + 1024 + 1023) & ~1023u;

    if (wid == 0) {
        asm volatile("tcgen05.alloc.cta_group::1.sync.aligned.shared::cta.b32 [%0], %1;"
                     :: "r"(TM_PTR), "r"(256u) : "memory");
        asm volatile("tcgen05.relinquish_alloc_permit.cta_group::1.sync.aligned;");
    }
    if (tid == 0) { MBAR_INIT(MB0, 1); MBAR_INIT(MB1, 1); }
    __syncthreads();
    uint32_t tmem;
    asm volatile("ld.shared.b32 %0, [%1];" : "=r"(tmem) : "r"(TM_PTR));

#define SWI_CP(c, b) do {                                                    \
        const int k0_ = (c) << 5;                                            \
        const uint32_t so_ = (uint32_t)(b) * 49152u;                         \
        _Pragma("unroll")                                                    \
        for (int it_ = 0; it_ < 12; it_++) {                                 \
            int idx_ = it_ * 256 + tid;                                      \
            int r_ = idx_ >> 3, q_ = idx_ & 7;                               \
            int rr_ = r_ & 127;                                              \
            const float* src_;                                               \
            if (r_ < 128)       src_ = Ap  + (long)rr_ * K + k0_ + q_ * 4;   \
            else if (r_ < 256)  src_ = Bgp + (long)rr_ * K + k0_ + q_ * 4;   \
            else                src_ = Bup + (long)rr_ * K + k0_ + q_ * 4;   \
            uint32_t off_ = (uint32_t)(rr_ * 128 + q_ * 16);                 \
            uint32_t sw_ = off_ ^ ((off_ >> 3) & 0x70u);                     \
            asm volatile("cp.async.cg.shared.global [%0], [%1], 16;"         \
                :: "r"(data0 + so_ + (uint32_t)(r_ >> 7) * 16384u + sw_),    \
                   "l"(src_) : "memory");                                    \
        }                                                                    \
        asm volatile("cp.async.commit_group;" ::: "memory");                 \
    } while (0)

    int ph0 = 0, ph1 = 0;
    SWI_CP(0, 0);

    for (int i = 0; i < nch; i++) {
        const int ip1 = i + 1;
        if (ip1 < nch) {
            const int b = ip1 & 1;
            if (i >= 1) {   // buffer b last used by chunk i-1's MMA
                if (b == 0) { mbar_wait(MB0, ph0); ph0 ^= 1; }
                else        { mbar_wait(MB1, ph1); ph1 ^= 1; }
            }
            SWI_CP(ip1, b);
        }
        if (ip1 < nch) asm volatile("cp.async.wait_group 1;" ::: "memory");
        else           asm volatile("cp.async.wait_group 0;" ::: "memory");
        asm volatile("fence.proxy.async.shared::cta;" ::: "memory");
        __syncthreads();
        if (wid == 0 && elect1()) {
            const int bi = i & 1;
            uint64_t da  = make_desc(data0 + (uint32_t)bi * 49152u);
            uint64_t dbg = make_desc(data0 + (uint32_t)bi * 49152u + 16384u);
            uint64_t dbu = make_desc(data0 + (uint32_t)bi * 49152u + 32768u);
            uint32_t en0 = (i > 0) ? 1u : 0u;
#pragma unroll
            for (int ks = 0; ks < 4; ks++) {
                uint32_t en = (en0 || ks > 0) ? 1u : 0u;
                mma_tf32(tmem,       da + ks * 2, dbg + ks * 2, IDESC_TF32, en);
                mma_tf32(tmem + 128, da + ks * 2, dbu + ks * 2, IDESC_TF32, en);
            }
            if (bi == 0) TC_COMMIT(MB0);
            else         TC_COMMIT(MB1);
        }
    }
    mbar_wait(MB0, ph0);
    mbar_wait(MB1, ph1);
    asm volatile("tcgen05.fence::after_thread_sync;" ::: "memory");
#undef SWI_CP

    {
        const int sp   = wid & 3;
        const int half = wid >> 2;
        const int row  = m0 + sp * 32 + lane;
        float* Crow = C + (long)row * N + n0;
#pragma unroll
        for (int c = 0; c < 2; c++) {
            const int cb = half * 64 + c * 32;
            uint32_t gr[32], ur[32];
            LDTM_X32(gr, tmem + cb);
            LDTM_X32(ur, tmem + 128 + cb);
            asm volatile("tcgen05.wait::ld.sync.aligned;" ::: "memory");
#pragma unroll
            for (int j = 0; j < 32; j += 4) {
                float4 v;
                v.x = rndf(silu_f(__uint_as_float(gr[j + 0])) * __uint_as_float(ur[j + 0]));
                v.y = rndf(silu_f(__uint_as_float(gr[j + 1])) * __uint_as_float(ur[j + 1]));
                v.z = rndf(silu_f(__uint_as_float(gr[j + 2])) * __uint_as_float(ur[j + 2]));
                v.w = rndf(silu_f(__uint_as_float(gr[j + 3])) * __uint_as_float(ur[j + 3]));
                *(float4*)(Crow + cb + j) = v;
            }
        }
    }
    asm volatile("tcgen05.fence::before_thread_sync;" ::: "memory");
    __syncthreads();
    if (wid == 0) {
        asm volatile("tcgen05.dealloc.cta_group::1.sync.aligned.b32 %0, %1;"
                     :: "r"(tmem), "r"(256u));
    }
#else
    for (int idx = tid; idx < 128 * 128; idx += 256) {
        int rr = idx >> 7, cc = idx & 127;
        float g = 0.f, u = 0.f;
        for (int k = 0; k < K; k++) {
            float a = A[(long)(m0 + rr) * K + k];
            g += a * Bg[(long)(n0 + cc) * K + k];
            u += a * Bu[(long)(n0 + cc) * K + k];
        }
        C[(long)(m0 + rr) * N + n0 + cc] = rndf(silu_f(g) * u);
    }
#endif
}

// ============================================================
// tc_adapt: fused adapt attention; output PRE-SCALED by 0.1 (validated)
// ============================================================
#define ADP_SMEM (2048 + 3 * 65536)   // 198656

__global__ __launch_bounds__(256)
void tc_adapt(const float* __restrict__ Ain,   // [B][S][A] tf32
              const float* __restrict__ Aout,  // [B][S][A] tf32
              const float* __restrict__ AiT,   // [B][A][S] tf32
              float* __restrict__ AdaptS)      // [B][S][A] out = rnd(0.1*acc)
{
    extern __shared__ char smem[];
    const int tid  = threadIdx.x;
    const int wid  = tid >> 5;
    const int lane = tid & 31;
    const int b    = blockIdx.y;
    const int m0   = blockIdx.x * 128;

    const float* AinB  = Ain  + (long)b * SS * AA;
    const float* AoutB = Aout + (long)b * SS * AA;
    const float* AiTB  = AiT  + (long)b * AA * SS;
    float*       AdB   = AdaptS + (long)b * SS * AA;

#ifdef TCPATH
    uint32_t sbase = smem_u32(smem);
    const uint32_t TM_PTR = sbase;
    const uint32_t MB0 = sbase + 16;
    const uint32_t MB1 = sbase + 24;
    uint32_t data0 = (sbase + 1024 + 1023) & ~1023u;
    const uint32_t AinS = data0;
    const uint32_t Bsh  = data0 + 65536u;
    const uint32_t Psh  = data0 + 131072u;

    if (wid == 0) {
        asm volatile("tcgen05.alloc.cta_group::1.sync.aligned.shared::cta.b32 [%0], %1;"
                     :: "r"(TM_PTR), "r"(256u) : "memory");
        asm volatile("tcgen05.relinquish_alloc_permit.cta_group::1.sync.aligned;");
    }
    if (tid == 0) { MBAR_INIT(MB0, 1); MBAR_INIT(MB1, 1); }
    __syncthreads();
    uint32_t tmem;
    asm volatile("ld.shared.b32 %0, [%1];" : "=r"(tmem) : "r"(TM_PTR));

#define ADP_LOAD256(base, gptr, ldg) do {                                    \
        _Pragma("unroll")                                                    \
        for (int it_ = 0; it_ < 16; it_++) {                                 \
            int idx_ = it_ * 256 + tid;                                      \
            int c_ = idx_ >> 10, r_ = (idx_ >> 3) & 127, q_ = idx_ & 7;      \
            const float* src_ = (gptr) + (long)r_ * (ldg) + c_ * 32 + q_ * 4;\
            uint32_t off_ = (uint32_t)(r_ * 128 + q_ * 16);                  \
            uint32_t sw_ = off_ ^ ((off_ >> 3) & 0x70u);                     \
            asm volatile("cp.async.cg.shared.global [%0], [%1], 16;"         \
                :: "r"((base) + (uint32_t)c_ * 16384u + sw_), "l"(src_)      \
                : "memory");                                                 \
        }                                                                    \
        asm volatile("cp.async.commit_group;" ::: "memory");                 \
    } while (0)

    ADP_LOAD256(AinS, AinB + (long)m0 * AA, AA);
    ADP_LOAD256(Bsh,  AoutB, AA);
    asm volatile("cp.async.wait_group 0;" ::: "memory");
    asm volatile("fence.proxy.async.shared::cta;" ::: "memory");
    __syncthreads();

    int ph0 = 0, ph1 = 0;
    for (int kt = 0; kt < 16; kt++) {
        if (wid == 0 && elect1()) {
#pragma unroll
            for (int c = 0; c < 4; c++) {
                uint64_t da = make_desc(AinS + (uint32_t)c * 16384u);
                uint64_t db = make_desc(Bsh  + (uint32_t)c * 16384u);
#pragma unroll
                for (int ks = 0; ks < 4; ks++)
                    mma_tf32(tmem, da + ks * 2, db + ks * 2, IDESC_TF32,
                             (c > 0 || ks > 0) ? 1u : 0u);
            }
            TC_COMMIT(MB0);
        }
        mbar_wait(MB0, ph0); ph0 ^= 1;
        asm volatile("tcgen05.fence::after_thread_sync;" ::: "memory");

        if (wid < 4) {
            const int r = wid * 32 + lane;
#pragma unroll
            for (int cb = 0; cb < 4; cb++) {
                uint32_t rg[32];
                LDTM_X32(rg, tmem + cb * 32);
                asm volatile("tcgen05.wait::ld.sync.aligned;" ::: "memory");
#pragma unroll
                for (int j = 0; j < 32; j += 4) {
                    float4 v;
                    v.x = rndf(silu_f(fminf(5.f, fmaxf(-5.f, __uint_as_float(rg[j + 0])))));
                    v.y = rndf(silu_f(fminf(5.f, fmaxf(-5.f, __uint_as_float(rg[j + 1])))));
                    v.z = rndf(silu_f(fminf(5.f, fmaxf(-5.f, __uint_as_float(rg[j + 2])))));
                    v.w = rndf(silu_f(fminf(5.f, fmaxf(-5.f, __uint_as_float(rg[j + 3])))));
                    uint32_t off = (uint32_t)(r * 128 + j * 4);
                    uint32_t sw = off ^ ((off >> 3) & 0x70u);
                    uint32_t addr = Psh + (uint32_t)cb * 16384u + sw;
                    asm volatile("st.shared.v4.b32 [%0], {%1, %2, %3, %4};"
                        :: "r"(addr), "r"(__float_as_uint(v.x)), "r"(__float_as_uint(v.y)),
                           "r"(__float_as_uint(v.z)), "r"(__float_as_uint(v.w)) : "memory");
                }
            }
        } else {
            const int tid2 = tid - 128;
#pragma unroll
            for (int it = 0; it < 32; it++) {
                int idx = it * 128 + tid2;
                int c = idx >> 10, r = (idx >> 3) & 127, q = idx & 7;
                const float* src = AiTB + (long)r * SS + kt * 128 + c * 32 + q * 4;
                uint32_t off = (uint32_t)(r * 128 + q * 16);
                uint32_t sw = off ^ ((off >> 3) & 0x70u);
                asm volatile("cp.async.cg.shared.global [%0], [%1], 16;"
                    :: "r"(Bsh + (uint32_t)c * 16384u + sw), "l"(src) : "memory");
            }
            asm volatile("cp.async.commit_group;" ::: "memory");
        }
        asm volatile("cp.async.wait_group 0;" ::: "memory");
        asm volatile("fence.proxy.async.shared::cta;" ::: "memory");
        __syncthreads();

        if (wid == 0 && elect1()) {
#pragma unroll
            for (int c = 0; c < 4; c++) {
                uint64_t da = make_desc(Psh + (uint32_t)c * 16384u);
                uint64_t db = make_desc(Bsh + (uint32_t)c * 16384u);
#pragma unroll
                for (int ks = 0; ks < 4; ks++)
                    mma_tf32(tmem + 128, da + ks * 2, db + ks * 2, IDESC_TF32,
                             (kt > 0 || c > 0 || ks > 0) ? 1u : 0u);
            }
            TC_COMMIT(MB1);
        }
        mbar_wait(MB1, ph1); ph1 ^= 1;

        if (kt < 15) {
            ADP_LOAD256(Bsh, AoutB + (long)(kt + 1) * 128 * AA, AA);
            asm volatile("cp.async.wait_group 0;" ::: "memory");
            asm volatile("fence.proxy.async.shared::cta;" ::: "memory");
            __syncthreads();
        }
    }
#undef ADP_LOAD256

    asm volatile("tcgen05.fence::after_thread_sync;" ::: "memory");
    if (wid < 4) {
        const int r = wid * 32 + lane;
        float* Crow = AdB + (long)(m0 + r) * AA;
#pragma unroll
        for (int cb = 0; cb < 128; cb += 32) {
            uint32_t rg[32];
            LDTM_X32(rg, tmem + 128 + cb);
            asm volatile("tcgen05.wait::ld.sync.aligned;" ::: "memory");
#pragma unroll
            for (int j = 0; j < 32; j += 4) {
                float4 v;
                v.x = rndf(0.1f * __uint_as_float(rg[j + 0]));
                v.y = rndf(0.1f * __uint_as_float(rg[j + 1]));
                v.z = rndf(0.1f * __uint_as_float(rg[j + 2]));
                v.w = rndf(0.1f * __uint_as_float(rg[j + 3]));
                *(float4*)(Crow + cb + j) = v;
            }
        }
    }
    asm volatile("tcgen05.fence::before_thread_sync;" ::: "memory");
    __syncthreads();
    if (wid == 0) {
        asm volatile("tcgen05.dealloc.cta_group::1.sync.aligned.b32 %0, %1;"
                     :: "r"(tmem), "r"(256u));
    }
#else
    for (int r = tid; r < 128; r += 256) {
        float acc[AA];
        for (int a = 0; a < AA; a++) acc[a] = 0.f;
        for (int s = 0; s < SS; s++) {
            float p = 0.f;
            for (int a = 0; a < AA; a++)
                p += AinB[(long)(m0 + r) * AA + a] * AoutB[(long)s * AA + a];
            p = silu_f(fminf(5.f, fmaxf(-5.f, p)));
            for (int a = 0; a < AA; a++)
                acc[a] += p * AinB[(long)s * AA + a];
        }
        for (int a = 0; a < AA; a++)
            AdB[(long)(m0 + r) * AA + a] = rndf(0.1f * acc[a]);
    }
#endif
}

// ============================================================
// Small helpers
// ============================================================
__global__ void zero_kernel(float* p, long n)
{
    long i = (long)blockIdx.x * blockDim.x + threadIdx.x;
    long stride = (long)gridDim.x * blockDim.x;
    for (; i < n; i += stride) p[i] = 0.f;
}

// one float4 per thread, exact grid
__global__ void rnd_kernel(const float* __restrict__ in, float* __restrict__ out, long n)
{
    long j = ((long)blockIdx.x * blockDim.x + threadIdx.x) * 4;
    if (j < n) {
        float4 v = *(const float4*)(in + j);
        v.x = rndf(v.x); v.y = rndf(v.y); v.z = rndf(v.z); v.w = rndf(v.w);
        *(float4*)(out + j) = v;
    }
}
#define RND_GRID(n) ((int)(((n) / 4 + 255) / 256))

// 8-segment batched rnd (one launch)
struct Rnd8 {
    const float* in[8];
    float*       out[8];
    long         cum[9];   // cumulative float4 counts
};
__global__ void rnd_multi(Rnd8 s)
{
    long t = (long)blockIdx.x * blockDim.x + threadIdx.x;   // float4 index
    if (t >= s.cum[8]) return;
    int k = 0;
#pragma unroll
    for (int i = 1; i < 8; i++) if (t >= s.cum[i]) k = i;
    long j = (t - s.cum[k]) * 4;
    float4 v = *(const float4*)(s.in[k] + j);
    v.x = rndf(v.x); v.y = rndf(v.y); v.z = rndf(v.z); v.w = rndf(v.w);
    *(float4*)(s.out[k] + j) = v;
}

__global__ void transpose_kernel(const float* __restrict__ in, float* __restrict__ out,
                                 int R, int C, long sIn, long sOut)
{
    __shared__ float tile[32][33];
    in  += (long)blockIdx.z * sIn;
    out += (long)blockIdx.z * sOut;
    int r0 = blockIdx.y * 32, c0 = blockIdx.x * 32;
    int tx = threadIdx.x, ty = threadIdx.y;
#pragma unroll
    for (int i = 0; i < 32; i += 8)
        tile[ty + i][tx] = in[(long)(r0 + ty + i) * C + c0 + tx];
    __syncthreads();
#pragma unroll
    for (int i = 0; i < 32; i += 8)
        out[(long)(c0 + ty + i) * R + r0 + tx] = rndf(tile[tx][ty + i]);
}

// ============================================================
// Launch
// ============================================================
extern "C" void kernel_launch(void* const* d_in, const int* in_sizes, int n_in,
                              void* d_out, int out_size)
{
    const float* x       = (const float*)d_in[0];
    const float* ew      = (const float*)d_in[1];
    const float* w_up    = (const float*)d_in[2];
    const float* w_gate  = (const float*)d_in[3];
    const float* w_down  = (const float*)d_in[4];
    const float* w_pre   = (const float*)d_in[5];
    const float* w_post  = (const float*)d_in[6];
    const float* an_g    = (const float*)d_in[7];
    const float* an_b    = (const float*)d_in[8];
    const float* w_aproj = (const float*)d_in[9];
    const float* w_exp   = (const float*)d_in[10];
    const float* eln_g   = (const float*)d_in[11];
    const float* eln_b   = (const float*)d_in[12];
    const float* w_eproj = (const float*)d_in[13];
    const float* w_out   = (const float*)d_in[14];
    float* out = (float*)d_out;

    float *Hid, *Pre, *Ain, *Aout, *AiT, *AdaptS,
          *EcompS, *Wcomb, *WcombR, *W2, *W2R, *Tep, *Tap,
          *xR, *WgR, *WuR, *WdR, *WoutR, *WpreR, *WpostR, *WexpR;
    cudaGetSymbolAddress((void**)&Hid,    g_Hid);
    cudaGetSymbolAddress((void**)&Pre,    g_Pre);
    cudaGetSymbolAddress((void**)&Ain,    g_Ain);
    cudaGetSymbolAddress((void**)&Aout,   g_Aout);
    cudaGetSymbolAddress((void**)&AiT,    g_AiT);
    cudaGetSymbolAddress((void**)&AdaptS, g_AdaptS);
    cudaGetSymbolAddress((void**)&EcompS, g_EcompS);
    cudaGetSymbolAddress((void**)&Wcomb,  g_Wcomb);
    cudaGetSymbolAddress((void**)&WcombR, g_WcombR);
    cudaGetSymbolAddress((void**)&W2,     g_W2);
    cudaGetSymbolAddress((void**)&W2R,    g_W2R);
    cudaGetSymbolAddress((void**)&Tep,    g_Tep);
    cudaGetSymbolAddress((void**)&Tap,    g_Tap);
    cudaGetSymbolAddress((void**)&xR,     g_xR);
    cudaGetSymbolAddress((void**)&WgR,    g_WgR);
    cudaGetSymbolAddress((void**)&WuR,    g_WuR);
    cudaGetSymbolAddress((void**)&WdR,    g_WdR);
    cudaGetSymbolAddress((void**)&WoutR,  g_WoutR);
    cudaGetSymbolAddress((void**)&WpreR,  g_WpreR);
    cudaGetSymbolAddress((void**)&WpostR, g_WpostR);
    cudaGetSymbolAddress((void**)&WexpR,  g_WexpR);

    cudaFuncSetAttribute(tc_gemm,   cudaFuncAttributeMaxDynamicSharedMemorySize, TCG_SMEM);
    cudaFuncSetAttribute(tc_preln,  cudaFuncAttributeMaxDynamicSharedMemorySize, TCG_SMEM);
    cudaFuncSetAttribute(tc_eall,   cudaFuncAttributeMaxDynamicSharedMemorySize, TCG_SMEM);
    cudaFuncSetAttribute(tc_out,    cudaFuncAttributeMaxDynamicSharedMemorySize, TCG_SMEM);
    cudaFuncSetAttribute(tc_swiglu, cudaFuncAttributeMaxDynamicSharedMemorySize, SWI_SMEM);
    cudaFuncSetAttribute(tc_adapt,  cudaFuncAttributeMaxDynamicSharedMemorySize, ADP_SMEM);

    dim3 tb32(32, 8);

    // ---- round all 8 raw inputs in ONE launch ----
    {
        Rnd8 s;
        const float* ins[8]  = { x, w_gate, w_up, w_down, w_out, w_pre, w_post, w_exp };
        float*       outs[8] = { xR, WgR, WuR, WdR, WoutR, WpreR, WpostR, WexpR };
        long         ns[8]   = { (long)MM * DD, (long)HH * DD, (long)HH * DD,
                                 (long)DD * HH, (long)DD * HH, (long)AA * DD,
                                 (long)AA * HH, (long)EE * AA * AA };
        long c = 0;
        for (int i = 0; i < 8; i++) {
            s.in[i] = ins[i]; s.out[i] = outs[i];
            s.cum[i] = c; c += ns[i] / 4;
        }
        s.cum[8] = c;
        int blocks = (int)((c + 255) / 256);
        rnd_multi<<<blocks, 256>>>(s);
    }

    // ---- zero split-K atomic targets (EcompS handled by tc_eall now) ----
    zero_kernel<<<64, 256>>>(Wcomb, (long)DD * AA);
    zero_kernel<<<64, 256>>>(W2,    (long)DD * AA);

    // ---- weight-only precomputes (split-K 16, atomic) ----
    transpose_kernel<<<dim3(AA / 32, HH / 32, 1), tb32>>>(w_eproj, Tep, HH, AA, 0, 0);
    transpose_kernel<<<dim3(AA / 32, HH / 32, 1), tb32>>>(w_aproj, Tap, HH, AA, 0, 0);
    tc_gemm<<<dim3(1, DD / 128, 16), 256, TCG_SMEM>>>(WoutR, Tep, Wcomb, nullptr,
                                                      DD, AA, HH, 0, 0, 0, 1.f, 4, 16, 0);
    tc_gemm<<<dim3(1, DD / 128, 16), 256, TCG_SMEM>>>(WdR, Tap, W2, nullptr,
                                                      DD, AA, HH, 0, 0, 0, 1.f, 4, 16, 0);
    rnd_kernel<<<RND_GRID((long)DD * AA), 256>>>(Wcomb, WcombR, (long)DD * AA);
    rnd_kernel<<<RND_GRID((long)DD * AA), 256>>>(W2,    W2R,    (long)DD * AA);

    // ---- fused gate+up+SwiGLU -> Hid (2-stage, 2 CTAs/SM) ----
    tc_swiglu<<<dim3(HH / 128, MM / 128, 1), 256, SWI_SMEM>>>(xR, WgR, WuR, Hid, DD);

    // ---- pre GEMM + LN + transpose fused: Pre, Ain, AiT ----
    tc_preln<<<dim3(1, MM / 128, 1), 256, TCG_SMEM>>>(xR, WpreR, Ain, Pre, AiT,
                                                      an_g, an_b, DD);

    // ---- post GEMM + LN fused: Aout ----
    tc_preln<<<dim3(1, MM / 128, 1), 256, TCG_SMEM>>>(Hid, WpostR, Aout, nullptr, nullptr,
                                                      an_g, an_b, HH);

    // ---- fused adapt attention -> AdaptS (pre-scaled 0.1) ----
    tc_adapt<<<dim3(SS / 128, BB, 1), 256, ADP_SMEM>>>(Ain, Aout, AiT, AdaptS);

    // ---- experts: GEMM + select + LN + zero-fill fused -> EcompS ----
    tc_eall<<<dim3(EE, MM / 128, 1), 256, TCG_SMEM>>>(Pre, WexpR, ew, eln_g, eln_b, EcompS);

    // ---- single-pass output: out = Hid@WdR^T + AdaptS@W2R^T + EcompS@WcombR^T ----
    tc_out<<<dim3(DD / 128, MM / 128, 1), 256, TCG_SMEM>>>(Hid, WdR, AdaptS, W2R,
                                                           EcompS, WcombR, out);
}